// round 1
// baseline (speedup 1.0000x reference)
#include <cuda_runtime.h>
#include <math_constants.h>

#define BATCH  2
#define SEQ    2048
#define DMODEL 1024
#define NHEADS 16
#define HDIM   64
#define MTOT   (BATCH*SEQ)   // 4096

// Scratch (allocation-free rule: __device__ globals)
__device__ float g_Q[(size_t)MTOT * DMODEL];
__device__ float g_K[(size_t)MTOT * DMODEL];
__device__ float g_V[(size_t)MTOT * DMODEL];
__device__ float g_C[(size_t)MTOT * DMODEL];

// ---------------------------------------------------------------------------
// Tiled SGEMM: Y[M,1024] = X[M,1024] @ W[1024,1024]^T + b   (NT layout)
// BM=128, BN=128, BK=16, 256 threads, 8x8 micro-tile per thread.
// ---------------------------------------------------------------------------
__device__ __forceinline__ void gemm_body(const float* __restrict__ X,
                                          const float* __restrict__ W,
                                          const float* __restrict__ bias,
                                          float* __restrict__ Y)
{
    __shared__ float Xs[16][128];   // [k][m] transposed
    __shared__ float Ws[16][128];   // [k][n] transposed

    const int bm  = blockIdx.y * 128;
    const int bn  = blockIdx.x * 128;
    const int tid = threadIdx.x;
    const int tx  = tid & 15;
    const int ty  = tid >> 4;

    float acc[8][8] = {};

    for (int k0 = 0; k0 < DMODEL; k0 += 16) {
        #pragma unroll
        for (int it = 0; it < 2; it++) {
            int v   = tid + it * 256;   // 0..511 float4 slots
            int row = v >> 2;           // 0..127
            int c4  = v & 3;            // 0..3
            float4 xv = *(const float4*)(X + (size_t)(bm + row) * DMODEL + k0 + c4 * 4);
            float4 wv = *(const float4*)(W + (size_t)(bn + row) * DMODEL + k0 + c4 * 4);
            Xs[c4*4+0][row] = xv.x; Xs[c4*4+1][row] = xv.y;
            Xs[c4*4+2][row] = xv.z; Xs[c4*4+3][row] = xv.w;
            Ws[c4*4+0][row] = wv.x; Ws[c4*4+1][row] = wv.y;
            Ws[c4*4+2][row] = wv.z; Ws[c4*4+3][row] = wv.w;
        }
        __syncthreads();

        #pragma unroll
        for (int kk = 0; kk < 16; kk++) {
            float a[8], b[8];
            *(float4*)(a)     = *(const float4*)&Xs[kk][ty * 8];
            *(float4*)(a + 4) = *(const float4*)&Xs[kk][ty * 8 + 4];
            *(float4*)(b)     = *(const float4*)&Ws[kk][tx * 8];
            *(float4*)(b + 4) = *(const float4*)&Ws[kk][tx * 8 + 4];
            #pragma unroll
            for (int i = 0; i < 8; i++)
                #pragma unroll
                for (int j = 0; j < 8; j++)
                    acc[i][j] = fmaf(a[i], b[j], acc[i][j]);
        }
        __syncthreads();
    }

    #pragma unroll
    for (int i = 0; i < 8; i++) {
        size_t gm = bm + ty * 8 + i;
        #pragma unroll
        for (int j = 0; j < 8; j += 4) {
            int gn = bn + tx * 8 + j;
            float4 o = make_float4(acc[i][j+0] + bias[gn+0],
                                   acc[i][j+1] + bias[gn+1],
                                   acc[i][j+2] + bias[gn+2],
                                   acc[i][j+3] + bias[gn+3]);
            *(float4*)(Y + gm * DMODEL + gn) = o;
        }
    }
}

__global__ __launch_bounds__(256)
void gemm_qkv(const float* __restrict__ x,
              const float* __restrict__ Wq, const float* __restrict__ bq,
              const float* __restrict__ Wk, const float* __restrict__ bk,
              const float* __restrict__ Wv, const float* __restrict__ bv)
{
    const float* W; const float* b; float* Y;
    if (blockIdx.z == 0)      { W = Wq; b = bq; Y = g_Q; }
    else if (blockIdx.z == 1) { W = Wk; b = bk; Y = g_K; }
    else                      { W = Wv; b = bv; Y = g_V; }
    gemm_body(x, W, b, Y);
}

__global__ __launch_bounds__(256)
void gemm_out(const float* __restrict__ Wo, const float* __restrict__ bo,
              float* __restrict__ Y)
{
    gemm_body(g_C, Wo, bo, Y);
}

// ---------------------------------------------------------------------------
// Flash attention, fp32. 64 q-rows x full hd=64 per block, K/V tiles of 64.
// 256 threads = 16x16; each thread owns a 4x4 micro-tile.
// smem: Qs[d][q], KP (K-phase: [d][k], P-phase: [q][k]), Vs[k][d]. 48 KB total.
// ---------------------------------------------------------------------------
__device__ __forceinline__ float rmax16(float v) {
    #pragma unroll
    for (int o = 8; o > 0; o >>= 1)
        v = fmaxf(v, __shfl_xor_sync(0xffffffffu, v, o, 16));
    return v;
}
__device__ __forceinline__ float rsum16(float v) {
    #pragma unroll
    for (int o = 8; o > 0; o >>= 1)
        v += __shfl_xor_sync(0xffffffffu, v, o, 16);
    return v;
}

__global__ __launch_bounds__(256)
void flash_attn()
{
    __shared__ float Qs[64][64];   // [d][qrow]
    __shared__ float KP[64][64];   // K phase: [d][key] ; P phase: [qrow][key]
    __shared__ float Vs[64][64];   // [key][d]

    const int b  = blockIdx.z;
    const int h  = blockIdx.y;
    const int q0 = blockIdx.x * 64;
    const int tid = threadIdx.x;
    const int tx = tid & 15;       // key-col / hd-col group
    const int ty = tid >> 4;       // q-row group

    const size_t base = (size_t)b * SEQ * DMODEL + (size_t)h * HDIM;
    const float* Qg = g_Q + base;
    const float* Kg = g_K + base;
    const float* Vg = g_V + base;
    float*       Og = g_C + base;

    // Load Q tile transposed: Qs[d][row]
    #pragma unroll
    for (int it = 0; it < 4; it++) {
        int v   = tid + it * 256;   // 0..1023 float4 slots
        int row = v >> 4;           // 0..63
        int c4  = v & 15;           // 0..15
        float4 qv = *(const float4*)(Qg + (size_t)(q0 + row) * DMODEL + c4 * 4);
        Qs[c4*4+0][row] = qv.x; Qs[c4*4+1][row] = qv.y;
        Qs[c4*4+2][row] = qv.z; Qs[c4*4+3][row] = qv.w;
    }

    float m[4], l[4], acc[4][4];
    #pragma unroll
    for (int i = 0; i < 4; i++) {
        m[i] = -CUDART_INF_F; l[i] = 0.f;
        #pragma unroll
        for (int j = 0; j < 4; j++) acc[i][j] = 0.f;
    }

    for (int kt = 0; kt < SEQ / 64; kt++) {
        const int k0 = kt * 64;

        // Load K (transposed -> KP[d][key]) and V (direct -> Vs[key][d])
        #pragma unroll
        for (int it = 0; it < 4; it++) {
            int v   = tid + it * 256;
            int row = v >> 4;
            int c4  = v & 15;
            float4 kv = *(const float4*)(Kg + (size_t)(k0 + row) * DMODEL + c4 * 4);
            KP[c4*4+0][row] = kv.x; KP[c4*4+1][row] = kv.y;
            KP[c4*4+2][row] = kv.z; KP[c4*4+3][row] = kv.w;
            float4 vv = *(const float4*)(Vg + (size_t)(k0 + row) * DMODEL + c4 * 4);
            *(float4*)&Vs[row][c4 * 4] = vv;
        }
        __syncthreads();

        // Scores: s[i][j] = sum_d Q[q][d] * K[k][d]
        float s[4][4] = {};
        #pragma unroll
        for (int d = 0; d < 64; d += 4) {
            float a4[4][4], b4[4][4];   // [dd][i], [dd][j]
            #pragma unroll
            for (int dd = 0; dd < 4; dd++) {
                *(float4*)a4[dd] = *(const float4*)&Qs[d + dd][ty * 4];
                *(float4*)b4[dd] = *(const float4*)&KP[d + dd][tx * 4];
            }
            #pragma unroll
            for (int dd = 0; dd < 4; dd++)
                #pragma unroll
                for (int i = 0; i < 4; i++)
                    #pragma unroll
                    for (int j = 0; j < 4; j++)
                        s[i][j] = fmaf(a4[dd][i], b4[dd][j], s[i][j]);
        }
        __syncthreads();   // done reading KP as K-tile

        // Online softmax (scale 1/sqrt(64) = 0.125)
        #pragma unroll
        for (int i = 0; i < 4; i++) {
            float lmax = -CUDART_INF_F;
            #pragma unroll
            for (int j = 0; j < 4; j++) {
                s[i][j] *= 0.125f;
                lmax = fmaxf(lmax, s[i][j]);
            }
            float mnew = fmaxf(m[i], rmax16(lmax));
            float corr = __expf(m[i] - mnew);
            float rs = 0.f;
            #pragma unroll
            for (int j = 0; j < 4; j++) {
                s[i][j] = __expf(s[i][j] - mnew);
                rs += s[i][j];
            }
            rs = rsum16(rs);
            l[i] = l[i] * corr + rs;
            m[i] = mnew;
            #pragma unroll
            for (int j = 0; j < 4; j++) acc[i][j] *= corr;
        }

        // Write P into KP as [qrow][key] (float4 per thread-row)
        #pragma unroll
        for (int i = 0; i < 4; i++)
            *(float4*)&KP[ty * 4 + i][tx * 4] =
                make_float4(s[i][0], s[i][1], s[i][2], s[i][3]);
        __syncthreads();

        // acc += P @ V : acc[i][j] += sum_k P[q][k] * V[k][d]
        #pragma unroll
        for (int k = 0; k < 64; k += 4) {
            float a4[4][4], b4[4][4];   // a4[i][kk] = P[q_i][k+kk], b4[kk][j] = V[k+kk][d_j]
            #pragma unroll
            for (int i = 0; i < 4; i++)
                *(float4*)a4[i] = *(const float4*)&KP[ty * 4 + i][k];
            #pragma unroll
            for (int kk = 0; kk < 4; kk++)
                *(float4*)b4[kk] = *(const float4*)&Vs[k + kk][tx * 4];
            #pragma unroll
            for (int kk = 0; kk < 4; kk++)
                #pragma unroll
                for (int i = 0; i < 4; i++)
                    #pragma unroll
                    for (int j = 0; j < 4; j++)
                        acc[i][j] = fmaf(a4[i][kk], b4[kk][j], acc[i][j]);
        }
        __syncthreads();   // before next tile overwrites KP/Vs
    }

    // Epilogue: normalize and write ctx in [B,S,D] layout
    #pragma unroll
    for (int i = 0; i < 4; i++) {
        float inv = 1.0f / l[i];
        float4 o = make_float4(acc[i][0] * inv, acc[i][1] * inv,
                               acc[i][2] * inv, acc[i][3] * inv);
        *(float4*)(Og + (size_t)(q0 + ty * 4 + i) * DMODEL + tx * 4) = o;
    }
}

// ---------------------------------------------------------------------------
extern "C" void kernel_launch(void* const* d_in, const int* in_sizes, int n_in,
                              void* d_out, int out_size)
{
    const float* x  = (const float*)d_in[0];
    const float* Wq = (const float*)d_in[1];
    const float* bq = (const float*)d_in[2];
    const float* Wk = (const float*)d_in[3];
    const float* bk = (const float*)d_in[4];
    const float* Wv = (const float*)d_in[5];
    const float* bv = (const float*)d_in[6];
    const float* Wo = (const float*)d_in[7];
    const float* bo = (const float*)d_in[8];
    float* out = (float*)d_out;

    dim3 gblk(256);
    dim3 ggrid(DMODEL / 128, MTOT / 128, 3);
    gemm_qkv<<<ggrid, gblk>>>(x, Wq, bq, Wk, bk, Wv, bv);

    dim3 fgrid(SEQ / 64, NHEADS, BATCH);
    flash_attn<<<fgrid, 256>>>();

    dim3 ogrid(DMODEL / 128, MTOT / 128, 1);
    gemm_out<<<ogrid, gblk>>>(Wo, bo, out);
}

// round 3
// speedup vs baseline: 1.3817x; 1.3817x over previous
#include <cuda_runtime.h>
#include <cuda_bf16.h>
#include <math_constants.h>
#include <cstdint>

#define BATCH  2
#define SEQ    2048
#define DMODEL 1024
#define NHEADS 16
#define HDIM   64
#define MTOT   (BATCH*SEQ)   // 4096
#define WSZ    (DMODEL*DMODEL)

// ---------------- scratch (allocation-free rule: __device__ globals) --------
__device__ float g_Q[(size_t)MTOT * DMODEL];
__device__ float g_K[(size_t)MTOT * DMODEL];
__device__ float g_V[(size_t)MTOT * DMODEL];
__device__ __nv_bfloat16 g_Xhi[(size_t)MTOT * DMODEL];
__device__ __nv_bfloat16 g_Xlo[(size_t)MTOT * DMODEL];
__device__ __nv_bfloat16 g_Whi[(size_t)4 * WSZ];
__device__ __nv_bfloat16 g_Wlo[(size_t)4 * WSZ];
__device__ __nv_bfloat16 g_Chi[(size_t)MTOT * DMODEL];
__device__ __nv_bfloat16 g_Clo[(size_t)MTOT * DMODEL];

// ---------------- helpers (baseline ISA only: compute_80-compatible) --------
__device__ __forceinline__ uint32_t smem_u32(const void* p) {
    uint32_t a;
    asm("{ .reg .u64 t; cvta.to.shared.u64 t, %1; cvt.u32.u64 %0, t; }"
        : "=r"(a) : "l"(p));
    return a;
}
__device__ __forceinline__ void cpasync16(uint32_t dst, const void* src) {
    asm volatile("cp.async.cg.shared.global [%0], [%1], 16;" :: "r"(dst), "l"(src));
}
#define CPASYNC_COMMIT() asm volatile("cp.async.commit_group;" ::: "memory")
#define CPASYNC_WAIT(n)  asm volatile("cp.async.wait_group %0;" :: "n"(n) : "memory")

__device__ __forceinline__ void ldm_x4(uint32_t* r, uint32_t addr) {
    asm volatile("ldmatrix.sync.aligned.m8n8.x4.shared.b16 {%0,%1,%2,%3}, [%4];"
        : "=r"(r[0]), "=r"(r[1]), "=r"(r[2]), "=r"(r[3]) : "r"(addr));
}
__device__ __forceinline__ void mma_bf16(float* c, const uint32_t* a,
                                         uint32_t b0, uint32_t b1) {
    asm volatile("mma.sync.aligned.m16n8k16.row.col.f32.bf16.bf16.f32 "
        "{%0,%1,%2,%3}, {%4,%5,%6,%7}, {%8,%9}, {%0,%1,%2,%3};"
        : "+f"(c[0]), "+f"(c[1]), "+f"(c[2]), "+f"(c[3])
        : "r"(a[0]), "r"(a[1]), "r"(a[2]), "r"(a[3]), "r"(b0), "r"(b1));
}

// ---------------- fp32 -> (hi, lo) bf16 split --------------------------------
__global__ __launch_bounds__(256)
void split_kernel(const float* __restrict__ src, __nv_bfloat16* __restrict__ hi,
                  __nv_bfloat16* __restrict__ lo, int n8)
{
    int i = blockIdx.x * blockDim.x + threadIdx.x;
    if (i >= n8) return;
    const float4* s = (const float4*)src + (size_t)i * 2;
    float4 a = s[0], b = s[1];
    float v[8] = {a.x, a.y, a.z, a.w, b.x, b.y, b.z, b.w};
    __nv_bfloat16 h[8], l[8];
    #pragma unroll
    for (int k = 0; k < 8; k++) {
        h[k] = __float2bfloat16(v[k]);
        l[k] = __float2bfloat16(v[k] - __bfloat162float(h[k]));
    }
    uint4 hp, lp;
    hp.x = ((uint32_t)__bfloat16_as_ushort(h[1]) << 16) | __bfloat16_as_ushort(h[0]);
    hp.y = ((uint32_t)__bfloat16_as_ushort(h[3]) << 16) | __bfloat16_as_ushort(h[2]);
    hp.z = ((uint32_t)__bfloat16_as_ushort(h[5]) << 16) | __bfloat16_as_ushort(h[4]);
    hp.w = ((uint32_t)__bfloat16_as_ushort(h[7]) << 16) | __bfloat16_as_ushort(h[6]);
    lp.x = ((uint32_t)__bfloat16_as_ushort(l[1]) << 16) | __bfloat16_as_ushort(l[0]);
    lp.y = ((uint32_t)__bfloat16_as_ushort(l[3]) << 16) | __bfloat16_as_ushort(l[2]);
    lp.z = ((uint32_t)__bfloat16_as_ushort(l[5]) << 16) | __bfloat16_as_ushort(l[4]);
    lp.w = ((uint32_t)__bfloat16_as_ushort(l[7]) << 16) | __bfloat16_as_ushort(l[6]);
    ((uint4*)hi)[i] = hp;
    ((uint4*)lo)[i] = lp;
}

// ---------------- HMMA split-bf16 GEMM ---------------------------------------
// Y[M,1024] = X[M,1024] @ W[1024,1024]^T + bias
// CTA tile 128x128, K-chunk 32, 8 warps (2m x 4n), warp tile 64x32.
// smem rows padded to 40 bf16 (80B) -> conflict-free ldmatrix.
#define BK        32
#define ROWB      80                       // bytes per padded smem row
#define TILE_B    (128 * ROWB)             // 10240
#define OFF_AHI   0
#define OFF_ALO   (TILE_B)
#define OFF_BHI   (2 * TILE_B)
#define OFF_BLO   (3 * TILE_B)
#define STAGE_B   (4 * TILE_B)             // 40960
#define SMEM_GEMM (2 * STAGE_B)            // 81920

__device__ __forceinline__ void load_chunk(
    uint32_t sdst,
    const __nv_bfloat16* __restrict__ Xhi, const __nv_bfloat16* __restrict__ Xlo,
    const __nv_bfloat16* __restrict__ Whi, const __nv_bfloat16* __restrict__ Wlo,
    int bm, int bn, int k0, int tid)
{
    #pragma unroll
    for (int it = 0; it < 2; it++) {
        int u = tid + it * 256;            // 0..511
        int r = u >> 2, c = u & 3;         // row 0..127, 16B chunk 0..3
        uint32_t so = (uint32_t)(r * ROWB + c * 16);
        size_t ga = (size_t)(bm + r) * DMODEL + k0 + c * 8;
        size_t gb = (size_t)(bn + r) * DMODEL + k0 + c * 8;
        cpasync16(sdst + OFF_AHI + so, Xhi + ga);
        cpasync16(sdst + OFF_ALO + so, Xlo + ga);
        cpasync16(sdst + OFF_BHI + so, Whi + gb);
        cpasync16(sdst + OFF_BLO + so, Wlo + gb);
    }
}

__device__ __forceinline__ void gemm_hmma_body(
    const __nv_bfloat16* __restrict__ Xhi, const __nv_bfloat16* __restrict__ Xlo,
    const __nv_bfloat16* __restrict__ Whi, const __nv_bfloat16* __restrict__ Wlo,
    const float* __restrict__ bias, float* __restrict__ Y)
{
    extern __shared__ char smem[];
    const uint32_t sb = smem_u32(smem);
    const int tid  = threadIdx.x;
    const int wid  = tid >> 5;
    const int lane = tid & 31;
    const int wm   = wid & 1;              // 0..1 (64 rows each)
    const int wn   = wid >> 1;             // 0..3 (32 cols each)

    const int bm = blockIdx.y * 128;
    const int bn = blockIdx.x * 128;

    float acc[4][4][4];
    #pragma unroll
    for (int mi = 0; mi < 4; mi++)
        #pragma unroll
        for (int ni = 0; ni < 4; ni++)
            #pragma unroll
            for (int e = 0; e < 4; e++) acc[mi][ni][e] = 0.f;

    // ldmatrix lane address components
    const uint32_t a_row  = (uint32_t)(wm * 64 + (lane & 15));
    const uint32_t a_koff = (uint32_t)(((lane >> 4) & 1) * 16);
    const uint32_t b_nrow = (uint32_t)(wn * 32 + (lane & 7) + ((lane >> 4) & 1) * 8);
    const uint32_t b_koff = (uint32_t)(((lane >> 3) & 1) * 16);

    load_chunk(sb, Xhi, Xlo, Whi, Wlo, bm, bn, 0, tid);
    CPASYNC_COMMIT();

    const int NCH = DMODEL / BK;           // 32
    for (int ch = 0; ch < NCH; ch++) {
        const uint32_t st = sb + (uint32_t)(ch & 1) * STAGE_B;
        if (ch + 1 < NCH) {
            load_chunk(sb + (uint32_t)((ch + 1) & 1) * STAGE_B,
                       Xhi, Xlo, Whi, Wlo, bm, bn, (ch + 1) * BK, tid);
            CPASYNC_COMMIT();
            CPASYNC_WAIT(1);
        } else {
            CPASYNC_WAIT(0);
        }
        __syncthreads();

        #pragma unroll
        for (int ks = 0; ks < 2; ks++) {
            const uint32_t kb = (uint32_t)(ks * 32);
            uint32_t aH[4][4], aL[4][4], bH[2][4], bL[2][4];
            #pragma unroll
            for (int mi = 0; mi < 4; mi++) {
                uint32_t ad = st + (a_row + mi * 16) * ROWB + kb + a_koff;
                ldm_x4(aH[mi], ad + OFF_AHI);
                ldm_x4(aL[mi], ad + OFF_ALO);
            }
            #pragma unroll
            for (int p = 0; p < 2; p++) {
                uint32_t bd = st + (b_nrow + p * 16) * ROWB + kb + b_koff;
                ldm_x4(bH[p], bd + OFF_BHI);
                ldm_x4(bL[p], bd + OFF_BLO);
            }
            #pragma unroll
            for (int mi = 0; mi < 4; mi++)
                #pragma unroll
                for (int ni = 0; ni < 4; ni++) {
                    const uint32_t* bh = &bH[ni >> 1][(ni & 1) * 2];
                    const uint32_t* bl = &bL[ni >> 1][(ni & 1) * 2];
                    mma_bf16(acc[mi][ni], aH[mi], bh[0], bh[1]);   // hi*hi
                    mma_bf16(acc[mi][ni], aH[mi], bl[0], bl[1]);   // hi*lo
                    mma_bf16(acc[mi][ni], aL[mi], bh[0], bh[1]);   // lo*hi
                }
        }
        __syncthreads();
    }

    // epilogue: fragment layout c0,c1 -> (row l/4, col 2(l%4)+{0,1}); c2,c3 -> row+8
    const int l4 = lane >> 2;
    const int l2 = (lane & 3) * 2;
    #pragma unroll
    for (int mi = 0; mi < 4; mi++) {
        #pragma unroll
        for (int ni = 0; ni < 4; ni++) {
            int gr = bm + wm * 64 + mi * 16 + l4;
            int gc = bn + wn * 32 + ni * 8 + l2;
            float b0 = bias[gc], b1 = bias[gc + 1];
            float2 o0 = make_float2(acc[mi][ni][0] + b0, acc[mi][ni][1] + b1);
            float2 o1 = make_float2(acc[mi][ni][2] + b0, acc[mi][ni][3] + b1);
            *(float2*)(Y + (size_t)gr * DMODEL + gc)       = o0;
            *(float2*)(Y + (size_t)(gr + 8) * DMODEL + gc) = o1;
        }
    }
}

__global__ __launch_bounds__(256)
void gemm_qkv_mma(const float* __restrict__ bq, const float* __restrict__ bk,
                  const float* __restrict__ bv)
{
    const float* bias; float* Y;
    int z = blockIdx.z;
    if (z == 0)      { bias = bq; Y = g_Q; }
    else if (z == 1) { bias = bk; Y = g_K; }
    else             { bias = bv; Y = g_V; }
    gemm_hmma_body(g_Xhi, g_Xlo, g_Whi + (size_t)z * WSZ, g_Wlo + (size_t)z * WSZ,
                   bias, Y);
}

__global__ __launch_bounds__(256)
void gemm_out_mma(const float* __restrict__ bo, float* __restrict__ Y)
{
    gemm_hmma_body(g_Chi, g_Clo, g_Whi + (size_t)3 * WSZ, g_Wlo + (size_t)3 * WSZ,
                   bo, Y);
}

// ---------------- flash attention (fp32, proven in R1) ----------------------
__device__ __forceinline__ float rmax16(float v) {
    #pragma unroll
    for (int o = 8; o > 0; o >>= 1)
        v = fmaxf(v, __shfl_xor_sync(0xffffffffu, v, o, 16));
    return v;
}
__device__ __forceinline__ float rsum16(float v) {
    #pragma unroll
    for (int o = 8; o > 0; o >>= 1)
        v += __shfl_xor_sync(0xffffffffu, v, o, 16);
    return v;
}

__global__ __launch_bounds__(256)
void flash_attn()
{
    __shared__ float Qs[64][64];
    __shared__ float KP[64][64];
    __shared__ float Vs[64][64];

    const int b  = blockIdx.z;
    const int h  = blockIdx.y;
    const int q0 = blockIdx.x * 64;
    const int tid = threadIdx.x;
    const int tx = tid & 15;
    const int ty = tid >> 4;

    const size_t base = (size_t)b * SEQ * DMODEL + (size_t)h * HDIM;
    const float* Qg = g_Q + base;
    const float* Kg = g_K + base;
    const float* Vg = g_V + base;

    #pragma unroll
    for (int it = 0; it < 4; it++) {
        int v   = tid + it * 256;
        int row = v >> 4;
        int c4  = v & 15;
        float4 qv = *(const float4*)(Qg + (size_t)(q0 + row) * DMODEL + c4 * 4);
        Qs[c4*4+0][row] = qv.x; Qs[c4*4+1][row] = qv.y;
        Qs[c4*4+2][row] = qv.z; Qs[c4*4+3][row] = qv.w;
    }

    float m[4], l[4], acc[4][4];
    #pragma unroll
    for (int i = 0; i < 4; i++) {
        m[i] = -CUDART_INF_F; l[i] = 0.f;
        #pragma unroll
        for (int j = 0; j < 4; j++) acc[i][j] = 0.f;
    }

    for (int kt = 0; kt < SEQ / 64; kt++) {
        const int k0 = kt * 64;
        #pragma unroll
        for (int it = 0; it < 4; it++) {
            int v   = tid + it * 256;
            int row = v >> 4;
            int c4  = v & 15;
            float4 kv = *(const float4*)(Kg + (size_t)(k0 + row) * DMODEL + c4 * 4);
            KP[c4*4+0][row] = kv.x; KP[c4*4+1][row] = kv.y;
            KP[c4*4+2][row] = kv.z; KP[c4*4+3][row] = kv.w;
            float4 vv = *(const float4*)(Vg + (size_t)(k0 + row) * DMODEL + c4 * 4);
            *(float4*)&Vs[row][c4 * 4] = vv;
        }
        __syncthreads();

        float s[4][4] = {};
        #pragma unroll
        for (int d = 0; d < 64; d += 4) {
            float a4[4][4], b4[4][4];
            #pragma unroll
            for (int dd = 0; dd < 4; dd++) {
                *(float4*)a4[dd] = *(const float4*)&Qs[d + dd][ty * 4];
                *(float4*)b4[dd] = *(const float4*)&KP[d + dd][tx * 4];
            }
            #pragma unroll
            for (int dd = 0; dd < 4; dd++)
                #pragma unroll
                for (int i = 0; i < 4; i++)
                    #pragma unroll
                    for (int j = 0; j < 4; j++)
                        s[i][j] = fmaf(a4[dd][i], b4[dd][j], s[i][j]);
        }
        __syncthreads();

        #pragma unroll
        for (int i = 0; i < 4; i++) {
            float lmax = -CUDART_INF_F;
            #pragma unroll
            for (int j = 0; j < 4; j++) {
                s[i][j] *= 0.125f;
                lmax = fmaxf(lmax, s[i][j]);
            }
            float mnew = fmaxf(m[i], rmax16(lmax));
            float corr = __expf(m[i] - mnew);
            float rs = 0.f;
            #pragma unroll
            for (int j = 0; j < 4; j++) {
                s[i][j] = __expf(s[i][j] - mnew);
                rs += s[i][j];
            }
            rs = rsum16(rs);
            l[i] = l[i] * corr + rs;
            m[i] = mnew;
            #pragma unroll
            for (int j = 0; j < 4; j++) acc[i][j] *= corr;
        }

        #pragma unroll
        for (int i = 0; i < 4; i++)
            *(float4*)&KP[ty * 4 + i][tx * 4] =
                make_float4(s[i][0], s[i][1], s[i][2], s[i][3]);
        __syncthreads();

        #pragma unroll
        for (int k = 0; k < 64; k += 4) {
            float a4[4][4], b4[4][4];
            #pragma unroll
            for (int i = 0; i < 4; i++)
                *(float4*)a4[i] = *(const float4*)&KP[ty * 4 + i][k];
            #pragma unroll
            for (int kk = 0; kk < 4; kk++)
                *(float4*)b4[kk] = *(const float4*)&Vs[k + kk][tx * 4];
            #pragma unroll
            for (int kk = 0; kk < 4; kk++)
                #pragma unroll
                for (int i = 0; i < 4; i++)
                    #pragma unroll
                    for (int j = 0; j < 4; j++)
                        acc[i][j] = fmaf(a4[i][kk], b4[kk][j], acc[i][j]);
        }
        __syncthreads();
    }

    // normalize + split to bf16 hi/lo context for the out projection
    #pragma unroll
    for (int i = 0; i < 4; i++) {
        float inv = 1.0f / l[i];
        size_t e = base + (size_t)(q0 + ty * 4 + i) * DMODEL + tx * 4;
        float v[4] = {acc[i][0]*inv, acc[i][1]*inv, acc[i][2]*inv, acc[i][3]*inv};
        __nv_bfloat16 hh[4], ll[4];
        #pragma unroll
        for (int j = 0; j < 4; j++) {
            hh[j] = __float2bfloat16(v[j]);
            ll[j] = __float2bfloat16(v[j] - __bfloat162float(hh[j]));
        }
        uint2 hp, lp;
        hp.x = ((uint32_t)__bfloat16_as_ushort(hh[1]) << 16) | __bfloat16_as_ushort(hh[0]);
        hp.y = ((uint32_t)__bfloat16_as_ushort(hh[3]) << 16) | __bfloat16_as_ushort(hh[2]);
        lp.x = ((uint32_t)__bfloat16_as_ushort(ll[1]) << 16) | __bfloat16_as_ushort(ll[0]);
        lp.y = ((uint32_t)__bfloat16_as_ushort(ll[3]) << 16) | __bfloat16_as_ushort(ll[2]);
        *(uint2*)(g_Chi + e) = hp;
        *(uint2*)(g_Clo + e) = lp;
    }
}

// ---------------------------------------------------------------------------
extern "C" void kernel_launch(void* const* d_in, const int* in_sizes, int n_in,
                              void* d_out, int out_size)
{
    const float* x  = (const float*)d_in[0];
    const float* Wq = (const float*)d_in[1];
    const float* bq = (const float*)d_in[2];
    const float* Wk = (const float*)d_in[3];
    const float* bk = (const float*)d_in[4];
    const float* Wv = (const float*)d_in[5];
    const float* bv = (const float*)d_in[6];
    const float* Wo = (const float*)d_in[7];
    const float* bo = (const float*)d_in[8];
    float* out = (float*)d_out;

    cudaFuncSetAttribute(gemm_qkv_mma, cudaFuncAttributeMaxDynamicSharedMemorySize, SMEM_GEMM);
    cudaFuncSetAttribute(gemm_out_mma, cudaFuncAttributeMaxDynamicSharedMemorySize, SMEM_GEMM);

    __nv_bfloat16 *xhi, *xlo, *whi, *wlo;
    cudaGetSymbolAddress((void**)&xhi, g_Xhi);
    cudaGetSymbolAddress((void**)&xlo, g_Xlo);
    cudaGetSymbolAddress((void**)&whi, g_Whi);
    cudaGetSymbolAddress((void**)&wlo, g_Wlo);

    split_kernel<<<(MTOT * DMODEL / 8 + 255) / 256, 256>>>(x, xhi, xlo, MTOT * DMODEL / 8);
    split_kernel<<<(WSZ / 8 + 255) / 256, 256>>>(Wq, whi + (size_t)0 * WSZ, wlo + (size_t)0 * WSZ, WSZ / 8);
    split_kernel<<<(WSZ / 8 + 255) / 256, 256>>>(Wk, whi + (size_t)1 * WSZ, wlo + (size_t)1 * WSZ, WSZ / 8);
    split_kernel<<<(WSZ / 8 + 255) / 256, 256>>>(Wv, whi + (size_t)2 * WSZ, wlo + (size_t)2 * WSZ, WSZ / 8);
    split_kernel<<<(WSZ / 8 + 255) / 256, 256>>>(Wo, whi + (size_t)3 * WSZ, wlo + (size_t)3 * WSZ, WSZ / 8);

    dim3 qgrid(DMODEL / 128, MTOT / 128, 3);
    gemm_qkv_mma<<<qgrid, 256, SMEM_GEMM>>>(bq, bk, bv);

    dim3 fgrid(SEQ / 64, NHEADS, BATCH);
    flash_attn<<<fgrid, 256>>>();

    dim3 ogrid(DMODEL / 128, MTOT / 128, 1);
    gemm_out_mma<<<ogrid, 256, SMEM_GEMM>>>(bo, out);
}

// round 4
// speedup vs baseline: 2.6592x; 1.9246x over previous
#include <cuda_runtime.h>
#include <cuda_bf16.h>
#include <math_constants.h>
#include <cstdint>

#define BATCH  2
#define SEQ    2048
#define DMODEL 1024
#define NHEADS 16
#define HDIM   64
#define MTOT   (BATCH*SEQ)   // 4096
#define WSZ    (DMODEL*DMODEL)

// ---------------- scratch (allocation-free rule: __device__ globals) --------
__device__ __nv_bfloat16 g_Xhi[(size_t)MTOT * DMODEL];
__device__ __nv_bfloat16 g_Xlo[(size_t)MTOT * DMODEL];
__device__ __nv_bfloat16 g_Whi[(size_t)4 * WSZ];
__device__ __nv_bfloat16 g_Wlo[(size_t)4 * WSZ];
__device__ __nv_bfloat16 g_Qhi[(size_t)MTOT * DMODEL];
__device__ __nv_bfloat16 g_Qlo[(size_t)MTOT * DMODEL];
__device__ __nv_bfloat16 g_Khi[(size_t)MTOT * DMODEL];
__device__ __nv_bfloat16 g_Klo[(size_t)MTOT * DMODEL];
__device__ __nv_bfloat16 g_Vhi[(size_t)MTOT * DMODEL];
__device__ __nv_bfloat16 g_Vlo[(size_t)MTOT * DMODEL];
__device__ __nv_bfloat16 g_Chi[(size_t)MTOT * DMODEL];
__device__ __nv_bfloat16 g_Clo[(size_t)MTOT * DMODEL];

// ---------------- helpers (baseline ISA only) --------------------------------
__device__ __forceinline__ uint32_t smem_u32(const void* p) {
    uint32_t a;
    asm("{ .reg .u64 t; cvta.to.shared.u64 t, %1; cvt.u32.u64 %0, t; }"
        : "=r"(a) : "l"(p));
    return a;
}
__device__ __forceinline__ void cpasync16(uint32_t dst, const void* src) {
    asm volatile("cp.async.cg.shared.global [%0], [%1], 16;" :: "r"(dst), "l"(src));
}
#define CPASYNC_COMMIT() asm volatile("cp.async.commit_group;" ::: "memory")
#define CPASYNC_WAIT(n)  asm volatile("cp.async.wait_group %0;" :: "n"(n) : "memory")

__device__ __forceinline__ void ldm_x4(uint32_t* r, uint32_t addr) {
    asm volatile("ldmatrix.sync.aligned.m8n8.x4.shared.b16 {%0,%1,%2,%3}, [%4];"
        : "=r"(r[0]), "=r"(r[1]), "=r"(r[2]), "=r"(r[3]) : "r"(addr));
}
__device__ __forceinline__ void ldm_x4t(uint32_t* r, uint32_t addr) {
    asm volatile("ldmatrix.sync.aligned.m8n8.x4.trans.shared.b16 {%0,%1,%2,%3}, [%4];"
        : "=r"(r[0]), "=r"(r[1]), "=r"(r[2]), "=r"(r[3]) : "r"(addr));
}
__device__ __forceinline__ void mma_bf16(float* c, const uint32_t* a,
                                         uint32_t b0, uint32_t b1) {
    asm volatile("mma.sync.aligned.m16n8k16.row.col.f32.bf16.bf16.f32 "
        "{%0,%1,%2,%3}, {%4,%5,%6,%7}, {%8,%9}, {%0,%1,%2,%3};"
        : "+f"(c[0]), "+f"(c[1]), "+f"(c[2]), "+f"(c[3])
        : "r"(a[0]), "r"(a[1]), "r"(a[2]), "r"(a[3]), "r"(b0), "r"(b1));
}
__device__ __forceinline__ uint32_t pack2(float v0, float v1) {
    return ((uint32_t)__bfloat16_as_ushort(__float2bfloat16(v1)) << 16)
         |  (uint32_t)__bfloat16_as_ushort(__float2bfloat16(v0));
}
__device__ __forceinline__ void split2(float v0, float v1, uint32_t& hi, uint32_t& lo) {
    __nv_bfloat16 h0 = __float2bfloat16(v0), h1 = __float2bfloat16(v1);
    __nv_bfloat16 l0 = __float2bfloat16(v0 - __bfloat162float(h0));
    __nv_bfloat16 l1 = __float2bfloat16(v1 - __bfloat162float(h1));
    hi = ((uint32_t)__bfloat16_as_ushort(h1) << 16) | __bfloat16_as_ushort(h0);
    lo = ((uint32_t)__bfloat16_as_ushort(l1) << 16) | __bfloat16_as_ushort(l0);
}

// ---------------- fp32 -> (hi, lo) bf16 split --------------------------------
__global__ __launch_bounds__(256)
void split_kernel(const float* __restrict__ src, __nv_bfloat16* __restrict__ hi,
                  __nv_bfloat16* __restrict__ lo, int n8)
{
    int i = blockIdx.x * blockDim.x + threadIdx.x;
    if (i >= n8) return;
    const float4* s = (const float4*)src + (size_t)i * 2;
    float4 a = s[0], b = s[1];
    float v[8] = {a.x, a.y, a.z, a.w, b.x, b.y, b.z, b.w};
    uint4 hp, lp;
    split2(v[0], v[1], hp.x, lp.x);
    split2(v[2], v[3], hp.y, lp.y);
    split2(v[4], v[5], hp.z, lp.z);
    split2(v[6], v[7], hp.w, lp.w);
    ((uint4*)hi)[i] = hp;
    ((uint4*)lo)[i] = lp;
}

// ---------------- HMMA split-bf16 GEMM ---------------------------------------
#define BK        32
#define ROWB      80
#define TILE_B    (128 * ROWB)
#define OFF_AHI   0
#define OFF_ALO   (TILE_B)
#define OFF_BHI   (2 * TILE_B)
#define OFF_BLO   (3 * TILE_B)
#define STAGE_B   (4 * TILE_B)
#define SMEM_GEMM (2 * STAGE_B)

__device__ __forceinline__ void load_chunk(
    uint32_t sdst,
    const __nv_bfloat16* __restrict__ Xhi, const __nv_bfloat16* __restrict__ Xlo,
    const __nv_bfloat16* __restrict__ Whi, const __nv_bfloat16* __restrict__ Wlo,
    int bm, int bn, int k0, int tid)
{
    #pragma unroll
    for (int it = 0; it < 2; it++) {
        int u = tid + it * 256;
        int r = u >> 2, c = u & 3;
        uint32_t so = (uint32_t)(r * ROWB + c * 16);
        size_t ga = (size_t)(bm + r) * DMODEL + k0 + c * 8;
        size_t gb = (size_t)(bn + r) * DMODEL + k0 + c * 8;
        cpasync16(sdst + OFF_AHI + so, Xhi + ga);
        cpasync16(sdst + OFF_ALO + so, Xlo + ga);
        cpasync16(sdst + OFF_BHI + so, Whi + gb);
        cpasync16(sdst + OFF_BLO + so, Wlo + gb);
    }
}

template<int MODE>   // 0: fp32 Y ; 1: split hi/lo bf16
__device__ __forceinline__ void gemm_hmma_body(
    const __nv_bfloat16* __restrict__ Xhi, const __nv_bfloat16* __restrict__ Xlo,
    const __nv_bfloat16* __restrict__ Whi, const __nv_bfloat16* __restrict__ Wlo,
    const float* __restrict__ bias, float* __restrict__ Y,
    __nv_bfloat16* __restrict__ Yhi, __nv_bfloat16* __restrict__ Ylo)
{
    extern __shared__ char smem[];
    const uint32_t sb = smem_u32(smem);
    const int tid  = threadIdx.x;
    const int wid  = tid >> 5;
    const int lane = tid & 31;
    const int wm   = wid & 1;
    const int wn   = wid >> 1;

    const int bm = blockIdx.y * 128;
    const int bn = blockIdx.x * 128;

    float acc[4][4][4];
    #pragma unroll
    for (int mi = 0; mi < 4; mi++)
        #pragma unroll
        for (int ni = 0; ni < 4; ni++)
            #pragma unroll
            for (int e = 0; e < 4; e++) acc[mi][ni][e] = 0.f;

    const uint32_t a_row  = (uint32_t)(wm * 64 + (lane & 15));
    const uint32_t a_koff = (uint32_t)(((lane >> 4) & 1) * 16);
    const uint32_t b_nrow = (uint32_t)(wn * 32 + (lane & 7) + ((lane >> 4) & 1) * 8);
    const uint32_t b_koff = (uint32_t)(((lane >> 3) & 1) * 16);

    load_chunk(sb, Xhi, Xlo, Whi, Wlo, bm, bn, 0, tid);
    CPASYNC_COMMIT();

    const int NCH = DMODEL / BK;
    for (int ch = 0; ch < NCH; ch++) {
        const uint32_t st = sb + (uint32_t)(ch & 1) * STAGE_B;
        if (ch + 1 < NCH) {
            load_chunk(sb + (uint32_t)((ch + 1) & 1) * STAGE_B,
                       Xhi, Xlo, Whi, Wlo, bm, bn, (ch + 1) * BK, tid);
            CPASYNC_COMMIT();
            CPASYNC_WAIT(1);
        } else {
            CPASYNC_WAIT(0);
        }
        __syncthreads();

        #pragma unroll
        for (int ks = 0; ks < 2; ks++) {
            const uint32_t kb = (uint32_t)(ks * 32);
            uint32_t aH[4][4], aL[4][4], bH[2][4], bL[2][4];
            #pragma unroll
            for (int mi = 0; mi < 4; mi++) {
                uint32_t ad = st + (a_row + mi * 16) * ROWB + kb + a_koff;
                ldm_x4(aH[mi], ad + OFF_AHI);
                ldm_x4(aL[mi], ad + OFF_ALO);
            }
            #pragma unroll
            for (int p = 0; p < 2; p++) {
                uint32_t bd = st + (b_nrow + p * 16) * ROWB + kb + b_koff;
                ldm_x4(bH[p], bd + OFF_BHI);
                ldm_x4(bL[p], bd + OFF_BLO);
            }
            #pragma unroll
            for (int mi = 0; mi < 4; mi++)
                #pragma unroll
                for (int ni = 0; ni < 4; ni++) {
                    const uint32_t* bh = &bH[ni >> 1][(ni & 1) * 2];
                    const uint32_t* bl = &bL[ni >> 1][(ni & 1) * 2];
                    mma_bf16(acc[mi][ni], aH[mi], bh[0], bh[1]);
                    mma_bf16(acc[mi][ni], aH[mi], bl[0], bl[1]);
                    mma_bf16(acc[mi][ni], aL[mi], bh[0], bh[1]);
                }
        }
        __syncthreads();
    }

    const int l4 = lane >> 2;
    const int l2 = (lane & 3) * 2;
    #pragma unroll
    for (int mi = 0; mi < 4; mi++) {
        #pragma unroll
        for (int ni = 0; ni < 4; ni++) {
            int gr = bm + wm * 64 + mi * 16 + l4;
            int gc = bn + wn * 32 + ni * 8 + l2;
            float b0 = bias[gc], b1 = bias[gc + 1];
            float v0 = acc[mi][ni][0] + b0, v1 = acc[mi][ni][1] + b1;
            float v2 = acc[mi][ni][2] + b0, v3 = acc[mi][ni][3] + b1;
            if (MODE == 0) {
                *(float2*)(Y + (size_t)gr * DMODEL + gc)       = make_float2(v0, v1);
                *(float2*)(Y + (size_t)(gr + 8) * DMODEL + gc) = make_float2(v2, v3);
            } else {
                uint32_t h0, l0, h1, l1;
                split2(v0, v1, h0, l0);
                split2(v2, v3, h1, l1);
                *(uint32_t*)(Yhi + (size_t)gr * DMODEL + gc)       = h0;
                *(uint32_t*)(Ylo + (size_t)gr * DMODEL + gc)       = l0;
                *(uint32_t*)(Yhi + (size_t)(gr + 8) * DMODEL + gc) = h1;
                *(uint32_t*)(Ylo + (size_t)(gr + 8) * DMODEL + gc) = l1;
            }
        }
    }
}

__global__ __launch_bounds__(256)
void gemm_qkv_mma(const float* __restrict__ bq, const float* __restrict__ bk,
                  const float* __restrict__ bv)
{
    const float* bias; __nv_bfloat16 *Yh, *Yl;
    int z = blockIdx.z;
    if (z == 0)      { bias = bq; Yh = g_Qhi; Yl = g_Qlo; }
    else if (z == 1) { bias = bk; Yh = g_Khi; Yl = g_Klo; }
    else             { bias = bv; Yh = g_Vhi; Yl = g_Vlo; }
    gemm_hmma_body<1>(g_Xhi, g_Xlo, g_Whi + (size_t)z * WSZ, g_Wlo + (size_t)z * WSZ,
                      bias, nullptr, Yh, Yl);
}

__global__ __launch_bounds__(256)
void gemm_out_mma(const float* __restrict__ bo, float* __restrict__ Y)
{
    gemm_hmma_body<0>(g_Chi, g_Clo, g_Whi + (size_t)3 * WSZ, g_Wlo + (size_t)3 * WSZ,
                      bo, Y, nullptr, nullptr);
}

// ---------------- flash attention: split-bf16 HMMA ---------------------------
// CTA: 128 q-rows x one (b,h); 8 warps x 16 rows. K/V tiles of 128 keys,
// double-buffered cp.async. P kept in registers (C-frag == A-frag trick).
#define FROWB   144                       // 64 bf16 = 128B + 16B pad
#define FTILE   (128 * FROWB)             // 18432
#define FQ_HI   0
#define FQ_LO   (FTILE)
#define FSTAGE(s) (2 * FTILE + (s) * 4 * FTILE)
#define FK_HI   0
#define FK_LO   (FTILE)
#define FV_HI   (2 * FTILE)
#define FV_LO   (3 * FTILE)
#define SMEM_FLASH (10 * FTILE)           // 184320

__device__ __forceinline__ void flash_load_q(uint32_t sb, const __nv_bfloat16* Qh,
                                             const __nv_bfloat16* Ql, int q0, int tid)
{
    #pragma unroll
    for (int it = 0; it < 4; it++) {
        int u = tid + it * 256;           // 0..1023
        int r = u >> 3, c = u & 7;
        uint32_t so = (uint32_t)(r * FROWB + c * 16);
        size_t ge = (size_t)(q0 + r) * DMODEL + c * 8;
        cpasync16(sb + FQ_HI + so, Qh + ge);
        cpasync16(sb + FQ_LO + so, Ql + ge);
    }
}
__device__ __forceinline__ void flash_load_kv(uint32_t stb,
    const __nv_bfloat16* Kh, const __nv_bfloat16* Kl,
    const __nv_bfloat16* Vh, const __nv_bfloat16* Vl, int k0, int tid)
{
    #pragma unroll
    for (int it = 0; it < 4; it++) {
        int u = tid + it * 256;
        int r = u >> 3, c = u & 7;
        uint32_t so = (uint32_t)(r * FROWB + c * 16);
        size_t ge = (size_t)(k0 + r) * DMODEL + c * 8;
        cpasync16(stb + FK_HI + so, Kh + ge);
        cpasync16(stb + FK_LO + so, Kl + ge);
        cpasync16(stb + FV_HI + so, Vh + ge);
        cpasync16(stb + FV_LO + so, Vl + ge);
    }
}

__global__ __launch_bounds__(256)
void flash_attn_mma()
{
    extern __shared__ char smem[];
    const uint32_t sb = smem_u32(smem);
    const int tid  = threadIdx.x;
    const int w    = tid >> 5;
    const int lane = tid & 31;

    const int b  = blockIdx.z;
    const int h  = blockIdx.y;
    const int q0 = blockIdx.x * 128;

    const size_t base = (size_t)b * SEQ * DMODEL + (size_t)h * HDIM;
    const __nv_bfloat16* Qh = g_Qhi + base;
    const __nv_bfloat16* Ql = g_Qlo + base;
    const __nv_bfloat16* Kh = g_Khi + base;
    const __nv_bfloat16* Kl = g_Klo + base;
    const __nv_bfloat16* Vh = g_Vhi + base;
    const __nv_bfloat16* Vl = g_Vlo + base;

    // ldmatrix lane addresses
    const uint32_t qa = (uint32_t)((w * 16 + (lane & 15)) * FROWB
                      + ((lane >> 4) & 1) * 16);
    const uint32_t ka_row = (uint32_t)((lane & 7) + ((lane >> 4) & 1) * 8);
    const uint32_t ka_ko  = (uint32_t)(((lane >> 3) & 1) * 16);
    const uint32_t va_row = (uint32_t)(lane & 15);
    const uint32_t va_co  = (uint32_t)(((lane >> 4) & 1) * 16);

    float o[8][4];
    #pragma unroll
    for (int nb = 0; nb < 8; nb++)
        #pragma unroll
        for (int e = 0; e < 4; e++) o[nb][e] = 0.f;
    float m_a = -CUDART_INF_F, m_b = -CUDART_INF_F, l_a = 0.f, l_b = 0.f;

    uint32_t aH[4][4], aL[4][4];

    flash_load_q(sb, Qh, Ql, q0, tid);
    flash_load_kv(sb + FSTAGE(0), Kh, Kl, Vh, Vl, 0, tid);
    CPASYNC_COMMIT();

    const int NKT = SEQ / 128;            // 16
    for (int kt = 0; kt < NKT; kt++) {
        const uint32_t st = sb + FSTAGE(kt & 1);
        if (kt + 1 < NKT) {
            flash_load_kv(sb + FSTAGE((kt + 1) & 1), Kh, Kl, Vh, Vl,
                          (kt + 1) * 128, tid);
            CPASYNC_COMMIT();
            CPASYNC_WAIT(1);
        } else {
            CPASYNC_WAIT(0);
        }
        __syncthreads();

        if (kt == 0) {
            #pragma unroll
            for (int k4 = 0; k4 < 4; k4++) {
                ldm_x4(aH[k4], sb + FQ_HI + qa + k4 * 32);
                ldm_x4(aL[k4], sb + FQ_LO + qa + k4 * 32);
            }
        }

        // ---- S = Q K^T (3-pass split), S is 16 x 128 per warp --------------
        float s[16][4];
        #pragma unroll
        for (int j = 0; j < 16; j++)
            #pragma unroll
            for (int e = 0; e < 4; e++) s[j][e] = 0.f;

        #pragma unroll
        for (int k4 = 0; k4 < 4; k4++) {
            #pragma unroll
            for (int nb = 0; nb < 8; nb++) {
                uint32_t bh[4];
                uint32_t kaddr = st + (uint32_t)(nb * 16) * FROWB + ka_row * FROWB
                               + ka_ko + k4 * 32;
                ldm_x4(bh, kaddr + FK_HI);
                mma_bf16(s[2*nb],   aH[k4], bh[0], bh[1]);
                mma_bf16(s[2*nb+1], aH[k4], bh[2], bh[3]);
                mma_bf16(s[2*nb],   aL[k4], bh[0], bh[1]);
                mma_bf16(s[2*nb+1], aL[k4], bh[2], bh[3]);
            }
            #pragma unroll
            for (int nb = 0; nb < 8; nb++) {
                uint32_t bl[4];
                uint32_t kaddr = st + (uint32_t)(nb * 16) * FROWB + ka_row * FROWB
                               + ka_ko + k4 * 32;
                ldm_x4(bl, kaddr + FK_LO);
                mma_bf16(s[2*nb],   aH[k4], bl[0], bl[1]);
                mma_bf16(s[2*nb+1], aH[k4], bl[2], bl[3]);
            }
        }

        // ---- online softmax (rows: a = lane/4, b = lane/4+8) ----------------
        float mloc_a = -CUDART_INF_F, mloc_b = -CUDART_INF_F;
        #pragma unroll
        for (int j = 0; j < 16; j++) {
            s[j][0] *= 0.125f; s[j][1] *= 0.125f;
            s[j][2] *= 0.125f; s[j][3] *= 0.125f;
            mloc_a = fmaxf(mloc_a, fmaxf(s[j][0], s[j][1]));
            mloc_b = fmaxf(mloc_b, fmaxf(s[j][2], s[j][3]));
        }
        mloc_a = fmaxf(mloc_a, __shfl_xor_sync(0xffffffffu, mloc_a, 1));
        mloc_a = fmaxf(mloc_a, __shfl_xor_sync(0xffffffffu, mloc_a, 2));
        mloc_b = fmaxf(mloc_b, __shfl_xor_sync(0xffffffffu, mloc_b, 1));
        mloc_b = fmaxf(mloc_b, __shfl_xor_sync(0xffffffffu, mloc_b, 2));

        float mn_a = fmaxf(m_a, mloc_a), mn_b = fmaxf(m_b, mloc_b);
        float corr_a = __expf(m_a - mn_a), corr_b = __expf(m_b - mn_b);
        m_a = mn_a; m_b = mn_b;

        float rs_a = 0.f, rs_b = 0.f;
        #pragma unroll
        for (int j = 0; j < 16; j++) {
            s[j][0] = __expf(s[j][0] - mn_a);
            s[j][1] = __expf(s[j][1] - mn_a);
            s[j][2] = __expf(s[j][2] - mn_b);
            s[j][3] = __expf(s[j][3] - mn_b);
            rs_a += s[j][0] + s[j][1];
            rs_b += s[j][2] + s[j][3];
        }
        rs_a += __shfl_xor_sync(0xffffffffu, rs_a, 1);
        rs_a += __shfl_xor_sync(0xffffffffu, rs_a, 2);
        rs_b += __shfl_xor_sync(0xffffffffu, rs_b, 1);
        rs_b += __shfl_xor_sync(0xffffffffu, rs_b, 2);
        l_a = l_a * corr_a + rs_a;
        l_b = l_b * corr_b + rs_b;

        #pragma unroll
        for (int nb = 0; nb < 8; nb++) {
            o[nb][0] *= corr_a; o[nb][1] *= corr_a;
            o[nb][2] *= corr_b; o[nb][3] *= corr_b;
        }

        // ---- pack P -> bf16 hi/lo A-fragments -------------------------------
        uint32_t pH[8][4], pL[8][4];
        #pragma unroll
        for (int t = 0; t < 8; t++) {
            split2(s[2*t][0],   s[2*t][1],   pH[t][0], pL[t][0]);
            split2(s[2*t][2],   s[2*t][3],   pH[t][1], pL[t][1]);
            split2(s[2*t+1][0], s[2*t+1][1], pH[t][2], pL[t][2]);
            split2(s[2*t+1][2], s[2*t+1][3], pH[t][3], pL[t][3]);
        }

        // ---- O += P V (3-pass split) ----------------------------------------
        #pragma unroll
        for (int t = 0; t < 8; t++) {
            #pragma unroll
            for (int ng = 0; ng < 4; ng++) {
                uint32_t vaddr = st + (uint32_t)(t * 16 + va_row) * FROWB
                               + (uint32_t)(ng * 32) + va_co;
                uint32_t vh[4], vl[4];
                ldm_x4t(vh, vaddr + FV_HI);
                mma_bf16(o[2*ng],   pH[t], vh[0], vh[1]);
                mma_bf16(o[2*ng+1], pH[t], vh[2], vh[3]);
                mma_bf16(o[2*ng],   pL[t], vh[0], vh[1]);
                mma_bf16(o[2*ng+1], pL[t], vh[2], vh[3]);
                ldm_x4t(vl, vaddr + FV_LO);
                mma_bf16(o[2*ng],   pH[t], vl[0], vl[1]);
                mma_bf16(o[2*ng+1], pH[t], vl[2], vl[3]);
            }
        }
        __syncthreads();
    }

    // ---- epilogue: normalize, split, write ctx hi/lo ------------------------
    const float inv_a = 1.0f / l_a, inv_b = 1.0f / l_b;
    const int row_a = q0 + w * 16 + (lane >> 2);
    const int col0  = (lane & 3) * 2;
    #pragma unroll
    for (int nb = 0; nb < 8; nb++) {
        int col = nb * 8 + col0;
        uint32_t h0, l0, h1, l1;
        split2(o[nb][0] * inv_a, o[nb][1] * inv_a, h0, l0);
        split2(o[nb][2] * inv_b, o[nb][3] * inv_b, h1, l1);
        size_t ea = base + (size_t)row_a * DMODEL + col;
        size_t eb = base + (size_t)(row_a + 8) * DMODEL + col;
        *(uint32_t*)(g_Chi + ea) = h0;
        *(uint32_t*)(g_Clo + ea) = l0;
        *(uint32_t*)(g_Chi + eb) = h1;
        *(uint32_t*)(g_Clo + eb) = l1;
    }
}

// ---------------------------------------------------------------------------
extern "C" void kernel_launch(void* const* d_in, const int* in_sizes, int n_in,
                              void* d_out, int out_size)
{
    const float* x  = (const float*)d_in[0];
    const float* Wq = (const float*)d_in[1];
    const float* bq = (const float*)d_in[2];
    const float* Wk = (const float*)d_in[3];
    const float* bk = (const float*)d_in[4];
    const float* Wv = (const float*)d_in[5];
    const float* bv = (const float*)d_in[6];
    const float* Wo = (const float*)d_in[7];
    const float* bo = (const float*)d_in[8];
    float* out = (float*)d_out;

    cudaFuncSetAttribute(gemm_qkv_mma,  cudaFuncAttributeMaxDynamicSharedMemorySize, SMEM_GEMM);
    cudaFuncSetAttribute(gemm_out_mma,  cudaFuncAttributeMaxDynamicSharedMemorySize, SMEM_GEMM);
    cudaFuncSetAttribute(flash_attn_mma, cudaFuncAttributeMaxDynamicSharedMemorySize, SMEM_FLASH);

    __nv_bfloat16 *xhi, *xlo, *whi, *wlo;
    cudaGetSymbolAddress((void**)&xhi, g_Xhi);
    cudaGetSymbolAddress((void**)&xlo, g_Xlo);
    cudaGetSymbolAddress((void**)&whi, g_Whi);
    cudaGetSymbolAddress((void**)&wlo, g_Wlo);

    split_kernel<<<(MTOT * DMODEL / 8 + 255) / 256, 256>>>(x, xhi, xlo, MTOT * DMODEL / 8);
    split_kernel<<<(WSZ / 8 + 255) / 256, 256>>>(Wq, whi + (size_t)0 * WSZ, wlo + (size_t)0 * WSZ, WSZ / 8);
    split_kernel<<<(WSZ / 8 + 255) / 256, 256>>>(Wk, whi + (size_t)1 * WSZ, wlo + (size_t)1 * WSZ, WSZ / 8);
    split_kernel<<<(WSZ / 8 + 255) / 256, 256>>>(Wv, whi + (size_t)2 * WSZ, wlo + (size_t)2 * WSZ, WSZ / 8);
    split_kernel<<<(WSZ / 8 + 255) / 256, 256>>>(Wo, whi + (size_t)3 * WSZ, wlo + (size_t)3 * WSZ, WSZ / 8);

    dim3 qgrid(DMODEL / 128, MTOT / 128, 3);
    gemm_qkv_mma<<<qgrid, 256, SMEM_GEMM>>>(bq, bk, bv);

    dim3 fgrid(SEQ / 128, NHEADS, BATCH);
    flash_attn_mma<<<fgrid, 256, SMEM_FLASH>>>();

    dim3 ogrid(DMODEL / 128, MTOT / 128, 1);
    gemm_out_mma<<<ogrid, 256, SMEM_GEMM>>>(bo, out);
}

// round 5
// speedup vs baseline: 2.9232x; 1.0993x over previous
#include <cuda_runtime.h>
#include <cuda_bf16.h>
#include <math_constants.h>
#include <cstdint>

#define BATCH  2
#define SEQ    2048
#define DMODEL 1024
#define NHEADS 16
#define HDIM   64
#define MTOT   (BATCH*SEQ)   // 4096
#define WSZ    (DMODEL*DMODEL)

// ---------------- scratch (allocation-free rule: __device__ globals) --------
__device__ __nv_bfloat16 g_Xhi[(size_t)MTOT * DMODEL];
__device__ __nv_bfloat16 g_Xlo[(size_t)MTOT * DMODEL];
__device__ __nv_bfloat16 g_Whi[(size_t)4 * WSZ];
__device__ __nv_bfloat16 g_Wlo[(size_t)4 * WSZ];
__device__ __nv_bfloat16 g_Qhi[(size_t)MTOT * DMODEL];
__device__ __nv_bfloat16 g_Qlo[(size_t)MTOT * DMODEL];
__device__ __nv_bfloat16 g_Khi[(size_t)MTOT * DMODEL];
__device__ __nv_bfloat16 g_Klo[(size_t)MTOT * DMODEL];
__device__ __nv_bfloat16 g_Vhi[(size_t)MTOT * DMODEL];
__device__ __nv_bfloat16 g_Vlo[(size_t)MTOT * DMODEL];
__device__ __nv_bfloat16 g_Chi[(size_t)MTOT * DMODEL];
__device__ __nv_bfloat16 g_Clo[(size_t)MTOT * DMODEL];

// ---------------- helpers (baseline ISA only) --------------------------------
__device__ __forceinline__ uint32_t smem_u32(const void* p) {
    uint32_t a;
    asm("{ .reg .u64 t; cvta.to.shared.u64 t, %1; cvt.u32.u64 %0, t; }"
        : "=r"(a) : "l"(p));
    return a;
}
__device__ __forceinline__ void cpasync16(uint32_t dst, const void* src) {
    asm volatile("cp.async.cg.shared.global [%0], [%1], 16;" :: "r"(dst), "l"(src));
}
#define CPASYNC_COMMIT() asm volatile("cp.async.commit_group;" ::: "memory")
#define CPASYNC_WAIT(n)  asm volatile("cp.async.wait_group %0;" :: "n"(n) : "memory")

__device__ __forceinline__ void ldm_x4(uint32_t* r, uint32_t addr) {
    asm volatile("ldmatrix.sync.aligned.m8n8.x4.shared.b16 {%0,%1,%2,%3}, [%4];"
        : "=r"(r[0]), "=r"(r[1]), "=r"(r[2]), "=r"(r[3]) : "r"(addr));
}
__device__ __forceinline__ void ldm_x4t(uint32_t* r, uint32_t addr) {
    asm volatile("ldmatrix.sync.aligned.m8n8.x4.trans.shared.b16 {%0,%1,%2,%3}, [%4];"
        : "=r"(r[0]), "=r"(r[1]), "=r"(r[2]), "=r"(r[3]) : "r"(addr));
}
__device__ __forceinline__ void mma_bf16(float* c, const uint32_t* a,
                                         uint32_t b0, uint32_t b1) {
    asm volatile("mma.sync.aligned.m16n8k16.row.col.f32.bf16.bf16.f32 "
        "{%0,%1,%2,%3}, {%4,%5,%6,%7}, {%8,%9}, {%0,%1,%2,%3};"
        : "+f"(c[0]), "+f"(c[1]), "+f"(c[2]), "+f"(c[3])
        : "r"(a[0]), "r"(a[1]), "r"(a[2]), "r"(a[3]), "r"(b0), "r"(b1));
}
__device__ __forceinline__ void split2(float v0, float v1, uint32_t& hi, uint32_t& lo) {
    __nv_bfloat16 h0 = __float2bfloat16(v0), h1 = __float2bfloat16(v1);
    __nv_bfloat16 l0 = __float2bfloat16(v0 - __bfloat162float(h0));
    __nv_bfloat16 l1 = __float2bfloat16(v1 - __bfloat162float(h1));
    hi = ((uint32_t)__bfloat16_as_ushort(h1) << 16) | __bfloat16_as_ushort(h0);
    lo = ((uint32_t)__bfloat16_as_ushort(l1) << 16) | __bfloat16_as_ushort(l0);
}

// ---------------- fused fp32 -> (hi, lo) bf16 split for x + 4 weights --------
#define XN8  (MTOT * DMODEL / 8)          // 524288
#define WN8  (WSZ / 8)                    // 131072
__global__ __launch_bounds__(256)
void split_all(const float* __restrict__ x,  const float* __restrict__ Wq,
               const float* __restrict__ Wk, const float* __restrict__ Wv,
               const float* __restrict__ Wo)
{
    int id = blockIdx.x * 256 + threadIdx.x;
    const float* src;
    __nv_bfloat16 *hi, *lo;
    int off;
    if (id < XN8) {
        src = x; hi = g_Xhi; lo = g_Xlo; off = id;
    } else {
        int r = (id - XN8) >> 17;          // WN8 = 2^17
        off   = (id - XN8) & (WN8 - 1);
        src = (r == 0) ? Wq : (r == 1) ? Wk : (r == 2) ? Wv : Wo;
        hi = g_Whi + (size_t)r * WSZ;
        lo = g_Wlo + (size_t)r * WSZ;
    }
    const float4* s = (const float4*)src + (size_t)off * 2;
    float4 a = s[0], b = s[1];
    uint4 hp, lp;
    split2(a.x, a.y, hp.x, lp.x);
    split2(a.z, a.w, hp.y, lp.y);
    split2(b.x, b.y, hp.z, lp.z);
    split2(b.z, b.w, hp.w, lp.w);
    ((uint4*)hi)[off] = hp;
    ((uint4*)lo)[off] = lp;
}

// ---------------- HMMA split-bf16 GEMM (unchanged from R4) -------------------
#define BK        32
#define ROWB      80
#define TILE_B    (128 * ROWB)
#define OFF_AHI   0
#define OFF_ALO   (TILE_B)
#define OFF_BHI   (2 * TILE_B)
#define OFF_BLO   (3 * TILE_B)
#define STAGE_B   (4 * TILE_B)
#define SMEM_GEMM (2 * STAGE_B)

__device__ __forceinline__ void load_chunk(
    uint32_t sdst,
    const __nv_bfloat16* __restrict__ Xhi, const __nv_bfloat16* __restrict__ Xlo,
    const __nv_bfloat16* __restrict__ Whi, const __nv_bfloat16* __restrict__ Wlo,
    int bm, int bn, int k0, int tid)
{
    #pragma unroll
    for (int it = 0; it < 2; it++) {
        int u = tid + it * 256;
        int r = u >> 2, c = u & 3;
        uint32_t so = (uint32_t)(r * ROWB + c * 16);
        size_t ga = (size_t)(bm + r) * DMODEL + k0 + c * 8;
        size_t gb = (size_t)(bn + r) * DMODEL + k0 + c * 8;
        cpasync16(sdst + OFF_AHI + so, Xhi + ga);
        cpasync16(sdst + OFF_ALO + so, Xlo + ga);
        cpasync16(sdst + OFF_BHI + so, Whi + gb);
        cpasync16(sdst + OFF_BLO + so, Wlo + gb);
    }
}

template<int MODE>   // 0: fp32 Y ; 1: split hi/lo bf16
__device__ __forceinline__ void gemm_hmma_body(
    const __nv_bfloat16* __restrict__ Xhi, const __nv_bfloat16* __restrict__ Xlo,
    const __nv_bfloat16* __restrict__ Whi, const __nv_bfloat16* __restrict__ Wlo,
    const float* __restrict__ bias, float* __restrict__ Y,
    __nv_bfloat16* __restrict__ Yhi, __nv_bfloat16* __restrict__ Ylo)
{
    extern __shared__ char smem[];
    const uint32_t sb = smem_u32(smem);
    const int tid  = threadIdx.x;
    const int wid  = tid >> 5;
    const int lane = tid & 31;
    const int wm   = wid & 1;
    const int wn   = wid >> 1;

    const int bm = blockIdx.y * 128;
    const int bn = blockIdx.x * 128;

    float acc[4][4][4];
    #pragma unroll
    for (int mi = 0; mi < 4; mi++)
        #pragma unroll
        for (int ni = 0; ni < 4; ni++)
            #pragma unroll
            for (int e = 0; e < 4; e++) acc[mi][ni][e] = 0.f;

    const uint32_t a_row  = (uint32_t)(wm * 64 + (lane & 15));
    const uint32_t a_koff = (uint32_t)(((lane >> 4) & 1) * 16);
    const uint32_t b_nrow = (uint32_t)(wn * 32 + (lane & 7) + ((lane >> 4) & 1) * 8);
    const uint32_t b_koff = (uint32_t)(((lane >> 3) & 1) * 16);

    load_chunk(sb, Xhi, Xlo, Whi, Wlo, bm, bn, 0, tid);
    CPASYNC_COMMIT();

    const int NCH = DMODEL / BK;
    for (int ch = 0; ch < NCH; ch++) {
        const uint32_t st = sb + (uint32_t)(ch & 1) * STAGE_B;
        if (ch + 1 < NCH) {
            load_chunk(sb + (uint32_t)((ch + 1) & 1) * STAGE_B,
                       Xhi, Xlo, Whi, Wlo, bm, bn, (ch + 1) * BK, tid);
            CPASYNC_COMMIT();
            CPASYNC_WAIT(1);
        } else {
            CPASYNC_WAIT(0);
        }
        __syncthreads();

        #pragma unroll
        for (int ks = 0; ks < 2; ks++) {
            const uint32_t kb = (uint32_t)(ks * 32);
            uint32_t aH[4][4], aL[4][4], bH[2][4], bL[2][4];
            #pragma unroll
            for (int mi = 0; mi < 4; mi++) {
                uint32_t ad = st + (a_row + mi * 16) * ROWB + kb + a_koff;
                ldm_x4(aH[mi], ad + OFF_AHI);
                ldm_x4(aL[mi], ad + OFF_ALO);
            }
            #pragma unroll
            for (int p = 0; p < 2; p++) {
                uint32_t bd = st + (b_nrow + p * 16) * ROWB + kb + b_koff;
                ldm_x4(bH[p], bd + OFF_BHI);
                ldm_x4(bL[p], bd + OFF_BLO);
            }
            #pragma unroll
            for (int mi = 0; mi < 4; mi++)
                #pragma unroll
                for (int ni = 0; ni < 4; ni++) {
                    const uint32_t* bh = &bH[ni >> 1][(ni & 1) * 2];
                    const uint32_t* bl = &bL[ni >> 1][(ni & 1) * 2];
                    mma_bf16(acc[mi][ni], aH[mi], bh[0], bh[1]);
                    mma_bf16(acc[mi][ni], aH[mi], bl[0], bl[1]);
                    mma_bf16(acc[mi][ni], aL[mi], bh[0], bh[1]);
                }
        }
        __syncthreads();
    }

    const int l4 = lane >> 2;
    const int l2 = (lane & 3) * 2;
    #pragma unroll
    for (int mi = 0; mi < 4; mi++) {
        #pragma unroll
        for (int ni = 0; ni < 4; ni++) {
            int gr = bm + wm * 64 + mi * 16 + l4;
            int gc = bn + wn * 32 + ni * 8 + l2;
            float b0 = bias[gc], b1 = bias[gc + 1];
            float v0 = acc[mi][ni][0] + b0, v1 = acc[mi][ni][1] + b1;
            float v2 = acc[mi][ni][2] + b0, v3 = acc[mi][ni][3] + b1;
            if (MODE == 0) {
                *(float2*)(Y + (size_t)gr * DMODEL + gc)       = make_float2(v0, v1);
                *(float2*)(Y + (size_t)(gr + 8) * DMODEL + gc) = make_float2(v2, v3);
            } else {
                uint32_t h0, l0, h1, l1;
                split2(v0, v1, h0, l0);
                split2(v2, v3, h1, l1);
                *(uint32_t*)(Yhi + (size_t)gr * DMODEL + gc)       = h0;
                *(uint32_t*)(Ylo + (size_t)gr * DMODEL + gc)       = l0;
                *(uint32_t*)(Yhi + (size_t)(gr + 8) * DMODEL + gc) = h1;
                *(uint32_t*)(Ylo + (size_t)(gr + 8) * DMODEL + gc) = l1;
            }
        }
    }
}

__global__ __launch_bounds__(256)
void gemm_qkv_mma(const float* __restrict__ bq, const float* __restrict__ bk,
                  const float* __restrict__ bv)
{
    const float* bias; __nv_bfloat16 *Yh, *Yl;
    int z = blockIdx.z;
    if (z == 0)      { bias = bq; Yh = g_Qhi; Yl = g_Qlo; }
    else if (z == 1) { bias = bk; Yh = g_Khi; Yl = g_Klo; }
    else             { bias = bv; Yh = g_Vhi; Yl = g_Vlo; }
    gemm_hmma_body<1>(g_Xhi, g_Xlo, g_Whi + (size_t)z * WSZ, g_Wlo + (size_t)z * WSZ,
                      bias, nullptr, Yh, Yl);
}

__global__ __launch_bounds__(256)
void gemm_out_mma(const float* __restrict__ bo, float* __restrict__ Y)
{
    gemm_hmma_body<0>(g_Chi, g_Clo, g_Whi + (size_t)3 * WSZ, g_Wlo + (size_t)3 * WSZ,
                      bo, Y, nullptr, nullptr);
}

// ---------------- flash attention v2: 64-key tiles, 2 CTAs/SM ----------------
#define FROWB   144                        // 64 bf16 = 128B + 16B pad
#define FQTILE  (128 * FROWB)              // 18432 (Q: 128 rows)
#define KTILE   (64 * FROWB)               // 9216  (K/V: 64 rows)
#define FQ_HI   0
#define FQ_LO   (FQTILE)
#define FSTAGE(s) (2 * FQTILE + (s) * 4 * KTILE)
#define FK_HI   0
#define FK_LO   (KTILE)
#define FV_HI   (2 * KTILE)
#define FV_LO   (3 * KTILE)
#define SMEM_FLASH (2 * FQTILE + 8 * KTILE)   // 110592 (108 KB)

__device__ __forceinline__ void flash_load_q(uint32_t sb, const __nv_bfloat16* Qh,
                                             const __nv_bfloat16* Ql, int q0, int tid)
{
    #pragma unroll
    for (int it = 0; it < 4; it++) {
        int u = tid + it * 256;           // 0..1023
        int r = u >> 3, c = u & 7;
        uint32_t so = (uint32_t)(r * FROWB + c * 16);
        size_t ge = (size_t)(q0 + r) * DMODEL + c * 8;
        cpasync16(sb + FQ_HI + so, Qh + ge);
        cpasync16(sb + FQ_LO + so, Ql + ge);
    }
}
__device__ __forceinline__ void flash_load_kv(uint32_t stb,
    const __nv_bfloat16* Kh, const __nv_bfloat16* Kl,
    const __nv_bfloat16* Vh, const __nv_bfloat16* Vl, int k0, int tid)
{
    #pragma unroll
    for (int it = 0; it < 2; it++) {
        int u = tid + it * 256;           // 0..511
        int r = u >> 3, c = u & 7;
        uint32_t so = (uint32_t)(r * FROWB + c * 16);
        size_t ge = (size_t)(k0 + r) * DMODEL + c * 8;
        cpasync16(stb + FK_HI + so, Kh + ge);
        cpasync16(stb + FK_LO + so, Kl + ge);
        cpasync16(stb + FV_HI + so, Vh + ge);
        cpasync16(stb + FV_LO + so, Vl + ge);
    }
}

__global__ __launch_bounds__(256, 2)
void flash_attn_mma()
{
    extern __shared__ char smem[];
    const uint32_t sb = smem_u32(smem);
    const int tid  = threadIdx.x;
    const int w    = tid >> 5;
    const int lane = tid & 31;

    const int b  = blockIdx.z;
    const int h  = blockIdx.y;
    const int q0 = blockIdx.x * 128;

    const size_t base = (size_t)b * SEQ * DMODEL + (size_t)h * HDIM;
    const __nv_bfloat16* Qh = g_Qhi + base;
    const __nv_bfloat16* Ql = g_Qlo + base;
    const __nv_bfloat16* Kh = g_Khi + base;
    const __nv_bfloat16* Kl = g_Klo + base;
    const __nv_bfloat16* Vh = g_Vhi + base;
    const __nv_bfloat16* Vl = g_Vlo + base;

    const uint32_t qa = (uint32_t)((w * 16 + (lane & 15)) * FROWB
                      + ((lane >> 4) & 1) * 16);
    const uint32_t ka_row = (uint32_t)((lane & 7) + ((lane >> 4) & 1) * 8);
    const uint32_t ka_ko  = (uint32_t)(((lane >> 3) & 1) * 16);
    const uint32_t va_row = (uint32_t)(lane & 15);
    const uint32_t va_co  = (uint32_t)(((lane >> 4) & 1) * 16);

    float o[8][4];
    #pragma unroll
    for (int nb = 0; nb < 8; nb++)
        #pragma unroll
        for (int e = 0; e < 4; e++) o[nb][e] = 0.f;
    float m_a = -CUDART_INF_F, m_b = -CUDART_INF_F, l_a = 0.f, l_b = 0.f;

    uint32_t aH[4][4], aL[4][4];

    flash_load_q(sb, Qh, Ql, q0, tid);
    flash_load_kv(sb + FSTAGE(0), Kh, Kl, Vh, Vl, 0, tid);
    CPASYNC_COMMIT();

    const int NKT = SEQ / 64;             // 32
    for (int kt = 0; kt < NKT; kt++) {
        const uint32_t st = sb + FSTAGE(kt & 1);
        if (kt + 1 < NKT) {
            flash_load_kv(sb + FSTAGE((kt + 1) & 1), Kh, Kl, Vh, Vl,
                          (kt + 1) * 64, tid);
            CPASYNC_COMMIT();
            CPASYNC_WAIT(1);
        } else {
            CPASYNC_WAIT(0);
        }
        __syncthreads();

        if (kt == 0) {
            #pragma unroll
            for (int k4 = 0; k4 < 4; k4++) {
                ldm_x4(aH[k4], sb + FQ_HI + qa + k4 * 32);
                ldm_x4(aL[k4], sb + FQ_LO + qa + k4 * 32);
            }
        }

        // ---- S = Q K^T (3-pass split), 16 x 64 per warp ---------------------
        float s[8][4];
        #pragma unroll
        for (int j = 0; j < 8; j++)
            #pragma unroll
            for (int e = 0; e < 4; e++) s[j][e] = 0.f;

        #pragma unroll
        for (int k4 = 0; k4 < 4; k4++) {
            #pragma unroll
            for (int nb = 0; nb < 4; nb++) {
                uint32_t bh[4];
                uint32_t kaddr = st + FK_HI + (uint32_t)(nb * 16 + 0) * FROWB
                               + ka_row * FROWB + ka_ko + k4 * 32;
                ldm_x4(bh, kaddr);
                mma_bf16(s[2*nb],   aH[k4], bh[0], bh[1]);
                mma_bf16(s[2*nb+1], aH[k4], bh[2], bh[3]);
                mma_bf16(s[2*nb],   aL[k4], bh[0], bh[1]);
                mma_bf16(s[2*nb+1], aL[k4], bh[2], bh[3]);
            }
            #pragma unroll
            for (int nb = 0; nb < 4; nb++) {
                uint32_t bl[4];
                uint32_t kaddr = st + FK_LO + (uint32_t)(nb * 16 + 0) * FROWB
                               + ka_row * FROWB + ka_ko + k4 * 32;
                ldm_x4(bl, kaddr);
                mma_bf16(s[2*nb],   aH[k4], bl[0], bl[1]);
                mma_bf16(s[2*nb+1], aH[k4], bl[2], bl[3]);
            }
        }

        // ---- online softmax (rows a = lane/4, b = lane/4+8) -----------------
        float mloc_a = -CUDART_INF_F, mloc_b = -CUDART_INF_F;
        #pragma unroll
        for (int j = 0; j < 8; j++) {
            s[j][0] *= 0.125f; s[j][1] *= 0.125f;
            s[j][2] *= 0.125f; s[j][3] *= 0.125f;
            mloc_a = fmaxf(mloc_a, fmaxf(s[j][0], s[j][1]));
            mloc_b = fmaxf(mloc_b, fmaxf(s[j][2], s[j][3]));
        }
        mloc_a = fmaxf(mloc_a, __shfl_xor_sync(0xffffffffu, mloc_a, 1));
        mloc_a = fmaxf(mloc_a, __shfl_xor_sync(0xffffffffu, mloc_a, 2));
        mloc_b = fmaxf(mloc_b, __shfl_xor_sync(0xffffffffu, mloc_b, 1));
        mloc_b = fmaxf(mloc_b, __shfl_xor_sync(0xffffffffu, mloc_b, 2));

        float mn_a = fmaxf(m_a, mloc_a), mn_b = fmaxf(m_b, mloc_b);
        float corr_a = __expf(m_a - mn_a), corr_b = __expf(m_b - mn_b);
        m_a = mn_a; m_b = mn_b;

        float rs_a = 0.f, rs_b = 0.f;
        #pragma unroll
        for (int j = 0; j < 8; j++) {
            s[j][0] = __expf(s[j][0] - mn_a);
            s[j][1] = __expf(s[j][1] - mn_a);
            s[j][2] = __expf(s[j][2] - mn_b);
            s[j][3] = __expf(s[j][3] - mn_b);
            rs_a += s[j][0] + s[j][1];
            rs_b += s[j][2] + s[j][3];
        }
        rs_a += __shfl_xor_sync(0xffffffffu, rs_a, 1);
        rs_a += __shfl_xor_sync(0xffffffffu, rs_a, 2);
        rs_b += __shfl_xor_sync(0xffffffffu, rs_b, 1);
        rs_b += __shfl_xor_sync(0xffffffffu, rs_b, 2);
        l_a = l_a * corr_a + rs_a;
        l_b = l_b * corr_b + rs_b;

        #pragma unroll
        for (int nb = 0; nb < 8; nb++) {
            o[nb][0] *= corr_a; o[nb][1] *= corr_a;
            o[nb][2] *= corr_b; o[nb][3] *= corr_b;
        }

        // ---- O += P V: pack P per 16-key group, then 3-pass MMA -------------
        #pragma unroll
        for (int t = 0; t < 4; t++) {
            uint32_t pH[4], pL[4];
            split2(s[2*t][0],   s[2*t][1],   pH[0], pL[0]);
            split2(s[2*t][2],   s[2*t][3],   pH[1], pL[1]);
            split2(s[2*t+1][0], s[2*t+1][1], pH[2], pL[2]);
            split2(s[2*t+1][2], s[2*t+1][3], pH[3], pL[3]);
            #pragma unroll
            for (int ng = 0; ng < 4; ng++) {
                uint32_t vaddr = st + (uint32_t)(t * 16 + va_row) * FROWB
                               + (uint32_t)(ng * 32) + va_co;
                uint32_t vh[4], vl[4];
                ldm_x4t(vh, vaddr + FV_HI);
                mma_bf16(o[2*ng],   pH, vh[0], vh[1]);
                mma_bf16(o[2*ng+1], pH, vh[2], vh[3]);
                mma_bf16(o[2*ng],   pL, vh[0], vh[1]);
                mma_bf16(o[2*ng+1], pL, vh[2], vh[3]);
                ldm_x4t(vl, vaddr + FV_LO);
                mma_bf16(o[2*ng],   pH, vl[0], vl[1]);
                mma_bf16(o[2*ng+1], pH, vl[2], vl[3]);
            }
        }
        __syncthreads();
    }

    // ---- epilogue: normalize, split, write ctx hi/lo ------------------------
    const float inv_a = 1.0f / l_a, inv_b = 1.0f / l_b;
    const int row_a = q0 + w * 16 + (lane >> 2);
    const int col0  = (lane & 3) * 2;
    #pragma unroll
    for (int nb = 0; nb < 8; nb++) {
        int col = nb * 8 + col0;
        uint32_t h0, l0, h1, l1;
        split2(o[nb][0] * inv_a, o[nb][1] * inv_a, h0, l0);
        split2(o[nb][2] * inv_b, o[nb][3] * inv_b, h1, l1);
        size_t ea = base + (size_t)row_a * DMODEL + col;
        size_t eb = base + (size_t)(row_a + 8) * DMODEL + col;
        *(uint32_t*)(g_Chi + ea) = h0;
        *(uint32_t*)(g_Clo + ea) = l0;
        *(uint32_t*)(g_Chi + eb) = h1;
        *(uint32_t*)(g_Clo + eb) = l1;
    }
}

// ---------------------------------------------------------------------------
extern "C" void kernel_launch(void* const* d_in, const int* in_sizes, int n_in,
                              void* d_out, int out_size)
{
    const float* x  = (const float*)d_in[0];
    const float* Wq = (const float*)d_in[1];
    const float* bq = (const float*)d_in[2];
    const float* Wk = (const float*)d_in[3];
    const float* bk = (const float*)d_in[4];
    const float* Wv = (const float*)d_in[5];
    const float* bv = (const float*)d_in[6];
    const float* Wo = (const float*)d_in[7];
    const float* bo = (const float*)d_in[8];
    float* out = (float*)d_out;

    cudaFuncSetAttribute(gemm_qkv_mma,   cudaFuncAttributeMaxDynamicSharedMemorySize, SMEM_GEMM);
    cudaFuncSetAttribute(gemm_out_mma,   cudaFuncAttributeMaxDynamicSharedMemorySize, SMEM_GEMM);
    cudaFuncSetAttribute(flash_attn_mma, cudaFuncAttributeMaxDynamicSharedMemorySize, SMEM_FLASH);

    split_all<<<(XN8 + 4 * WN8) / 256, 256>>>(x, Wq, Wk, Wv, Wo);

    dim3 qgrid(DMODEL / 128, MTOT / 128, 3);
    gemm_qkv_mma<<<qgrid, 256, SMEM_GEMM>>>(bq, bk, bv);

    dim3 fgrid(SEQ / 128, NHEADS, BATCH);
    flash_attn_mma<<<fgrid, 256, SMEM_FLASH>>>();

    dim3 ogrid(DMODEL / 128, MTOT / 128, 1);
    gemm_out_mma<<<ogrid, 256, SMEM_GEMM>>>(bo, out);
}

// round 6
// speedup vs baseline: 2.9864x; 1.0216x over previous
#include <cuda_runtime.h>
#include <cuda_bf16.h>
#include <math_constants.h>
#include <cstdint>

#define BATCH  2
#define SEQ    2048
#define DMODEL 1024
#define NHEADS 16
#define HDIM   64
#define MTOT   (BATCH*SEQ)   // 4096
#define WSZ    (DMODEL*DMODEL)

// ---------------- scratch (allocation-free rule: __device__ globals) --------
__device__ __nv_bfloat16 g_Xhi[(size_t)MTOT * DMODEL];
__device__ __nv_bfloat16 g_Xlo[(size_t)MTOT * DMODEL];
__device__ __nv_bfloat16 g_Whi[(size_t)4 * WSZ];
__device__ __nv_bfloat16 g_Wlo[(size_t)4 * WSZ];
__device__ __nv_bfloat16 g_Qhi[(size_t)MTOT * DMODEL];
__device__ __nv_bfloat16 g_Qlo[(size_t)MTOT * DMODEL];
__device__ __nv_bfloat16 g_Khi[(size_t)MTOT * DMODEL];
__device__ __nv_bfloat16 g_Klo[(size_t)MTOT * DMODEL];
__device__ __nv_bfloat16 g_Vhi[(size_t)MTOT * DMODEL];
__device__ __nv_bfloat16 g_Vlo[(size_t)MTOT * DMODEL];
__device__ __nv_bfloat16 g_Chi[(size_t)MTOT * DMODEL];
__device__ __nv_bfloat16 g_Clo[(size_t)MTOT * DMODEL];

// ---------------- helpers (baseline ISA only) --------------------------------
__device__ __forceinline__ uint32_t smem_u32(const void* p) {
    uint32_t a;
    asm("{ .reg .u64 t; cvta.to.shared.u64 t, %1; cvt.u32.u64 %0, t; }"
        : "=r"(a) : "l"(p));
    return a;
}
__device__ __forceinline__ void cpasync16(uint32_t dst, const void* src) {
    asm volatile("cp.async.cg.shared.global [%0], [%1], 16;" :: "r"(dst), "l"(src));
}
#define CPASYNC_COMMIT() asm volatile("cp.async.commit_group;" ::: "memory")
#define CPASYNC_WAIT(n)  asm volatile("cp.async.wait_group %0;" :: "n"(n) : "memory")

__device__ __forceinline__ void ldm_x4(uint32_t* r, uint32_t addr) {
    asm volatile("ldmatrix.sync.aligned.m8n8.x4.shared.b16 {%0,%1,%2,%3}, [%4];"
        : "=r"(r[0]), "=r"(r[1]), "=r"(r[2]), "=r"(r[3]) : "r"(addr));
}
__device__ __forceinline__ void ldm_x4t(uint32_t* r, uint32_t addr) {
    asm volatile("ldmatrix.sync.aligned.m8n8.x4.trans.shared.b16 {%0,%1,%2,%3}, [%4];"
        : "=r"(r[0]), "=r"(r[1]), "=r"(r[2]), "=r"(r[3]) : "r"(addr));
}
__device__ __forceinline__ void mma_bf16(float* c, const uint32_t* a,
                                         uint32_t b0, uint32_t b1) {
    asm volatile("mma.sync.aligned.m16n8k16.row.col.f32.bf16.bf16.f32 "
        "{%0,%1,%2,%3}, {%4,%5,%6,%7}, {%8,%9}, {%0,%1,%2,%3};"
        : "+f"(c[0]), "+f"(c[1]), "+f"(c[2]), "+f"(c[3])
        : "r"(a[0]), "r"(a[1]), "r"(a[2]), "r"(a[3]), "r"(b0), "r"(b1));
}
__device__ __forceinline__ void split2(float v0, float v1, uint32_t& hi, uint32_t& lo) {
    __nv_bfloat16 h0 = __float2bfloat16(v0), h1 = __float2bfloat16(v1);
    __nv_bfloat16 l0 = __float2bfloat16(v0 - __bfloat162float(h0));
    __nv_bfloat16 l1 = __float2bfloat16(v1 - __bfloat162float(h1));
    hi = ((uint32_t)__bfloat16_as_ushort(h1) << 16) | __bfloat16_as_ushort(h0);
    lo = ((uint32_t)__bfloat16_as_ushort(l1) << 16) | __bfloat16_as_ushort(l0);
}

// ---------------- fused fp32 -> (hi, lo) bf16 split for x + 4 weights --------
#define XN8  (MTOT * DMODEL / 8)          // 524288
#define WN8  (WSZ / 8)                    // 131072
__global__ __launch_bounds__(256)
void split_all(const float* __restrict__ x,  const float* __restrict__ Wq,
               const float* __restrict__ Wk, const float* __restrict__ Wv,
               const float* __restrict__ Wo)
{
    int id = blockIdx.x * 256 + threadIdx.x;
    const float* src;
    __nv_bfloat16 *hi, *lo;
    int off;
    if (id < XN8) {
        src = x; hi = g_Xhi; lo = g_Xlo; off = id;
    } else {
        int r = (id - XN8) >> 17;          // WN8 = 2^17
        off   = (id - XN8) & (WN8 - 1);
        src = (r == 0) ? Wq : (r == 1) ? Wk : (r == 2) ? Wv : Wo;
        hi = g_Whi + (size_t)r * WSZ;
        lo = g_Wlo + (size_t)r * WSZ;
    }
    const float4* s = (const float4*)src + (size_t)off * 2;
    float4 a = s[0], b = s[1];
    uint4 hp, lp;
    split2(a.x, a.y, hp.x, lp.x);
    split2(a.z, a.w, hp.y, lp.y);
    split2(b.x, b.y, hp.z, lp.z);
    split2(b.z, b.w, hp.w, lp.w);
    ((uint4*)hi)[off] = hp;
    ((uint4*)lo)[off] = lp;
}

// ---------------- HMMA split-bf16 GEMM ---------------------------------------
#define BK        32
#define ROWB      80
#define TILE_B    (128 * ROWB)
#define OFF_AHI   0
#define OFF_ALO   (TILE_B)
#define OFF_BHI   (2 * TILE_B)
#define OFF_BLO   (3 * TILE_B)
#define STAGE_B   (4 * TILE_B)
#define SMEM_GEMM (2 * STAGE_B)

__device__ __forceinline__ void load_chunk(
    uint32_t sdst,
    const __nv_bfloat16* __restrict__ Xhi, const __nv_bfloat16* __restrict__ Xlo,
    const __nv_bfloat16* __restrict__ Whi, const __nv_bfloat16* __restrict__ Wlo,
    int bm, int bn, int k0, int tid)
{
    #pragma unroll
    for (int it = 0; it < 2; it++) {
        int u = tid + it * 256;
        int r = u >> 2, c = u & 3;
        uint32_t so = (uint32_t)(r * ROWB + c * 16);
        size_t ga = (size_t)(bm + r) * DMODEL + k0 + c * 8;
        size_t gb = (size_t)(bn + r) * DMODEL + k0 + c * 8;
        cpasync16(sdst + OFF_AHI + so, Xhi + ga);
        cpasync16(sdst + OFF_ALO + so, Xlo + ga);
        cpasync16(sdst + OFF_BHI + so, Whi + gb);
        cpasync16(sdst + OFF_BLO + so, Wlo + gb);
    }
}

template<int MODE>   // 0: fp32 Y ; 1: split hi/lo bf16
__device__ __forceinline__ void gemm_hmma_body(
    const __nv_bfloat16* __restrict__ Xhi, const __nv_bfloat16* __restrict__ Xlo,
    const __nv_bfloat16* __restrict__ Whi, const __nv_bfloat16* __restrict__ Wlo,
    const float* __restrict__ bias, float* __restrict__ Y,
    __nv_bfloat16* __restrict__ Yhi, __nv_bfloat16* __restrict__ Ylo)
{
    extern __shared__ char smem[];
    const uint32_t sb = smem_u32(smem);
    const int tid  = threadIdx.x;
    const int wid  = tid >> 5;
    const int lane = tid & 31;
    const int wm   = wid & 1;
    const int wn   = wid >> 1;

    const int bm = blockIdx.y * 128;
    const int bn = blockIdx.x * 128;

    float acc[4][4][4];
    #pragma unroll
    for (int mi = 0; mi < 4; mi++)
        #pragma unroll
        for (int ni = 0; ni < 4; ni++)
            #pragma unroll
            for (int e = 0; e < 4; e++) acc[mi][ni][e] = 0.f;

    const uint32_t a_row  = (uint32_t)(wm * 64 + (lane & 15));
    const uint32_t a_koff = (uint32_t)(((lane >> 4) & 1) * 16);
    const uint32_t b_nrow = (uint32_t)(wn * 32 + (lane & 7) + ((lane >> 4) & 1) * 8);
    const uint32_t b_koff = (uint32_t)(((lane >> 3) & 1) * 16);

    load_chunk(sb, Xhi, Xlo, Whi, Wlo, bm, bn, 0, tid);
    CPASYNC_COMMIT();

    const int NCH = DMODEL / BK;
    for (int ch = 0; ch < NCH; ch++) {
        const uint32_t st = sb + (uint32_t)(ch & 1) * STAGE_B;
        if (ch + 1 < NCH) {
            load_chunk(sb + (uint32_t)((ch + 1) & 1) * STAGE_B,
                       Xhi, Xlo, Whi, Wlo, bm, bn, (ch + 1) * BK, tid);
            CPASYNC_COMMIT();
            CPASYNC_WAIT(1);
        } else {
            CPASYNC_WAIT(0);
        }
        __syncthreads();

        #pragma unroll
        for (int ks = 0; ks < 2; ks++) {
            const uint32_t kb = (uint32_t)(ks * 32);
            uint32_t aH[4][4], aL[4][4], bH[2][4], bL[2][4];
            #pragma unroll
            for (int mi = 0; mi < 4; mi++) {
                uint32_t ad = st + (a_row + mi * 16) * ROWB + kb + a_koff;
                ldm_x4(aH[mi], ad + OFF_AHI);
                ldm_x4(aL[mi], ad + OFF_ALO);
            }
            #pragma unroll
            for (int p = 0; p < 2; p++) {
                uint32_t bd = st + (b_nrow + p * 16) * ROWB + kb + b_koff;
                ldm_x4(bH[p], bd + OFF_BHI);
                ldm_x4(bL[p], bd + OFF_BLO);
            }
            #pragma unroll
            for (int mi = 0; mi < 4; mi++)
                #pragma unroll
                for (int ni = 0; ni < 4; ni++) {
                    const uint32_t* bh = &bH[ni >> 1][(ni & 1) * 2];
                    const uint32_t* bl = &bL[ni >> 1][(ni & 1) * 2];
                    mma_bf16(acc[mi][ni], aH[mi], bh[0], bh[1]);
                    mma_bf16(acc[mi][ni], aH[mi], bl[0], bl[1]);
                    mma_bf16(acc[mi][ni], aL[mi], bh[0], bh[1]);
                }
        }
        __syncthreads();
    }

    const int l4 = lane >> 2;
    const int l2 = (lane & 3) * 2;
    #pragma unroll
    for (int mi = 0; mi < 4; mi++) {
        #pragma unroll
        for (int ni = 0; ni < 4; ni++) {
            int gr = bm + wm * 64 + mi * 16 + l4;
            int gc = bn + wn * 32 + ni * 8 + l2;
            float b0 = bias[gc], b1 = bias[gc + 1];
            float v0 = acc[mi][ni][0] + b0, v1 = acc[mi][ni][1] + b1;
            float v2 = acc[mi][ni][2] + b0, v3 = acc[mi][ni][3] + b1;
            if (MODE == 0) {
                *(float2*)(Y + (size_t)gr * DMODEL + gc)       = make_float2(v0, v1);
                *(float2*)(Y + (size_t)(gr + 8) * DMODEL + gc) = make_float2(v2, v3);
            } else {
                uint32_t h0, l0, h1, l1;
                split2(v0, v1, h0, l0);
                split2(v2, v3, h1, l1);
                *(uint32_t*)(Yhi + (size_t)gr * DMODEL + gc)       = h0;
                *(uint32_t*)(Ylo + (size_t)gr * DMODEL + gc)       = l0;
                *(uint32_t*)(Yhi + (size_t)(gr + 8) * DMODEL + gc) = h1;
                *(uint32_t*)(Ylo + (size_t)(gr + 8) * DMODEL + gc) = l1;
            }
        }
    }
}

__global__ __launch_bounds__(256, 2)
void gemm_qkv_mma(const float* __restrict__ bq, const float* __restrict__ bk,
                  const float* __restrict__ bv)
{
    const float* bias; __nv_bfloat16 *Yh, *Yl;
    int z = blockIdx.z;
    if (z == 0)      { bias = bq; Yh = g_Qhi; Yl = g_Qlo; }
    else if (z == 1) { bias = bk; Yh = g_Khi; Yl = g_Klo; }
    else             { bias = bv; Yh = g_Vhi; Yl = g_Vlo; }
    gemm_hmma_body<1>(g_Xhi, g_Xlo, g_Whi + (size_t)z * WSZ, g_Wlo + (size_t)z * WSZ,
                      bias, nullptr, Yh, Yl);
}

__global__ __launch_bounds__(256, 2)
void gemm_out_mma(const float* __restrict__ bo, float* __restrict__ Y)
{
    gemm_hmma_body<0>(g_Chi, g_Clo, g_Whi + (size_t)3 * WSZ, g_Wlo + (size_t)3 * WSZ,
                      bo, Y, nullptr, nullptr);
}

// ---------------- flash attention: 64-key tiles, 2 CTAs/SM -------------------
#define FROWB   144                        // 64 bf16 = 128B + 16B pad
#define FQTILE  (128 * FROWB)              // 18432 (Q: 128 rows)
#define KTILE   (64 * FROWB)               // 9216  (K/V: 64 rows)
#define FQ_HI   0
#define FQ_LO   (FQTILE)
#define FSTAGE(s) (2 * FQTILE + (s) * 4 * KTILE)
#define FK_HI   0
#define FK_LO   (KTILE)
#define FV_HI   (2 * KTILE)
#define FV_LO   (3 * KTILE)
#define SMEM_FLASH (2 * FQTILE + 8 * KTILE)   // 110592 (108 KB)

__device__ __forceinline__ void flash_load_q(uint32_t sb, const __nv_bfloat16* Qh,
                                             const __nv_bfloat16* Ql, int q0, int tid)
{
    #pragma unroll
    for (int it = 0; it < 4; it++) {
        int u = tid + it * 256;           // 0..1023
        int r = u >> 3, c = u & 7;
        uint32_t so = (uint32_t)(r * FROWB + c * 16);
        size_t ge = (size_t)(q0 + r) * DMODEL + c * 8;
        cpasync16(sb + FQ_HI + so, Qh + ge);
        cpasync16(sb + FQ_LO + so, Ql + ge);
    }
}
__device__ __forceinline__ void flash_load_kv(uint32_t stb,
    const __nv_bfloat16* Kh, const __nv_bfloat16* Kl,
    const __nv_bfloat16* Vh, const __nv_bfloat16* Vl, int k0, int tid)
{
    #pragma unroll
    for (int it = 0; it < 2; it++) {
        int u = tid + it * 256;           // 0..511
        int r = u >> 3, c = u & 7;
        uint32_t so = (uint32_t)(r * FROWB + c * 16);
        size_t ge = (size_t)(k0 + r) * DMODEL + c * 8;
        cpasync16(stb + FK_HI + so, Kh + ge);
        cpasync16(stb + FK_LO + so, Kl + ge);
        cpasync16(stb + FV_HI + so, Vh + ge);
        cpasync16(stb + FV_LO + so, Vl + ge);
    }
}

__global__ __launch_bounds__(256, 2)
void flash_attn_mma()
{
    extern __shared__ char smem[];
    const uint32_t sb = smem_u32(smem);
    const int tid  = threadIdx.x;
    const int w    = tid >> 5;
    const int lane = tid & 31;

    const int b  = blockIdx.z;
    const int h  = blockIdx.y;
    const int q0 = blockIdx.x * 128;

    const size_t base = (size_t)b * SEQ * DMODEL + (size_t)h * HDIM;
    const __nv_bfloat16* Qh = g_Qhi + base;
    const __nv_bfloat16* Ql = g_Qlo + base;
    const __nv_bfloat16* Kh = g_Khi + base;
    const __nv_bfloat16* Kl = g_Klo + base;
    const __nv_bfloat16* Vh = g_Vhi + base;
    const __nv_bfloat16* Vl = g_Vlo + base;

    const uint32_t qa = (uint32_t)((w * 16 + (lane & 15)) * FROWB
                      + ((lane >> 4) & 1) * 16);
    const uint32_t ka_row = (uint32_t)((lane & 7) + ((lane >> 4) & 1) * 8);
    const uint32_t ka_ko  = (uint32_t)(((lane >> 3) & 1) * 16);
    const uint32_t va_row = (uint32_t)(lane & 15);
    const uint32_t va_co  = (uint32_t)(((lane >> 4) & 1) * 16);

    float o[8][4];
    #pragma unroll
    for (int nb = 0; nb < 8; nb++)
        #pragma unroll
        for (int e = 0; e < 4; e++) o[nb][e] = 0.f;
    float m_a = -CUDART_INF_F, m_b = -CUDART_INF_F, l_a = 0.f, l_b = 0.f;

    uint32_t aH[4][4], aL[4][4];

    flash_load_q(sb, Qh, Ql, q0, tid);
    flash_load_kv(sb + FSTAGE(0), Kh, Kl, Vh, Vl, 0, tid);
    CPASYNC_COMMIT();

    const int NKT = SEQ / 64;             // 32
    for (int kt = 0; kt < NKT; kt++) {
        const uint32_t st = sb + FSTAGE(kt & 1);
        if (kt + 1 < NKT) {
            flash_load_kv(sb + FSTAGE((kt + 1) & 1), Kh, Kl, Vh, Vl,
                          (kt + 1) * 64, tid);
            CPASYNC_COMMIT();
            CPASYNC_WAIT(1);
        } else {
            CPASYNC_WAIT(0);
        }
        __syncthreads();

        if (kt == 0) {
            #pragma unroll
            for (int k4 = 0; k4 < 4; k4++) {
                ldm_x4(aH[k4], sb + FQ_HI + qa + k4 * 32);
                ldm_x4(aL[k4], sb + FQ_LO + qa + k4 * 32);
            }
        }

        // ---- S = Q K^T (3-pass split), 16 x 64 per warp ---------------------
        float s[8][4];
        #pragma unroll
        for (int j = 0; j < 8; j++)
            #pragma unroll
            for (int e = 0; e < 4; e++) s[j][e] = 0.f;

        #pragma unroll
        for (int k4 = 0; k4 < 4; k4++) {
            #pragma unroll
            for (int nb = 0; nb < 4; nb++) {
                uint32_t bh[4];
                uint32_t kaddr = st + FK_HI + (uint32_t)(nb * 16 + 0) * FROWB
                               + ka_row * FROWB + ka_ko + k4 * 32;
                ldm_x4(bh, kaddr);
                mma_bf16(s[2*nb],   aH[k4], bh[0], bh[1]);
                mma_bf16(s[2*nb+1], aH[k4], bh[2], bh[3]);
                mma_bf16(s[2*nb],   aL[k4], bh[0], bh[1]);
                mma_bf16(s[2*nb+1], aL[k4], bh[2], bh[3]);
            }
            #pragma unroll
            for (int nb = 0; nb < 4; nb++) {
                uint32_t bl[4];
                uint32_t kaddr = st + FK_LO + (uint32_t)(nb * 16 + 0) * FROWB
                               + ka_row * FROWB + ka_ko + k4 * 32;
                ldm_x4(bl, kaddr);
                mma_bf16(s[2*nb],   aH[k4], bl[0], bl[1]);
                mma_bf16(s[2*nb+1], aH[k4], bl[2], bl[3]);
            }
        }

        // ---- online softmax (rows a = lane/4, b = lane/4+8) -----------------
        float mloc_a = -CUDART_INF_F, mloc_b = -CUDART_INF_F;
        #pragma unroll
        for (int j = 0; j < 8; j++) {
            s[j][0] *= 0.125f; s[j][1] *= 0.125f;
            s[j][2] *= 0.125f; s[j][3] *= 0.125f;
            mloc_a = fmaxf(mloc_a, fmaxf(s[j][0], s[j][1]));
            mloc_b = fmaxf(mloc_b, fmaxf(s[j][2], s[j][3]));
        }
        mloc_a = fmaxf(mloc_a, __shfl_xor_sync(0xffffffffu, mloc_a, 1));
        mloc_a = fmaxf(mloc_a, __shfl_xor_sync(0xffffffffu, mloc_a, 2));
        mloc_b = fmaxf(mloc_b, __shfl_xor_sync(0xffffffffu, mloc_b, 1));
        mloc_b = fmaxf(mloc_b, __shfl_xor_sync(0xffffffffu, mloc_b, 2));

        float mn_a = fmaxf(m_a, mloc_a), mn_b = fmaxf(m_b, mloc_b);
        float corr_a = __expf(m_a - mn_a), corr_b = __expf(m_b - mn_b);
        m_a = mn_a; m_b = mn_b;

        float rs_a = 0.f, rs_b = 0.f;
        #pragma unroll
        for (int j = 0; j < 8; j++) {
            s[j][0] = __expf(s[j][0] - mn_a);
            s[j][1] = __expf(s[j][1] - mn_a);
            s[j][2] = __expf(s[j][2] - mn_b);
            s[j][3] = __expf(s[j][3] - mn_b);
            rs_a += s[j][0] + s[j][1];
            rs_b += s[j][2] + s[j][3];
        }
        rs_a += __shfl_xor_sync(0xffffffffu, rs_a, 1);
        rs_a += __shfl_xor_sync(0xffffffffu, rs_a, 2);
        rs_b += __shfl_xor_sync(0xffffffffu, rs_b, 1);
        rs_b += __shfl_xor_sync(0xffffffffu, rs_b, 2);
        l_a = l_a * corr_a + rs_a;
        l_b = l_b * corr_b + rs_b;

        #pragma unroll
        for (int nb = 0; nb < 8; nb++) {
            o[nb][0] *= corr_a; o[nb][1] *= corr_a;
            o[nb][2] *= corr_b; o[nb][3] *= corr_b;
        }

        // ---- O += P V: pack P per 16-key group, then 3-pass MMA -------------
        #pragma unroll
        for (int t = 0; t < 4; t++) {
            uint32_t pH[4], pL[4];
            split2(s[2*t][0],   s[2*t][1],   pH[0], pL[0]);
            split2(s[2*t][2],   s[2*t][3],   pH[1], pL[1]);
            split2(s[2*t+1][0], s[2*t+1][1], pH[2], pL[2]);
            split2(s[2*t+1][2], s[2*t+1][3], pH[3], pL[3]);
            #pragma unroll
            for (int ng = 0; ng < 4; ng++) {
                uint32_t vaddr = st + (uint32_t)(t * 16 + va_row) * FROWB
                               + (uint32_t)(ng * 32) + va_co;
                uint32_t vh[4], vl[4];
                ldm_x4t(vh, vaddr + FV_HI);
                mma_bf16(o[2*ng],   pH, vh[0], vh[1]);
                mma_bf16(o[2*ng+1], pH, vh[2], vh[3]);
                mma_bf16(o[2*ng],   pL, vh[0], vh[1]);
                mma_bf16(o[2*ng+1], pL, vh[2], vh[3]);
                ldm_x4t(vl, vaddr + FV_LO);
                mma_bf16(o[2*ng],   pH, vl[0], vl[1]);
                mma_bf16(o[2*ng+1], pH, vl[2], vl[3]);
            }
        }
        __syncthreads();
    }

    // ---- epilogue: normalize, split, write ctx hi/lo ------------------------
    const float inv_a = 1.0f / l_a, inv_b = 1.0f / l_b;
    const int row_a = q0 + w * 16 + (lane >> 2);
    const int col0  = (lane & 3) * 2;
    #pragma unroll
    for (int nb = 0; nb < 8; nb++) {
        int col = nb * 8 + col0;
        uint32_t h0, l0, h1, l1;
        split2(o[nb][0] * inv_a, o[nb][1] * inv_a, h0, l0);
        split2(o[nb][2] * inv_b, o[nb][3] * inv_b, h1, l1);
        size_t ea = base + (size_t)row_a * DMODEL + col;
        size_t eb = base + (size_t)(row_a + 8) * DMODEL + col;
        *(uint32_t*)(g_Chi + ea) = h0;
        *(uint32_t*)(g_Clo + ea) = l0;
        *(uint32_t*)(g_Chi + eb) = h1;
        *(uint32_t*)(g_Clo + eb) = l1;
    }
}

// ---------------------------------------------------------------------------
extern "C" void kernel_launch(void* const* d_in, const int* in_sizes, int n_in,
                              void* d_out, int out_size)
{
    const float* x  = (const float*)d_in[0];
    const float* Wq = (const float*)d_in[1];
    const float* bq = (const float*)d_in[2];
    const float* Wk = (const float*)d_in[3];
    const float* bk = (const float*)d_in[4];
    const float* Wv = (const float*)d_in[5];
    const float* bv = (const float*)d_in[6];
    const float* Wo = (const float*)d_in[7];
    const float* bo = (const float*)d_in[8];
    float* out = (float*)d_out;

    cudaFuncSetAttribute(gemm_qkv_mma,   cudaFuncAttributeMaxDynamicSharedMemorySize, SMEM_GEMM);
    cudaFuncSetAttribute(gemm_out_mma,   cudaFuncAttributeMaxDynamicSharedMemorySize, SMEM_GEMM);
    cudaFuncSetAttribute(flash_attn_mma, cudaFuncAttributeMaxDynamicSharedMemorySize, SMEM_FLASH);

    split_all<<<(XN8 + 4 * WN8) / 256, 256>>>(x, Wq, Wk, Wv, Wo);

    dim3 qgrid(DMODEL / 128, MTOT / 128, 3);
    gemm_qkv_mma<<<qgrid, 256, SMEM_GEMM>>>(bq, bk, bv);

    dim3 fgrid(SEQ / 128, NHEADS, BATCH);
    flash_attn_mma<<<fgrid, 256, SMEM_FLASH>>>();

    dim3 ogrid(DMODEL / 128, MTOT / 128, 1);
    gemm_out_mma<<<ogrid, 256, SMEM_GEMM>>>(bo, out);
}

// round 7
// speedup vs baseline: 3.0210x; 1.0116x over previous
#include <cuda_runtime.h>
#include <cuda_bf16.h>
#include <math_constants.h>
#include <cstdint>

#define BATCH  2
#define SEQ    2048
#define DMODEL 1024
#define NHEADS 16
#define HDIM   64
#define MTOT   (BATCH*SEQ)   // 4096
#define WSZ    (DMODEL*DMODEL)

// ---------------- scratch (allocation-free rule: __device__ globals) --------
__device__ __nv_bfloat16 g_Xhi[(size_t)MTOT * DMODEL];
__device__ __nv_bfloat16 g_Xlo[(size_t)MTOT * DMODEL];
__device__ __nv_bfloat16 g_Whi[(size_t)4 * WSZ];
__device__ __nv_bfloat16 g_Wlo[(size_t)4 * WSZ];
__device__ __nv_bfloat16 g_Qhi[(size_t)MTOT * DMODEL];
__device__ __nv_bfloat16 g_Qlo[(size_t)MTOT * DMODEL];
__device__ __nv_bfloat16 g_Khi[(size_t)MTOT * DMODEL];
__device__ __nv_bfloat16 g_Klo[(size_t)MTOT * DMODEL];
__device__ __nv_bfloat16 g_Vhi[(size_t)MTOT * DMODEL];
__device__ __nv_bfloat16 g_Vlo[(size_t)MTOT * DMODEL];
__device__ __nv_bfloat16 g_Chi[(size_t)MTOT * DMODEL];
__device__ __nv_bfloat16 g_Clo[(size_t)MTOT * DMODEL];

// ---------------- helpers (baseline ISA only) --------------------------------
__device__ __forceinline__ uint32_t smem_u32(const void* p) {
    uint32_t a;
    asm("{ .reg .u64 t; cvta.to.shared.u64 t, %1; cvt.u32.u64 %0, t; }"
        : "=r"(a) : "l"(p));
    return a;
}
__device__ __forceinline__ void cpasync16(uint32_t dst, const void* src) {
    asm volatile("cp.async.cg.shared.global [%0], [%1], 16;" :: "r"(dst), "l"(src));
}
#define CPASYNC_COMMIT() asm volatile("cp.async.commit_group;" ::: "memory")
#define CPASYNC_WAIT(n)  asm volatile("cp.async.wait_group %0;" :: "n"(n) : "memory")

__device__ __forceinline__ void ldm_x4(uint32_t* r, uint32_t addr) {
    asm volatile("ldmatrix.sync.aligned.m8n8.x4.shared.b16 {%0,%1,%2,%3}, [%4];"
        : "=r"(r[0]), "=r"(r[1]), "=r"(r[2]), "=r"(r[3]) : "r"(addr));
}
__device__ __forceinline__ void ldm_x4t(uint32_t* r, uint32_t addr) {
    asm volatile("ldmatrix.sync.aligned.m8n8.x4.trans.shared.b16 {%0,%1,%2,%3}, [%4];"
        : "=r"(r[0]), "=r"(r[1]), "=r"(r[2]), "=r"(r[3]) : "r"(addr));
}
__device__ __forceinline__ void mma_bf16(float* c, const uint32_t* a,
                                         uint32_t b0, uint32_t b1) {
    asm volatile("mma.sync.aligned.m16n8k16.row.col.f32.bf16.bf16.f32 "
        "{%0,%1,%2,%3}, {%4,%5,%6,%7}, {%8,%9}, {%0,%1,%2,%3};"
        : "+f"(c[0]), "+f"(c[1]), "+f"(c[2]), "+f"(c[3])
        : "r"(a[0]), "r"(a[1]), "r"(a[2]), "r"(a[3]), "r"(b0), "r"(b1));
}
__device__ __forceinline__ void split2(float v0, float v1, uint32_t& hi, uint32_t& lo) {
    __nv_bfloat16 h0 = __float2bfloat16(v0), h1 = __float2bfloat16(v1);
    __nv_bfloat16 l0 = __float2bfloat16(v0 - __bfloat162float(h0));
    __nv_bfloat16 l1 = __float2bfloat16(v1 - __bfloat162float(h1));
    hi = ((uint32_t)__bfloat16_as_ushort(h1) << 16) | __bfloat16_as_ushort(h0);
    lo = ((uint32_t)__bfloat16_as_ushort(l1) << 16) | __bfloat16_as_ushort(l0);
}

// ---------------- fused fp32 -> (hi, lo) bf16 split for x + 4 weights --------
#define XN8  (MTOT * DMODEL / 8)          // 524288
#define WN8  (WSZ / 8)                    // 131072
__global__ __launch_bounds__(256)
void split_all(const float* __restrict__ x,  const float* __restrict__ Wq,
               const float* __restrict__ Wk, const float* __restrict__ Wv,
               const float* __restrict__ Wo)
{
    int id = blockIdx.x * 256 + threadIdx.x;
    const float* src;
    __nv_bfloat16 *hi, *lo;
    int off;
    if (id < XN8) {
        src = x; hi = g_Xhi; lo = g_Xlo; off = id;
    } else {
        int r = (id - XN8) >> 17;          // WN8 = 2^17
        off   = (id - XN8) & (WN8 - 1);
        src = (r == 0) ? Wq : (r == 1) ? Wk : (r == 2) ? Wv : Wo;
        hi = g_Whi + (size_t)r * WSZ;
        lo = g_Wlo + (size_t)r * WSZ;
    }
    const float4* s = (const float4*)src + (size_t)off * 2;
    float4 a = s[0], b = s[1];
    uint4 hp, lp;
    split2(a.x, a.y, hp.x, lp.x);
    split2(a.z, a.w, hp.y, lp.y);
    split2(b.x, b.y, hp.z, lp.z);
    split2(b.z, b.w, hp.w, lp.w);
    ((uint4*)hi)[off] = hp;
    ((uint4*)lo)[off] = lp;
}

// ---------------- HMMA split-bf16 GEMM ---------------------------------------
#define BK        32
#define ROWB      80
#define TILE_B    (128 * ROWB)
#define OFF_AHI   0
#define OFF_ALO   (TILE_B)
#define OFF_BHI   (2 * TILE_B)
#define OFF_BLO   (3 * TILE_B)
#define STAGE_B   (4 * TILE_B)
#define SMEM_GEMM (2 * STAGE_B)

__device__ __forceinline__ void load_chunk(
    uint32_t sdst,
    const __nv_bfloat16* __restrict__ Xhi, const __nv_bfloat16* __restrict__ Xlo,
    const __nv_bfloat16* __restrict__ Whi, const __nv_bfloat16* __restrict__ Wlo,
    int bm, int bn, int k0, int tid)
{
    #pragma unroll
    for (int it = 0; it < 2; it++) {
        int u = tid + it * 256;
        int r = u >> 2, c = u & 3;
        uint32_t so = (uint32_t)(r * ROWB + c * 16);
        size_t ga = (size_t)(bm + r) * DMODEL + k0 + c * 8;
        size_t gb = (size_t)(bn + r) * DMODEL + k0 + c * 8;
        cpasync16(sdst + OFF_AHI + so, Xhi + ga);
        cpasync16(sdst + OFF_ALO + so, Xlo + ga);
        cpasync16(sdst + OFF_BHI + so, Whi + gb);
        cpasync16(sdst + OFF_BLO + so, Wlo + gb);
    }
}

template<int MODE>   // 0: fp32 Y ; 1: split hi/lo bf16
__device__ __forceinline__ void gemm_hmma_body(
    const __nv_bfloat16* __restrict__ Xhi, const __nv_bfloat16* __restrict__ Xlo,
    const __nv_bfloat16* __restrict__ Whi, const __nv_bfloat16* __restrict__ Wlo,
    const float* __restrict__ bias, float* __restrict__ Y,
    __nv_bfloat16* __restrict__ Yhi, __nv_bfloat16* __restrict__ Ylo)
{
    extern __shared__ char smem[];
    const uint32_t sb = smem_u32(smem);
    const int tid  = threadIdx.x;
    const int lane = tid & 31;
    const int wid  = tid >> 5;
    const int wm   = wid & 1;
    const int wn   = wid >> 1;

    const int bm = blockIdx.y * 128;
    const int bn = blockIdx.x * 128;

    float acc[4][4][4];
    #pragma unroll
    for (int mi = 0; mi < 4; mi++)
        #pragma unroll
        for (int ni = 0; ni < 4; ni++)
            #pragma unroll
            for (int e = 0; e < 4; e++) acc[mi][ni][e] = 0.f;

    const uint32_t a_row  = (uint32_t)(wm * 64 + (lane & 15));
    const uint32_t a_koff = (uint32_t)(((lane >> 4) & 1) * 16);
    const uint32_t b_nrow = (uint32_t)(wn * 32 + (lane & 7) + ((lane >> 4) & 1) * 8);
    const uint32_t b_koff = (uint32_t)(((lane >> 3) & 1) * 16);

    load_chunk(sb, Xhi, Xlo, Whi, Wlo, bm, bn, 0, tid);
    CPASYNC_COMMIT();

    const int NCH = DMODEL / BK;
    for (int ch = 0; ch < NCH; ch++) {
        const uint32_t st = sb + (uint32_t)(ch & 1) * STAGE_B;
        if (ch + 1 < NCH) {
            load_chunk(sb + (uint32_t)((ch + 1) & 1) * STAGE_B,
                       Xhi, Xlo, Whi, Wlo, bm, bn, (ch + 1) * BK, tid);
            CPASYNC_COMMIT();
            CPASYNC_WAIT(1);
        } else {
            CPASYNC_WAIT(0);
        }
        __syncthreads();

        #pragma unroll
        for (int ks = 0; ks < 2; ks++) {
            const uint32_t kb = (uint32_t)(ks * 32);
            uint32_t aH[4][4], aL[4][4], bH[2][4], bL[2][4];
            #pragma unroll
            for (int mi = 0; mi < 4; mi++) {
                uint32_t ad = st + (a_row + mi * 16) * ROWB + kb + a_koff;
                ldm_x4(aH[mi], ad + OFF_AHI);
                ldm_x4(aL[mi], ad + OFF_ALO);
            }
            #pragma unroll
            for (int p = 0; p < 2; p++) {
                uint32_t bd = st + (b_nrow + p * 16) * ROWB + kb + b_koff;
                ldm_x4(bH[p], bd + OFF_BHI);
                ldm_x4(bL[p], bd + OFF_BLO);
            }
            // pass-major issue: 16 independent MMAs per pass, dep gap = 16
            #pragma unroll
            for (int mi = 0; mi < 4; mi++)
                #pragma unroll
                for (int ni = 0; ni < 4; ni++) {
                    const uint32_t* bh = &bH[ni >> 1][(ni & 1) * 2];
                    mma_bf16(acc[mi][ni], aH[mi], bh[0], bh[1]);
                }
            #pragma unroll
            for (int mi = 0; mi < 4; mi++)
                #pragma unroll
                for (int ni = 0; ni < 4; ni++) {
                    const uint32_t* bl = &bL[ni >> 1][(ni & 1) * 2];
                    mma_bf16(acc[mi][ni], aH[mi], bl[0], bl[1]);
                }
            #pragma unroll
            for (int mi = 0; mi < 4; mi++)
                #pragma unroll
                for (int ni = 0; ni < 4; ni++) {
                    const uint32_t* bh = &bH[ni >> 1][(ni & 1) * 2];
                    mma_bf16(acc[mi][ni], aL[mi], bh[0], bh[1]);
                }
        }
        __syncthreads();
    }

    const int l4 = lane >> 2;
    const int l2 = (lane & 3) * 2;
    #pragma unroll
    for (int mi = 0; mi < 4; mi++) {
        #pragma unroll
        for (int ni = 0; ni < 4; ni++) {
            int gr = bm + wm * 64 + mi * 16 + l4;
            int gc = bn + wn * 32 + ni * 8 + l2;
            float b0 = bias[gc], b1 = bias[gc + 1];
            float v0 = acc[mi][ni][0] + b0, v1 = acc[mi][ni][1] + b1;
            float v2 = acc[mi][ni][2] + b0, v3 = acc[mi][ni][3] + b1;
            if (MODE == 0) {
                *(float2*)(Y + (size_t)gr * DMODEL + gc)       = make_float2(v0, v1);
                *(float2*)(Y + (size_t)(gr + 8) * DMODEL + gc) = make_float2(v2, v3);
            } else {
                uint32_t h0, l0, h1, l1;
                split2(v0, v1, h0, l0);
                split2(v2, v3, h1, l1);
                *(uint32_t*)(Yhi + (size_t)gr * DMODEL + gc)       = h0;
                *(uint32_t*)(Ylo + (size_t)gr * DMODEL + gc)       = l0;
                *(uint32_t*)(Yhi + (size_t)(gr + 8) * DMODEL + gc) = h1;
                *(uint32_t*)(Ylo + (size_t)(gr + 8) * DMODEL + gc) = l1;
            }
        }
    }
}

__global__ __launch_bounds__(256, 2)
void gemm_qkv_mma(const float* __restrict__ bq, const float* __restrict__ bk,
                  const float* __restrict__ bv)
{
    const float* bias; __nv_bfloat16 *Yh, *Yl;
    int z = blockIdx.z;
    if (z == 0)      { bias = bq; Yh = g_Qhi; Yl = g_Qlo; }
    else if (z == 1) { bias = bk; Yh = g_Khi; Yl = g_Klo; }
    else             { bias = bv; Yh = g_Vhi; Yl = g_Vlo; }
    gemm_hmma_body<1>(g_Xhi, g_Xlo, g_Whi + (size_t)z * WSZ, g_Wlo + (size_t)z * WSZ,
                      bias, nullptr, Yh, Yl);
}

__global__ __launch_bounds__(256, 2)
void gemm_out_mma(const float* __restrict__ bo, float* __restrict__ Y)
{
    gemm_hmma_body<0>(g_Chi, g_Clo, g_Whi + (size_t)3 * WSZ, g_Wlo + (size_t)3 * WSZ,
                      bo, Y, nullptr, nullptr);
}

// ---------------- flash attention: 64-key tiles, 2 CTAs/SM -------------------
#define FROWB   144                        // 64 bf16 = 128B + 16B pad
#define FQTILE  (128 * FROWB)              // 18432 (Q: 128 rows)
#define KTILE   (64 * FROWB)               // 9216  (K/V: 64 rows)
#define FQ_HI   0
#define FQ_LO   (FQTILE)
#define FSTAGE(s) (2 * FQTILE + (s) * 4 * KTILE)
#define FK_HI   0
#define FK_LO   (KTILE)
#define FV_HI   (2 * KTILE)
#define FV_LO   (3 * KTILE)
#define SMEM_FLASH (2 * FQTILE + 8 * KTILE)   // 110592 (108 KB)

__device__ __forceinline__ void flash_load_q(uint32_t sb, const __nv_bfloat16* Qh,
                                             const __nv_bfloat16* Ql, int q0, int tid)
{
    #pragma unroll
    for (int it = 0; it < 4; it++) {
        int u = tid + it * 256;           // 0..1023
        int r = u >> 3, c = u & 7;
        uint32_t so = (uint32_t)(r * FROWB + c * 16);
        size_t ge = (size_t)(q0 + r) * DMODEL + c * 8;
        cpasync16(sb + FQ_HI + so, Qh + ge);
        cpasync16(sb + FQ_LO + so, Ql + ge);
    }
}
__device__ __forceinline__ void flash_load_kv(uint32_t stb,
    const __nv_bfloat16* Kh, const __nv_bfloat16* Kl,
    const __nv_bfloat16* Vh, const __nv_bfloat16* Vl, int k0, int tid)
{
    #pragma unroll
    for (int it = 0; it < 2; it++) {
        int u = tid + it * 256;           // 0..511
        int r = u >> 3, c = u & 7;
        uint32_t so = (uint32_t)(r * FROWB + c * 16);
        size_t ge = (size_t)(k0 + r) * DMODEL + c * 8;
        cpasync16(stb + FK_HI + so, Kh + ge);
        cpasync16(stb + FK_LO + so, Kl + ge);
        cpasync16(stb + FV_HI + so, Vh + ge);
        cpasync16(stb + FV_LO + so, Vl + ge);
    }
}

__global__ __launch_bounds__(256, 2)
void flash_attn_mma()
{
    extern __shared__ char smem[];
    const uint32_t sb = smem_u32(smem);
    const int tid  = threadIdx.x;
    const int w    = tid >> 5;
    const int lane = tid & 31;

    const int b  = blockIdx.z;
    const int h  = blockIdx.y;
    const int q0 = blockIdx.x * 128;

    const size_t base = (size_t)b * SEQ * DMODEL + (size_t)h * HDIM;
    const __nv_bfloat16* Qh = g_Qhi + base;
    const __nv_bfloat16* Ql = g_Qlo + base;
    const __nv_bfloat16* Kh = g_Khi + base;
    const __nv_bfloat16* Kl = g_Klo + base;
    const __nv_bfloat16* Vh = g_Vhi + base;
    const __nv_bfloat16* Vl = g_Vlo + base;

    const uint32_t qa = (uint32_t)((w * 16 + (lane & 15)) * FROWB
                      + ((lane >> 4) & 1) * 16);
    const uint32_t ka_row = (uint32_t)((lane & 7) + ((lane >> 4) & 1) * 8);
    const uint32_t ka_ko  = (uint32_t)(((lane >> 3) & 1) * 16);
    const uint32_t va_row = (uint32_t)(lane & 15);
    const uint32_t va_co  = (uint32_t)(((lane >> 4) & 1) * 16);

    float o[8][4];
    #pragma unroll
    for (int nb = 0; nb < 8; nb++)
        #pragma unroll
        for (int e = 0; e < 4; e++) o[nb][e] = 0.f;
    float m_a = -CUDART_INF_F, m_b = -CUDART_INF_F, l_a = 0.f, l_b = 0.f;

    uint32_t aH[4][4], aL[4][4];

    flash_load_q(sb, Qh, Ql, q0, tid);
    flash_load_kv(sb + FSTAGE(0), Kh, Kl, Vh, Vl, 0, tid);
    CPASYNC_COMMIT();

    const int NKT = SEQ / 64;             // 32
    for (int kt = 0; kt < NKT; kt++) {
        const uint32_t st = sb + FSTAGE(kt & 1);
        if (kt + 1 < NKT) {
            flash_load_kv(sb + FSTAGE((kt + 1) & 1), Kh, Kl, Vh, Vl,
                          (kt + 1) * 64, tid);
            CPASYNC_COMMIT();
            CPASYNC_WAIT(1);
        } else {
            CPASYNC_WAIT(0);
        }
        __syncthreads();

        if (kt == 0) {
            #pragma unroll
            for (int k4 = 0; k4 < 4; k4++) {
                ldm_x4(aH[k4], sb + FQ_HI + qa + k4 * 32);
                ldm_x4(aL[k4], sb + FQ_LO + qa + k4 * 32);
            }
        }

        // ---- S = Q K^T, pass-major (8 indep accs per pass) ------------------
        float s[8][4];
        #pragma unroll
        for (int j = 0; j < 8; j++)
            #pragma unroll
            for (int e = 0; e < 4; e++) s[j][e] = 0.f;

        #pragma unroll
        for (int k4 = 0; k4 < 4; k4++) {
            uint32_t kH[4][4];
            #pragma unroll
            for (int nb = 0; nb < 4; nb++)
                ldm_x4(kH[nb], st + FK_HI + (uint32_t)(nb * 16) * FROWB
                               + ka_row * FROWB + ka_ko + k4 * 32);
            #pragma unroll
            for (int nb = 0; nb < 4; nb++) {
                mma_bf16(s[2*nb],   aH[k4], kH[nb][0], kH[nb][1]);
                mma_bf16(s[2*nb+1], aH[k4], kH[nb][2], kH[nb][3]);
            }
            #pragma unroll
            for (int nb = 0; nb < 4; nb++) {
                mma_bf16(s[2*nb],   aL[k4], kH[nb][0], kH[nb][1]);
                mma_bf16(s[2*nb+1], aL[k4], kH[nb][2], kH[nb][3]);
            }
            uint32_t kL[4][4];
            #pragma unroll
            for (int nb = 0; nb < 4; nb++)
                ldm_x4(kL[nb], st + FK_LO + (uint32_t)(nb * 16) * FROWB
                               + ka_row * FROWB + ka_ko + k4 * 32);
            #pragma unroll
            for (int nb = 0; nb < 4; nb++) {
                mma_bf16(s[2*nb],   aH[k4], kL[nb][0], kL[nb][1]);
                mma_bf16(s[2*nb+1], aH[k4], kL[nb][2], kL[nb][3]);
            }
        }

        // ---- online softmax (rows a = lane/4, b = lane/4+8) -----------------
        float mloc_a = -CUDART_INF_F, mloc_b = -CUDART_INF_F;
        #pragma unroll
        for (int j = 0; j < 8; j++) {
            s[j][0] *= 0.125f; s[j][1] *= 0.125f;
            s[j][2] *= 0.125f; s[j][3] *= 0.125f;
            mloc_a = fmaxf(mloc_a, fmaxf(s[j][0], s[j][1]));
            mloc_b = fmaxf(mloc_b, fmaxf(s[j][2], s[j][3]));
        }
        mloc_a = fmaxf(mloc_a, __shfl_xor_sync(0xffffffffu, mloc_a, 1));
        mloc_a = fmaxf(mloc_a, __shfl_xor_sync(0xffffffffu, mloc_a, 2));
        mloc_b = fmaxf(mloc_b, __shfl_xor_sync(0xffffffffu, mloc_b, 1));
        mloc_b = fmaxf(mloc_b, __shfl_xor_sync(0xffffffffu, mloc_b, 2));

        float mn_a = fmaxf(m_a, mloc_a), mn_b = fmaxf(m_b, mloc_b);
        float corr_a = __expf(m_a - mn_a), corr_b = __expf(m_b - mn_b);
        m_a = mn_a; m_b = mn_b;

        float rs_a = 0.f, rs_b = 0.f;
        #pragma unroll
        for (int j = 0; j < 8; j++) {
            s[j][0] = __expf(s[j][0] - mn_a);
            s[j][1] = __expf(s[j][1] - mn_a);
            s[j][2] = __expf(s[j][2] - mn_b);
            s[j][3] = __expf(s[j][3] - mn_b);
            rs_a += s[j][0] + s[j][1];
            rs_b += s[j][2] + s[j][3];
        }
        rs_a += __shfl_xor_sync(0xffffffffu, rs_a, 1);
        rs_a += __shfl_xor_sync(0xffffffffu, rs_a, 2);
        rs_b += __shfl_xor_sync(0xffffffffu, rs_b, 1);
        rs_b += __shfl_xor_sync(0xffffffffu, rs_b, 2);
        l_a = l_a * corr_a + rs_a;
        l_b = l_b * corr_b + rs_b;

        #pragma unroll
        for (int nb = 0; nb < 8; nb++) {
            o[nb][0] *= corr_a; o[nb][1] *= corr_a;
            o[nb][2] *= corr_b; o[nb][3] *= corr_b;
        }

        // ---- O += P V, pass-major over 8 indep o-accs -----------------------
        #pragma unroll
        for (int t = 0; t < 4; t++) {
            uint32_t pH[4], pL[4];
            split2(s[2*t][0],   s[2*t][1],   pH[0], pL[0]);
            split2(s[2*t][2],   s[2*t][3],   pH[1], pL[1]);
            split2(s[2*t+1][0], s[2*t+1][1], pH[2], pL[2]);
            split2(s[2*t+1][2], s[2*t+1][3], pH[3], pL[3]);

            uint32_t vH[4][4];
            #pragma unroll
            for (int ng = 0; ng < 4; ng++)
                ldm_x4t(vH[ng], st + FV_HI + (uint32_t)(t * 16 + va_row) * FROWB
                                + (uint32_t)(ng * 32) + va_co);
            #pragma unroll
            for (int ng = 0; ng < 4; ng++) {
                mma_bf16(o[2*ng],   pH, vH[ng][0], vH[ng][1]);
                mma_bf16(o[2*ng+1], pH, vH[ng][2], vH[ng][3]);
            }
            #pragma unroll
            for (int ng = 0; ng < 4; ng++) {
                mma_bf16(o[2*ng],   pL, vH[ng][0], vH[ng][1]);
                mma_bf16(o[2*ng+1], pL, vH[ng][2], vH[ng][3]);
            }
            uint32_t vL[4][4];
            #pragma unroll
            for (int ng = 0; ng < 4; ng++)
                ldm_x4t(vL[ng], st + FV_LO + (uint32_t)(t * 16 + va_row) * FROWB
                                + (uint32_t)(ng * 32) + va_co);
            #pragma unroll
            for (int ng = 0; ng < 4; ng++) {
                mma_bf16(o[2*ng],   pH, vL[ng][0], vL[ng][1]);
                mma_bf16(o[2*ng+1], pH, vL[ng][2], vL[ng][3]);
            }
        }
        __syncthreads();
    }

    // ---- epilogue: normalize, split, write ctx hi/lo ------------------------
    const float inv_a = 1.0f / l_a, inv_b = 1.0f / l_b;
    const int row_a = q0 + w * 16 + (lane >> 2);
    const int col0  = (lane & 3) * 2;
    #pragma unroll
    for (int nb = 0; nb < 8; nb++) {
        int col = nb * 8 + col0;
        uint32_t h0, l0, h1, l1;
        split2(o[nb][0] * inv_a, o[nb][1] * inv_a, h0, l0);
        split2(o[nb][2] * inv_b, o[nb][3] * inv_b, h1, l1);
        size_t ea = base + (size_t)row_a * DMODEL + col;
        size_t eb = base + (size_t)(row_a + 8) * DMODEL + col;
        *(uint32_t*)(g_Chi + ea) = h0;
        *(uint32_t*)(g_Clo + ea) = l0;
        *(uint32_t*)(g_Chi + eb) = h1;
        *(uint32_t*)(g_Clo + eb) = l1;
    }
}

// ---------------------------------------------------------------------------
extern "C" void kernel_launch(void* const* d_in, const int* in_sizes, int n_in,
                              void* d_out, int out_size)
{
    const float* x  = (const float*)d_in[0];
    const float* Wq = (const float*)d_in[1];
    const float* bq = (const float*)d_in[2];
    const float* Wk = (const float*)d_in[3];
    const float* bk = (const float*)d_in[4];
    const float* Wv = (const float*)d_in[5];
    const float* bv = (const float*)d_in[6];
    const float* Wo = (const float*)d_in[7];
    const float* bo = (const float*)d_in[8];
    float* out = (float*)d_out;

    cudaFuncSetAttribute(gemm_qkv_mma,   cudaFuncAttributeMaxDynamicSharedMemorySize, SMEM_GEMM);
    cudaFuncSetAttribute(gemm_out_mma,   cudaFuncAttributeMaxDynamicSharedMemorySize, SMEM_GEMM);
    cudaFuncSetAttribute(flash_attn_mma, cudaFuncAttributeMaxDynamicSharedMemorySize, SMEM_FLASH);

    split_all<<<(XN8 + 4 * WN8) / 256, 256>>>(x, Wq, Wk, Wv, Wo);

    dim3 qgrid(DMODEL / 128, MTOT / 128, 3);
    gemm_qkv_mma<<<qgrid, 256, SMEM_GEMM>>>(bq, bk, bv);

    dim3 fgrid(SEQ / 128, NHEADS, BATCH);
    flash_attn_mma<<<fgrid, 256, SMEM_FLASH>>>();

    dim3 ogrid(DMODEL / 128, MTOT / 128, 1);
    gemm_out_mma<<<ogrid, 256, SMEM_GEMM>>>(bo, out);
}

// round 8
// speedup vs baseline: 3.6636x; 1.2127x over previous
#include <cuda_runtime.h>
#include <cuda_fp16.h>
#include <math_constants.h>
#include <cstdint>

#define BATCH  2
#define SEQ    2048
#define DMODEL 1024
#define NHEADS 16
#define HDIM   64
#define MTOT   (BATCH*SEQ)   // 4096
#define WSZ    (DMODEL*DMODEL)

// ---------------- scratch (allocation-free rule: __device__ globals) --------
__device__ __half g_Xhi[(size_t)MTOT * DMODEL];
__device__ __half g_Xlo[(size_t)MTOT * DMODEL];
__device__ __half g_Whi[(size_t)4 * WSZ];
__device__ __half g_Wlo[(size_t)4 * WSZ];
__device__ __half g_Qhi[(size_t)MTOT * DMODEL];
__device__ __half g_Qlo[(size_t)MTOT * DMODEL];
__device__ __half g_Khi[(size_t)MTOT * DMODEL];
__device__ __half g_Klo[(size_t)MTOT * DMODEL];
__device__ __half g_V  [(size_t)MTOT * DMODEL];   // single fp16
__device__ __half g_C  [(size_t)MTOT * DMODEL];   // single fp16 context

// ---------------- helpers (baseline ISA only) --------------------------------
__device__ __forceinline__ uint32_t smem_u32(const void* p) {
    uint32_t a;
    asm("{ .reg .u64 t; cvta.to.shared.u64 t, %1; cvt.u32.u64 %0, t; }"
        : "=r"(a) : "l"(p));
    return a;
}
__device__ __forceinline__ void cpasync16(uint32_t dst, const void* src) {
    asm volatile("cp.async.cg.shared.global [%0], [%1], 16;" :: "r"(dst), "l"(src));
}
#define CPASYNC_COMMIT() asm volatile("cp.async.commit_group;" ::: "memory")
#define CPASYNC_WAIT(n)  asm volatile("cp.async.wait_group %0;" :: "n"(n) : "memory")

__device__ __forceinline__ void ldm_x4(uint32_t* r, uint32_t addr) {
    asm volatile("ldmatrix.sync.aligned.m8n8.x4.shared.b16 {%0,%1,%2,%3}, [%4];"
        : "=r"(r[0]), "=r"(r[1]), "=r"(r[2]), "=r"(r[3]) : "r"(addr));
}
__device__ __forceinline__ void ldm_x4t(uint32_t* r, uint32_t addr) {
    asm volatile("ldmatrix.sync.aligned.m8n8.x4.trans.shared.b16 {%0,%1,%2,%3}, [%4];"
        : "=r"(r[0]), "=r"(r[1]), "=r"(r[2]), "=r"(r[3]) : "r"(addr));
}
__device__ __forceinline__ void mma_f16(float* c, const uint32_t* a,
                                        uint32_t b0, uint32_t b1) {
    asm volatile("mma.sync.aligned.m16n8k16.row.col.f32.f16.f16.f32 "
        "{%0,%1,%2,%3}, {%4,%5,%6,%7}, {%8,%9}, {%0,%1,%2,%3};"
        : "+f"(c[0]), "+f"(c[1]), "+f"(c[2]), "+f"(c[3])
        : "r"(a[0]), "r"(a[1]), "r"(a[2]), "r"(a[3]), "r"(b0), "r"(b1));
}
__device__ __forceinline__ uint32_t pack2h(float v0, float v1) {
    __half h0 = __float2half_rn(v0), h1 = __float2half_rn(v1);
    return ((uint32_t)__half_as_ushort(h1) << 16) | __half_as_ushort(h0);
}
__device__ __forceinline__ void split2h(float v0, float v1, uint32_t& hi, uint32_t& lo) {
    __half h0 = __float2half_rn(v0), h1 = __float2half_rn(v1);
    __half l0 = __float2half_rn(v0 - __half2float(h0));
    __half l1 = __float2half_rn(v1 - __half2float(h1));
    hi = ((uint32_t)__half_as_ushort(h1) << 16) | __half_as_ushort(h0);
    lo = ((uint32_t)__half_as_ushort(l1) << 16) | __half_as_ushort(l0);
}

// ---------------- fused fp32 -> (hi, lo) fp16 split for x + 4 weights --------
#define XN8  (MTOT * DMODEL / 8)          // 524288
#define WN8  (WSZ / 8)                    // 131072
__global__ __launch_bounds__(256)
void split_all(const float* __restrict__ x,  const float* __restrict__ Wq,
               const float* __restrict__ Wk, const float* __restrict__ Wv,
               const float* __restrict__ Wo)
{
    int id = blockIdx.x * 256 + threadIdx.x;
    const float* src;
    __half *hi, *lo;
    int off;
    if (id < XN8) {
        src = x; hi = g_Xhi; lo = g_Xlo; off = id;
    } else {
        int r = (id - XN8) >> 17;          // WN8 = 2^17
        off   = (id - XN8) & (WN8 - 1);
        src = (r == 0) ? Wq : (r == 1) ? Wk : (r == 2) ? Wv : Wo;
        hi = g_Whi + (size_t)r * WSZ;
        lo = g_Wlo + (size_t)r * WSZ;
    }
    const float4* s = (const float4*)src + (size_t)off * 2;
    float4 a = s[0], b = s[1];
    uint4 hp, lp;
    split2h(a.x, a.y, hp.x, lp.x);
    split2h(a.z, a.w, hp.y, lp.y);
    split2h(b.x, b.y, hp.z, lp.z);
    split2h(b.z, b.w, hp.w, lp.w);
    ((uint4*)hi)[off] = hp;
    ((uint4*)lo)[off] = lp;
}

// ---------------- HMMA split-fp16 GEMM ---------------------------------------
// ASPLIT=1: A has hi/lo (3 passes). ASPLIT=0: A single (2 passes).
// outmode: 0 = fp32 Y ; 1 = split hi/lo fp16 ; 2 = single fp16
#define BK        32
#define ROWB      80
#define TILE_B    (128 * ROWB)

template<int ASPLIT>
__device__ __forceinline__ void load_chunk_t(
    uint32_t sdst,
    const __half* __restrict__ Ahi, const __half* __restrict__ Alo,
    const __half* __restrict__ Whi, const __half* __restrict__ Wlo,
    int bm, int bn, int k0, int tid)
{
    constexpr uint32_t OFF_BH = (uint32_t)((1 + ASPLIT) * TILE_B);
    constexpr uint32_t OFF_BL = (uint32_t)((2 + ASPLIT) * TILE_B);
    #pragma unroll
    for (int it = 0; it < 2; it++) {
        int u = tid + it * 256;
        int r = u >> 2, c = u & 3;
        uint32_t so = (uint32_t)(r * ROWB + c * 16);
        size_t ga = (size_t)(bm + r) * DMODEL + k0 + c * 8;
        size_t gb = (size_t)(bn + r) * DMODEL + k0 + c * 8;
        cpasync16(sdst + so, Ahi + ga);
        if (ASPLIT) cpasync16(sdst + TILE_B + so, Alo + ga);
        cpasync16(sdst + OFF_BH + so, Whi + gb);
        cpasync16(sdst + OFF_BL + so, Wlo + gb);
    }
}

template<int ASPLIT>
__device__ __forceinline__ void gemm_hmma_body(
    const __half* __restrict__ Ahi, const __half* __restrict__ Alo,
    const __half* __restrict__ Whi, const __half* __restrict__ Wlo,
    const float* __restrict__ bias, int outmode, float* __restrict__ Y,
    __half* __restrict__ Yhi, __half* __restrict__ Ylo)
{
    extern __shared__ char smem[];
    constexpr uint32_t OFF_BH  = (uint32_t)((1 + ASPLIT) * TILE_B);
    constexpr uint32_t OFF_BL  = (uint32_t)((2 + ASPLIT) * TILE_B);
    constexpr uint32_t STAGE   = (uint32_t)((3 + ASPLIT) * TILE_B);
    const uint32_t sb = smem_u32(smem);
    const int tid  = threadIdx.x;
    const int lane = tid & 31;
    const int wid  = tid >> 5;
    const int wm   = wid & 1;
    const int wn   = wid >> 1;

    const int bm = blockIdx.y * 128;
    const int bn = blockIdx.x * 128;

    float acc[4][4][4];
    #pragma unroll
    for (int mi = 0; mi < 4; mi++)
        #pragma unroll
        for (int ni = 0; ni < 4; ni++)
            #pragma unroll
            for (int e = 0; e < 4; e++) acc[mi][ni][e] = 0.f;

    const uint32_t a_row  = (uint32_t)(wm * 64 + (lane & 15));
    const uint32_t a_koff = (uint32_t)(((lane >> 4) & 1) * 16);
    const uint32_t b_nrow = (uint32_t)(wn * 32 + (lane & 7) + ((lane >> 4) & 1) * 8);
    const uint32_t b_koff = (uint32_t)(((lane >> 3) & 1) * 16);

    load_chunk_t<ASPLIT>(sb, Ahi, Alo, Whi, Wlo, bm, bn, 0, tid);
    CPASYNC_COMMIT();

    const int NCH = DMODEL / BK;
    for (int ch = 0; ch < NCH; ch++) {
        const uint32_t st = sb + (uint32_t)(ch & 1) * STAGE;
        if (ch + 1 < NCH) {
            load_chunk_t<ASPLIT>(sb + (uint32_t)((ch + 1) & 1) * STAGE,
                                 Ahi, Alo, Whi, Wlo, bm, bn, (ch + 1) * BK, tid);
            CPASYNC_COMMIT();
            CPASYNC_WAIT(1);
        } else {
            CPASYNC_WAIT(0);
        }
        __syncthreads();

        #pragma unroll
        for (int ks = 0; ks < 2; ks++) {
            const uint32_t kb = (uint32_t)(ks * 32);
            uint32_t aH[4][4], aL[4][4], bH[2][4], bL[2][4];
            #pragma unroll
            for (int mi = 0; mi < 4; mi++) {
                uint32_t ad = st + (a_row + mi * 16) * ROWB + kb + a_koff;
                ldm_x4(aH[mi], ad);
                if (ASPLIT) ldm_x4(aL[mi], ad + TILE_B);
            }
            #pragma unroll
            for (int p = 0; p < 2; p++) {
                uint32_t bd = st + (b_nrow + p * 16) * ROWB + kb + b_koff;
                ldm_x4(bH[p], bd + OFF_BH);
                ldm_x4(bL[p], bd + OFF_BL);
            }
            #pragma unroll
            for (int mi = 0; mi < 4; mi++)
                #pragma unroll
                for (int ni = 0; ni < 4; ni++) {
                    const uint32_t* bh = &bH[ni >> 1][(ni & 1) * 2];
                    mma_f16(acc[mi][ni], aH[mi], bh[0], bh[1]);
                }
            #pragma unroll
            for (int mi = 0; mi < 4; mi++)
                #pragma unroll
                for (int ni = 0; ni < 4; ni++) {
                    const uint32_t* bl = &bL[ni >> 1][(ni & 1) * 2];
                    mma_f16(acc[mi][ni], aH[mi], bl[0], bl[1]);
                }
            if (ASPLIT) {
                #pragma unroll
                for (int mi = 0; mi < 4; mi++)
                    #pragma unroll
                    for (int ni = 0; ni < 4; ni++) {
                        const uint32_t* bh = &bH[ni >> 1][(ni & 1) * 2];
                        mma_f16(acc[mi][ni], aL[mi], bh[0], bh[1]);
                    }
            }
        }
        __syncthreads();
    }

    const int l4 = lane >> 2;
    const int l2 = (lane & 3) * 2;
    #pragma unroll
    for (int mi = 0; mi < 4; mi++) {
        #pragma unroll
        for (int ni = 0; ni < 4; ni++) {
            int gr = bm + wm * 64 + mi * 16 + l4;
            int gc = bn + wn * 32 + ni * 8 + l2;
            float b0 = bias[gc], b1 = bias[gc + 1];
            float v0 = acc[mi][ni][0] + b0, v1 = acc[mi][ni][1] + b1;
            float v2 = acc[mi][ni][2] + b0, v3 = acc[mi][ni][3] + b1;
            if (outmode == 0) {
                *(float2*)(Y + (size_t)gr * DMODEL + gc)       = make_float2(v0, v1);
                *(float2*)(Y + (size_t)(gr + 8) * DMODEL + gc) = make_float2(v2, v3);
            } else if (outmode == 1) {
                uint32_t h0, l0, h1, l1;
                split2h(v0, v1, h0, l0);
                split2h(v2, v3, h1, l1);
                *(uint32_t*)(Yhi + (size_t)gr * DMODEL + gc)       = h0;
                *(uint32_t*)(Ylo + (size_t)gr * DMODEL + gc)       = l0;
                *(uint32_t*)(Yhi + (size_t)(gr + 8) * DMODEL + gc) = h1;
                *(uint32_t*)(Ylo + (size_t)(gr + 8) * DMODEL + gc) = l1;
            } else {
                *(uint32_t*)(Yhi + (size_t)gr * DMODEL + gc)       = pack2h(v0, v1);
                *(uint32_t*)(Yhi + (size_t)(gr + 8) * DMODEL + gc) = pack2h(v2, v3);
            }
        }
    }
}

#define SMEM_QKV (2 * 4 * TILE_B)          // 81920
#define SMEM_OUT (2 * 3 * TILE_B)          // 61440

__global__ __launch_bounds__(256, 2)
void gemm_qkv_mma(const float* __restrict__ bq, const float* __restrict__ bk,
                  const float* __restrict__ bv)
{
    int z = blockIdx.z;
    const float* bias = (z == 0) ? bq : (z == 1) ? bk : bv;
    __half* Yh = (z == 0) ? g_Qhi : (z == 1) ? g_Khi : g_V;
    __half* Yl = (z == 0) ? g_Qlo : (z == 1) ? g_Klo : nullptr;
    int outmode = (z == 2) ? 2 : 1;        // V is single fp16
    gemm_hmma_body<1>(g_Xhi, g_Xlo, g_Whi + (size_t)z * WSZ, g_Wlo + (size_t)z * WSZ,
                      bias, outmode, nullptr, Yh, Yl);
}

__global__ __launch_bounds__(256, 2)
void gemm_out_mma(const float* __restrict__ bo, float* __restrict__ Y)
{
    gemm_hmma_body<0>(g_C, nullptr, g_Whi + (size_t)3 * WSZ, g_Wlo + (size_t)3 * WSZ,
                      bo, 0, Y, nullptr, nullptr);
}

// ---------------- flash attention: fp16, V single, P single ------------------
#define FROWB   144                        // 64 fp16 = 128B + 16B pad
#define FQTILE  (128 * FROWB)              // 18432
#define KTILE   (64 * FROWB)               // 9216
#define FQ_HI   0
#define FQ_LO   (FQTILE)
#define FSTAGE(s) (2 * FQTILE + (s) * 3 * KTILE)
#define FK_HI   0
#define FK_LO   (KTILE)
#define FV      (2 * KTILE)
#define SMEM_FLASH (2 * FQTILE + 6 * KTILE)   // 92160 (90 KB)

__device__ __forceinline__ void flash_load_q(uint32_t sb, const __half* Qh,
                                             const __half* Ql, int q0, int tid)
{
    #pragma unroll
    for (int it = 0; it < 4; it++) {
        int u = tid + it * 256;           // 0..1023
        int r = u >> 3, c = u & 7;
        uint32_t so = (uint32_t)(r * FROWB + c * 16);
        size_t ge = (size_t)(q0 + r) * DMODEL + c * 8;
        cpasync16(sb + FQ_HI + so, Qh + ge);
        cpasync16(sb + FQ_LO + so, Ql + ge);
    }
}
__device__ __forceinline__ void flash_load_kv(uint32_t stb,
    const __half* Kh, const __half* Kl, const __half* Vs, int k0, int tid)
{
    #pragma unroll
    for (int it = 0; it < 2; it++) {
        int u = tid + it * 256;           // 0..511
        int r = u >> 3, c = u & 7;
        uint32_t so = (uint32_t)(r * FROWB + c * 16);
        size_t ge = (size_t)(k0 + r) * DMODEL + c * 8;
        cpasync16(stb + FK_HI + so, Kh + ge);
        cpasync16(stb + FK_LO + so, Kl + ge);
        cpasync16(stb + FV    + so, Vs + ge);
    }
}

__global__ __launch_bounds__(256, 2)
void flash_attn_mma()
{
    extern __shared__ char smem[];
    const uint32_t sb = smem_u32(smem);
    const int tid  = threadIdx.x;
    const int w    = tid >> 5;
    const int lane = tid & 31;

    const int b  = blockIdx.z;
    const int h  = blockIdx.y;
    const int q0 = blockIdx.x * 128;

    const size_t base = (size_t)b * SEQ * DMODEL + (size_t)h * HDIM;
    const __half* Qh = g_Qhi + base;
    const __half* Ql = g_Qlo + base;
    const __half* Kh = g_Khi + base;
    const __half* Kl = g_Klo + base;
    const __half* Vs = g_V   + base;

    const uint32_t qa = (uint32_t)((w * 16 + (lane & 15)) * FROWB
                      + ((lane >> 4) & 1) * 16);
    const uint32_t ka_row = (uint32_t)((lane & 7) + ((lane >> 4) & 1) * 8);
    const uint32_t ka_ko  = (uint32_t)(((lane >> 3) & 1) * 16);
    const uint32_t va_row = (uint32_t)(lane & 15);
    const uint32_t va_co  = (uint32_t)(((lane >> 4) & 1) * 16);

    float o[8][4];
    #pragma unroll
    for (int nb = 0; nb < 8; nb++)
        #pragma unroll
        for (int e = 0; e < 4; e++) o[nb][e] = 0.f;
    float m_a = -CUDART_INF_F, m_b = -CUDART_INF_F, l_a = 0.f, l_b = 0.f;

    uint32_t aH[4][4], aL[4][4];

    flash_load_q(sb, Qh, Ql, q0, tid);
    flash_load_kv(sb + FSTAGE(0), Kh, Kl, Vs, 0, tid);
    CPASYNC_COMMIT();

    const int NKT = SEQ / 64;             // 32
    for (int kt = 0; kt < NKT; kt++) {
        const uint32_t st = sb + FSTAGE(kt & 1);
        if (kt + 1 < NKT) {
            flash_load_kv(sb + FSTAGE((kt + 1) & 1), Kh, Kl, Vs, (kt + 1) * 64, tid);
            CPASYNC_COMMIT();
            CPASYNC_WAIT(1);
        } else {
            CPASYNC_WAIT(0);
        }
        __syncthreads();

        if (kt == 0) {
            #pragma unroll
            for (int k4 = 0; k4 < 4; k4++) {
                ldm_x4(aH[k4], sb + FQ_HI + qa + k4 * 32);
                ldm_x4(aL[k4], sb + FQ_LO + qa + k4 * 32);
            }
        }

        // ---- S = Q K^T (3-pass split fp16) ----------------------------------
        float s[8][4];
        #pragma unroll
        for (int j = 0; j < 8; j++)
            #pragma unroll
            for (int e = 0; e < 4; e++) s[j][e] = 0.f;

        #pragma unroll
        for (int k4 = 0; k4 < 4; k4++) {
            uint32_t kH[4][4];
            #pragma unroll
            for (int nb = 0; nb < 4; nb++)
                ldm_x4(kH[nb], st + FK_HI + (uint32_t)(nb * 16) * FROWB
                               + ka_row * FROWB + ka_ko + k4 * 32);
            #pragma unroll
            for (int nb = 0; nb < 4; nb++) {
                mma_f16(s[2*nb],   aH[k4], kH[nb][0], kH[nb][1]);
                mma_f16(s[2*nb+1], aH[k4], kH[nb][2], kH[nb][3]);
            }
            #pragma unroll
            for (int nb = 0; nb < 4; nb++) {
                mma_f16(s[2*nb],   aL[k4], kH[nb][0], kH[nb][1]);
                mma_f16(s[2*nb+1], aL[k4], kH[nb][2], kH[nb][3]);
            }
            uint32_t kL[4][4];
            #pragma unroll
            for (int nb = 0; nb < 4; nb++)
                ldm_x4(kL[nb], st + FK_LO + (uint32_t)(nb * 16) * FROWB
                               + ka_row * FROWB + ka_ko + k4 * 32);
            #pragma unroll
            for (int nb = 0; nb < 4; nb++) {
                mma_f16(s[2*nb],   aH[k4], kL[nb][0], kL[nb][1]);
                mma_f16(s[2*nb+1], aH[k4], kL[nb][2], kL[nb][3]);
            }
        }

        // ---- online softmax (rows a = lane/4, b = lane/4+8) -----------------
        float mloc_a = -CUDART_INF_F, mloc_b = -CUDART_INF_F;
        #pragma unroll
        for (int j = 0; j < 8; j++) {
            s[j][0] *= 0.125f; s[j][1] *= 0.125f;
            s[j][2] *= 0.125f; s[j][3] *= 0.125f;
            mloc_a = fmaxf(mloc_a, fmaxf(s[j][0], s[j][1]));
            mloc_b = fmaxf(mloc_b, fmaxf(s[j][2], s[j][3]));
        }
        mloc_a = fmaxf(mloc_a, __shfl_xor_sync(0xffffffffu, mloc_a, 1));
        mloc_a = fmaxf(mloc_a, __shfl_xor_sync(0xffffffffu, mloc_a, 2));
        mloc_b = fmaxf(mloc_b, __shfl_xor_sync(0xffffffffu, mloc_b, 1));
        mloc_b = fmaxf(mloc_b, __shfl_xor_sync(0xffffffffu, mloc_b, 2));

        float mn_a = fmaxf(m_a, mloc_a), mn_b = fmaxf(m_b, mloc_b);
        float corr_a = __expf(m_a - mn_a), corr_b = __expf(m_b - mn_b);
        m_a = mn_a; m_b = mn_b;

        float rs_a = 0.f, rs_b = 0.f;
        #pragma unroll
        for (int j = 0; j < 8; j++) {
            s[j][0] = __expf(s[j][0] - mn_a);
            s[j][1] = __expf(s[j][1] - mn_a);
            s[j][2] = __expf(s[j][2] - mn_b);
            s[j][3] = __expf(s[j][3] - mn_b);
            rs_a += s[j][0] + s[j][1];
            rs_b += s[j][2] + s[j][3];
        }
        rs_a += __shfl_xor_sync(0xffffffffu, rs_a, 1);
        rs_a += __shfl_xor_sync(0xffffffffu, rs_a, 2);
        rs_b += __shfl_xor_sync(0xffffffffu, rs_b, 1);
        rs_b += __shfl_xor_sync(0xffffffffu, rs_b, 2);
        l_a = l_a * corr_a + rs_a;
        l_b = l_b * corr_b + rs_b;

        #pragma unroll
        for (int nb = 0; nb < 8; nb++) {
            o[nb][0] *= corr_a; o[nb][1] *= corr_a;
            o[nb][2] *= corr_b; o[nb][3] *= corr_b;
        }

        // ---- O += P V: P single fp16, V single fp16 -> 1 pass ---------------
        #pragma unroll
        for (int t = 0; t < 4; t++) {
            uint32_t pP[4];
            pP[0] = pack2h(s[2*t][0],   s[2*t][1]);
            pP[1] = pack2h(s[2*t][2],   s[2*t][3]);
            pP[2] = pack2h(s[2*t+1][0], s[2*t+1][1]);
            pP[3] = pack2h(s[2*t+1][2], s[2*t+1][3]);

            uint32_t vS[4][4];
            #pragma unroll
            for (int ng = 0; ng < 4; ng++)
                ldm_x4t(vS[ng], st + FV + (uint32_t)(t * 16 + va_row) * FROWB
                                + (uint32_t)(ng * 32) + va_co);
            #pragma unroll
            for (int ng = 0; ng < 4; ng++) {
                mma_f16(o[2*ng],   pP, vS[ng][0], vS[ng][1]);
                mma_f16(o[2*ng+1], pP, vS[ng][2], vS[ng][3]);
            }
        }
        __syncthreads();
    }

    // ---- epilogue: normalize, pack single fp16 ctx --------------------------
    const float inv_a = 1.0f / l_a, inv_b = 1.0f / l_b;
    const int row_a = q0 + w * 16 + (lane >> 2);
    const int col0  = (lane & 3) * 2;
    #pragma unroll
    for (int nb = 0; nb < 8; nb++) {
        int col = nb * 8 + col0;
        size_t ea = base + (size_t)row_a * DMODEL + col;
        size_t eb = base + (size_t)(row_a + 8) * DMODEL + col;
        *(uint32_t*)(g_C + ea) = pack2h(o[nb][0] * inv_a, o[nb][1] * inv_a);
        *(uint32_t*)(g_C + eb) = pack2h(o[nb][2] * inv_b, o[nb][3] * inv_b);
    }
}

// ---------------------------------------------------------------------------
extern "C" void kernel_launch(void* const* d_in, const int* in_sizes, int n_in,
                              void* d_out, int out_size)
{
    const float* x  = (const float*)d_in[0];
    const float* Wq = (const float*)d_in[1];
    const float* bq = (const float*)d_in[2];
    const float* Wk = (const float*)d_in[3];
    const float* bk = (const float*)d_in[4];
    const float* Wv = (const float*)d_in[5];
    const float* bv = (const float*)d_in[6];
    const float* Wo = (const float*)d_in[7];
    const float* bo = (const float*)d_in[8];
    float* out = (float*)d_out;

    cudaFuncSetAttribute(gemm_qkv_mma,   cudaFuncAttributeMaxDynamicSharedMemorySize, SMEM_QKV);
    cudaFuncSetAttribute(gemm_out_mma,   cudaFuncAttributeMaxDynamicSharedMemorySize, SMEM_OUT);
    cudaFuncSetAttribute(flash_attn_mma, cudaFuncAttributeMaxDynamicSharedMemorySize, SMEM_FLASH);

    split_all<<<(XN8 + 4 * WN8) / 256, 256>>>(x, Wq, Wk, Wv, Wo);

    dim3 qgrid(DMODEL / 128, MTOT / 128, 3);
    gemm_qkv_mma<<<qgrid, 256, SMEM_QKV>>>(bq, bk, bv);

    dim3 fgrid(SEQ / 128, NHEADS, BATCH);
    flash_attn_mma<<<fgrid, 256, SMEM_FLASH>>>();

    dim3 ogrid(DMODEL / 128, MTOT / 128, 1);
    gemm_out_mma<<<ogrid, 256, SMEM_OUT>>>(bo, out);
}

// round 9
// speedup vs baseline: 4.3457x; 1.1862x over previous
#include <cuda_runtime.h>
#include <cuda_fp16.h>
#include <math_constants.h>
#include <cstdint>

#define BATCH  2
#define SEQ    2048
#define DMODEL 1024
#define NHEADS 16
#define HDIM   64
#define MTOT   (BATCH*SEQ)   // 4096
#define WSZ    (DMODEL*DMODEL)

// ---------------- scratch (allocation-free rule: __device__ globals) --------
__device__ __half g_Xhi[(size_t)MTOT * DMODEL];
__device__ __half g_Xlo[(size_t)MTOT * DMODEL];
__device__ __half g_Whi[(size_t)4 * WSZ];
__device__ __half g_Wlo[(size_t)4 * WSZ];
__device__ __half g_Q  [(size_t)MTOT * DMODEL];   // single fp16
__device__ __half g_Khi[(size_t)MTOT * DMODEL];
__device__ __half g_Klo[(size_t)MTOT * DMODEL];
__device__ __half g_V  [(size_t)MTOT * DMODEL];   // single fp16
__device__ __half g_C  [(size_t)MTOT * DMODEL];   // single fp16 context

// ---------------- helpers (baseline ISA only) --------------------------------
__device__ __forceinline__ uint32_t smem_u32(const void* p) {
    uint32_t a;
    asm("{ .reg .u64 t; cvta.to.shared.u64 t, %1; cvt.u32.u64 %0, t; }"
        : "=r"(a) : "l"(p));
    return a;
}
__device__ __forceinline__ void cpasync16(uint32_t dst, const void* src) {
    asm volatile("cp.async.cg.shared.global [%0], [%1], 16;" :: "r"(dst), "l"(src));
}
#define CPASYNC_COMMIT() asm volatile("cp.async.commit_group;" ::: "memory")
#define CPASYNC_WAIT(n)  asm volatile("cp.async.wait_group %0;" :: "n"(n) : "memory")

__device__ __forceinline__ void ldm_x4(uint32_t* r, uint32_t addr) {
    asm volatile("ldmatrix.sync.aligned.m8n8.x4.shared.b16 {%0,%1,%2,%3}, [%4];"
        : "=r"(r[0]), "=r"(r[1]), "=r"(r[2]), "=r"(r[3]) : "r"(addr));
}
__device__ __forceinline__ void ldm_x4t(uint32_t* r, uint32_t addr) {
    asm volatile("ldmatrix.sync.aligned.m8n8.x4.trans.shared.b16 {%0,%1,%2,%3}, [%4];"
        : "=r"(r[0]), "=r"(r[1]), "=r"(r[2]), "=r"(r[3]) : "r"(addr));
}
__device__ __forceinline__ void mma_f16(float* c, const uint32_t* a,
                                        uint32_t b0, uint32_t b1) {
    asm volatile("mma.sync.aligned.m16n8k16.row.col.f32.f16.f16.f32 "
        "{%0,%1,%2,%3}, {%4,%5,%6,%7}, {%8,%9}, {%0,%1,%2,%3};"
        : "+f"(c[0]), "+f"(c[1]), "+f"(c[2]), "+f"(c[3])
        : "r"(a[0]), "r"(a[1]), "r"(a[2]), "r"(a[3]), "r"(b0), "r"(b1));
}
__device__ __forceinline__ uint32_t pack2h(float v0, float v1) {
    __half h0 = __float2half_rn(v0), h1 = __float2half_rn(v1);
    return ((uint32_t)__half_as_ushort(h1) << 16) | __half_as_ushort(h0);
}
__device__ __forceinline__ void split2h(float v0, float v1, uint32_t& hi, uint32_t& lo) {
    __half h0 = __float2half_rn(v0), h1 = __float2half_rn(v1);
    __half l0 = __float2half_rn(v0 - __half2float(h0));
    __half l1 = __float2half_rn(v1 - __half2float(h1));
    hi = ((uint32_t)__half_as_ushort(h1) << 16) | __half_as_ushort(h0);
    lo = ((uint32_t)__half_as_ushort(l1) << 16) | __half_as_ushort(l0);
}

// ---------------- fused fp32 -> (hi, lo) fp16 split for x + 4 weights --------
#define XN8  (MTOT * DMODEL / 8)          // 524288
#define WN8  (WSZ / 8)                    // 131072
__global__ __launch_bounds__(256)
void split_all(const float* __restrict__ x,  const float* __restrict__ Wq,
               const float* __restrict__ Wk, const float* __restrict__ Wv,
               const float* __restrict__ Wo)
{
    int id = blockIdx.x * 256 + threadIdx.x;
    const float* src;
    __half *hi, *lo;
    int off;
    if (id < XN8) {
        src = x; hi = g_Xhi; lo = g_Xlo; off = id;
    } else {
        int r = (id - XN8) >> 17;          // WN8 = 2^17
        off   = (id - XN8) & (WN8 - 1);
        src = (r == 0) ? Wq : (r == 1) ? Wk : (r == 2) ? Wv : Wo;
        hi = g_Whi + (size_t)r * WSZ;
        lo = g_Wlo + (size_t)r * WSZ;
    }
    const float4* s = (const float4*)src + (size_t)off * 2;
    float4 a = s[0], b = s[1];
    uint4 hp, lp;
    split2h(a.x, a.y, hp.x, lp.x);
    split2h(a.z, a.w, hp.y, lp.y);
    split2h(b.x, b.y, hp.z, lp.z);
    split2h(b.z, b.w, hp.w, lp.w);
    ((uint4*)hi)[off] = hp;
    ((uint4*)lo)[off] = lp;
}

// ---------------- HMMA split-fp16 GEMM ---------------------------------------
// ASPLIT: A-lo tile present in smem layout. passes: 2 or 3 (3rd = A-lo * B-hi).
// outmode: 0 = fp32 Y ; 1 = split hi/lo fp16 ; 2 = single fp16
#define BK        32
#define ROWB      80
#define TILE_B    (128 * ROWB)

template<int ASPLIT>
__device__ __forceinline__ void load_chunk_t(
    uint32_t sdst,
    const __half* __restrict__ Ahi, const __half* __restrict__ Alo,
    const __half* __restrict__ Whi, const __half* __restrict__ Wlo,
    int bm, int bn, int k0, int tid, bool need_alo)
{
    constexpr uint32_t OFF_BH = (uint32_t)((1 + ASPLIT) * TILE_B);
    constexpr uint32_t OFF_BL = (uint32_t)((2 + ASPLIT) * TILE_B);
    #pragma unroll
    for (int it = 0; it < 2; it++) {
        int u = tid + it * 256;
        int r = u >> 2, c = u & 3;
        uint32_t so = (uint32_t)(r * ROWB + c * 16);
        size_t ga = (size_t)(bm + r) * DMODEL + k0 + c * 8;
        size_t gb = (size_t)(bn + r) * DMODEL + k0 + c * 8;
        cpasync16(sdst + so, Ahi + ga);
        if (ASPLIT && need_alo) cpasync16(sdst + TILE_B + so, Alo + ga);
        cpasync16(sdst + OFF_BH + so, Whi + gb);
        cpasync16(sdst + OFF_BL + so, Wlo + gb);
    }
}

template<int ASPLIT>
__device__ __forceinline__ void gemm_hmma_body(
    const __half* __restrict__ Ahi, const __half* __restrict__ Alo,
    const __half* __restrict__ Whi, const __half* __restrict__ Wlo,
    const float* __restrict__ bias, int passes, int outmode,
    float* __restrict__ Y, __half* __restrict__ Yhi, __half* __restrict__ Ylo)
{
    extern __shared__ char smem[];
    constexpr uint32_t OFF_BH  = (uint32_t)((1 + ASPLIT) * TILE_B);
    constexpr uint32_t OFF_BL  = (uint32_t)((2 + ASPLIT) * TILE_B);
    constexpr uint32_t STAGE   = (uint32_t)((3 + ASPLIT) * TILE_B);
    const uint32_t sb = smem_u32(smem);
    const int tid  = threadIdx.x;
    const int lane = tid & 31;
    const int wid  = tid >> 5;
    const int wm   = wid & 1;
    const int wn   = wid >> 1;
    const bool p3  = (passes == 3);

    const int bm = blockIdx.y * 128;
    const int bn = blockIdx.x * 128;

    float acc[4][4][4];
    #pragma unroll
    for (int mi = 0; mi < 4; mi++)
        #pragma unroll
        for (int ni = 0; ni < 4; ni++)
            #pragma unroll
            for (int e = 0; e < 4; e++) acc[mi][ni][e] = 0.f;

    const uint32_t a_row  = (uint32_t)(wm * 64 + (lane & 15));
    const uint32_t a_koff = (uint32_t)(((lane >> 4) & 1) * 16);
    const uint32_t b_nrow = (uint32_t)(wn * 32 + (lane & 7) + ((lane >> 4) & 1) * 8);
    const uint32_t b_koff = (uint32_t)(((lane >> 3) & 1) * 16);

    load_chunk_t<ASPLIT>(sb, Ahi, Alo, Whi, Wlo, bm, bn, 0, tid, p3);
    CPASYNC_COMMIT();

    const int NCH = DMODEL / BK;
    for (int ch = 0; ch < NCH; ch++) {
        const uint32_t st = sb + (uint32_t)(ch & 1) * STAGE;
        if (ch + 1 < NCH) {
            load_chunk_t<ASPLIT>(sb + (uint32_t)((ch + 1) & 1) * STAGE,
                                 Ahi, Alo, Whi, Wlo, bm, bn, (ch + 1) * BK, tid, p3);
            CPASYNC_COMMIT();
            CPASYNC_WAIT(1);
        } else {
            CPASYNC_WAIT(0);
        }
        __syncthreads();

        #pragma unroll
        for (int ks = 0; ks < 2; ks++) {
            const uint32_t kb = (uint32_t)(ks * 32);
            uint32_t aH[4][4], aL[4][4], bH[2][4], bL[2][4];
            #pragma unroll
            for (int mi = 0; mi < 4; mi++) {
                uint32_t ad = st + (a_row + mi * 16) * ROWB + kb + a_koff;
                ldm_x4(aH[mi], ad);
                if (ASPLIT && p3) ldm_x4(aL[mi], ad + TILE_B);
            }
            #pragma unroll
            for (int p = 0; p < 2; p++) {
                uint32_t bd = st + (b_nrow + p * 16) * ROWB + kb + b_koff;
                ldm_x4(bH[p], bd + OFF_BH);
                ldm_x4(bL[p], bd + OFF_BL);
            }
            #pragma unroll
            for (int mi = 0; mi < 4; mi++)
                #pragma unroll
                for (int ni = 0; ni < 4; ni++) {
                    const uint32_t* bh = &bH[ni >> 1][(ni & 1) * 2];
                    mma_f16(acc[mi][ni], aH[mi], bh[0], bh[1]);
                }
            #pragma unroll
            for (int mi = 0; mi < 4; mi++)
                #pragma unroll
                for (int ni = 0; ni < 4; ni++) {
                    const uint32_t* bl = &bL[ni >> 1][(ni & 1) * 2];
                    mma_f16(acc[mi][ni], aH[mi], bl[0], bl[1]);
                }
            if (ASPLIT && p3) {
                #pragma unroll
                for (int mi = 0; mi < 4; mi++)
                    #pragma unroll
                    for (int ni = 0; ni < 4; ni++) {
                        const uint32_t* bh = &bH[ni >> 1][(ni & 1) * 2];
                        mma_f16(acc[mi][ni], aL[mi], bh[0], bh[1]);
                    }
            }
        }
        __syncthreads();
    }

    const int l4 = lane >> 2;
    const int l2 = (lane & 3) * 2;
    #pragma unroll
    for (int mi = 0; mi < 4; mi++) {
        #pragma unroll
        for (int ni = 0; ni < 4; ni++) {
            int gr = bm + wm * 64 + mi * 16 + l4;
            int gc = bn + wn * 32 + ni * 8 + l2;
            float b0 = bias[gc], b1 = bias[gc + 1];
            float v0 = acc[mi][ni][0] + b0, v1 = acc[mi][ni][1] + b1;
            float v2 = acc[mi][ni][2] + b0, v3 = acc[mi][ni][3] + b1;
            if (outmode == 0) {
                *(float2*)(Y + (size_t)gr * DMODEL + gc)       = make_float2(v0, v1);
                *(float2*)(Y + (size_t)(gr + 8) * DMODEL + gc) = make_float2(v2, v3);
            } else if (outmode == 1) {
                uint32_t h0, l0, h1, l1;
                split2h(v0, v1, h0, l0);
                split2h(v2, v3, h1, l1);
                *(uint32_t*)(Yhi + (size_t)gr * DMODEL + gc)       = h0;
                *(uint32_t*)(Ylo + (size_t)gr * DMODEL + gc)       = l0;
                *(uint32_t*)(Yhi + (size_t)(gr + 8) * DMODEL + gc) = h1;
                *(uint32_t*)(Ylo + (size_t)(gr + 8) * DMODEL + gc) = l1;
            } else {
                *(uint32_t*)(Yhi + (size_t)gr * DMODEL + gc)       = pack2h(v0, v1);
                *(uint32_t*)(Yhi + (size_t)(gr + 8) * DMODEL + gc) = pack2h(v2, v3);
            }
        }
    }
}

#define SMEM_QKV (2 * 4 * TILE_B)          // 81920
#define SMEM_OUT (2 * 3 * TILE_B)          // 61440

__global__ __launch_bounds__(256, 2)
void gemm_qkv_mma(const float* __restrict__ bq, const float* __restrict__ bk,
                  const float* __restrict__ bv)
{
    int z = blockIdx.z;
    const float* bias = (z == 0) ? bq : (z == 1) ? bk : bv;
    __half* Yh = (z == 0) ? g_Q : (z == 1) ? g_Khi : g_V;
    __half* Yl = (z == 1) ? g_Klo : nullptr;
    int passes  = (z == 1) ? 3 : 2;        // K keeps full precision
    int outmode = (z == 1) ? 1 : 2;        // Q, V single fp16
    gemm_hmma_body<1>(g_Xhi, g_Xlo, g_Whi + (size_t)z * WSZ, g_Wlo + (size_t)z * WSZ,
                      bias, passes, outmode, nullptr, Yh, Yl);
}

__global__ __launch_bounds__(256, 2)
void gemm_out_mma(const float* __restrict__ bo, float* __restrict__ Y)
{
    gemm_hmma_body<0>(g_C, nullptr, g_Whi + (size_t)3 * WSZ, g_Wlo + (size_t)3 * WSZ,
                      bo, 2, 0, Y, nullptr, nullptr);
}

// ---------------- flash attention: Q single, S 2-pass, V/P single ------------
#define FROWB   144                        // 64 fp16 = 128B + 16B pad
#define FQTILE  (128 * FROWB)              // 18432
#define KTILE   (64 * FROWB)               // 9216
#define FSTAGE(s) (FQTILE + (s) * 3 * KTILE)
#define FK_HI   0
#define FK_LO   (KTILE)
#define FV      (2 * KTILE)
#define SMEM_FLASH (FQTILE + 6 * KTILE)    // 73728 (72 KB)

__device__ __forceinline__ void flash_load_q(uint32_t sb, const __half* Qs,
                                             int q0, int tid)
{
    #pragma unroll
    for (int it = 0; it < 4; it++) {
        int u = tid + it * 256;           // 0..1023
        int r = u >> 3, c = u & 7;
        uint32_t so = (uint32_t)(r * FROWB + c * 16);
        cpasync16(sb + so, Qs + (size_t)(q0 + r) * DMODEL + c * 8);
    }
}
__device__ __forceinline__ void flash_load_kv(uint32_t stb,
    const __half* Kh, const __half* Kl, const __half* Vs, int k0, int tid)
{
    #pragma unroll
    for (int it = 0; it < 2; it++) {
        int u = tid + it * 256;           // 0..511
        int r = u >> 3, c = u & 7;
        uint32_t so = (uint32_t)(r * FROWB + c * 16);
        size_t ge = (size_t)(k0 + r) * DMODEL + c * 8;
        cpasync16(stb + FK_HI + so, Kh + ge);
        cpasync16(stb + FK_LO + so, Kl + ge);
        cpasync16(stb + FV    + so, Vs + ge);
    }
}

__global__ __launch_bounds__(256, 2)
void flash_attn_mma()
{
    extern __shared__ char smem[];
    const uint32_t sb = smem_u32(smem);
    const int tid  = threadIdx.x;
    const int w    = tid >> 5;
    const int lane = tid & 31;

    const int b  = blockIdx.z;
    const int h  = blockIdx.y;
    const int q0 = blockIdx.x * 128;

    const size_t base = (size_t)b * SEQ * DMODEL + (size_t)h * HDIM;
    const __half* Qs = g_Q   + base;
    const __half* Kh = g_Khi + base;
    const __half* Kl = g_Klo + base;
    const __half* Vs = g_V   + base;

    const uint32_t qa = (uint32_t)((w * 16 + (lane & 15)) * FROWB
                      + ((lane >> 4) & 1) * 16);
    const uint32_t ka_row = (uint32_t)((lane & 7) + ((lane >> 4) & 1) * 8);
    const uint32_t ka_ko  = (uint32_t)(((lane >> 3) & 1) * 16);
    const uint32_t va_row = (uint32_t)(lane & 15);
    const uint32_t va_co  = (uint32_t)(((lane >> 4) & 1) * 16);

    float o[8][4];
    #pragma unroll
    for (int nb = 0; nb < 8; nb++)
        #pragma unroll
        for (int e = 0; e < 4; e++) o[nb][e] = 0.f;
    float m_a = -CUDART_INF_F, m_b = -CUDART_INF_F, l_a = 0.f, l_b = 0.f;

    uint32_t aQ[4][4];

    flash_load_q(sb, Qs, q0, tid);
    flash_load_kv(sb + FSTAGE(0), Kh, Kl, Vs, 0, tid);
    CPASYNC_COMMIT();

    const int NKT = SEQ / 64;             // 32
    for (int kt = 0; kt < NKT; kt++) {
        const uint32_t st = sb + FSTAGE(kt & 1);
        if (kt + 1 < NKT) {
            flash_load_kv(sb + FSTAGE((kt + 1) & 1), Kh, Kl, Vs, (kt + 1) * 64, tid);
            CPASYNC_COMMIT();
            CPASYNC_WAIT(1);
        } else {
            CPASYNC_WAIT(0);
        }
        __syncthreads();

        if (kt == 0) {
            #pragma unroll
            for (int k4 = 0; k4 < 4; k4++)
                ldm_x4(aQ[k4], sb + qa + k4 * 32);
        }

        // ---- S = Q (Khi + Klo): 2 passes ------------------------------------
        float s[8][4];
        #pragma unroll
        for (int j = 0; j < 8; j++)
            #pragma unroll
            for (int e = 0; e < 4; e++) s[j][e] = 0.f;

        #pragma unroll
        for (int k4 = 0; k4 < 4; k4++) {
            uint32_t kH[4][4];
            #pragma unroll
            for (int nb = 0; nb < 4; nb++)
                ldm_x4(kH[nb], st + FK_HI + (uint32_t)(nb * 16) * FROWB
                               + ka_row * FROWB + ka_ko + k4 * 32);
            #pragma unroll
            for (int nb = 0; nb < 4; nb++) {
                mma_f16(s[2*nb],   aQ[k4], kH[nb][0], kH[nb][1]);
                mma_f16(s[2*nb+1], aQ[k4], kH[nb][2], kH[nb][3]);
            }
            uint32_t kL[4][4];
            #pragma unroll
            for (int nb = 0; nb < 4; nb++)
                ldm_x4(kL[nb], st + FK_LO + (uint32_t)(nb * 16) * FROWB
                               + ka_row * FROWB + ka_ko + k4 * 32);
            #pragma unroll
            for (int nb = 0; nb < 4; nb++) {
                mma_f16(s[2*nb],   aQ[k4], kL[nb][0], kL[nb][1]);
                mma_f16(s[2*nb+1], aQ[k4], kL[nb][2], kL[nb][3]);
            }
        }

        // ---- online softmax (rows a = lane/4, b = lane/4+8) -----------------
        float mloc_a = -CUDART_INF_F, mloc_b = -CUDART_INF_F;
        #pragma unroll
        for (int j = 0; j < 8; j++) {
            s[j][0] *= 0.125f; s[j][1] *= 0.125f;
            s[j][2] *= 0.125f; s[j][3] *= 0.125f;
            mloc_a = fmaxf(mloc_a, fmaxf(s[j][0], s[j][1]));
            mloc_b = fmaxf(mloc_b, fmaxf(s[j][2], s[j][3]));
        }
        mloc_a = fmaxf(mloc_a, __shfl_xor_sync(0xffffffffu, mloc_a, 1));
        mloc_a = fmaxf(mloc_a, __shfl_xor_sync(0xffffffffu, mloc_a, 2));
        mloc_b = fmaxf(mloc_b, __shfl_xor_sync(0xffffffffu, mloc_b, 1));
        mloc_b = fmaxf(mloc_b, __shfl_xor_sync(0xffffffffu, mloc_b, 2));

        float mn_a = fmaxf(m_a, mloc_a), mn_b = fmaxf(m_b, mloc_b);
        float corr_a = __expf(m_a - mn_a), corr_b = __expf(m_b - mn_b);
        m_a = mn_a; m_b = mn_b;

        float rs_a = 0.f, rs_b = 0.f;
        #pragma unroll
        for (int j = 0; j < 8; j++) {
            s[j][0] = __expf(s[j][0] - mn_a);
            s[j][1] = __expf(s[j][1] - mn_a);
            s[j][2] = __expf(s[j][2] - mn_b);
            s[j][3] = __expf(s[j][3] - mn_b);
            rs_a += s[j][0] + s[j][1];
            rs_b += s[j][2] + s[j][3];
        }
        rs_a += __shfl_xor_sync(0xffffffffu, rs_a, 1);
        rs_a += __shfl_xor_sync(0xffffffffu, rs_a, 2);
        rs_b += __shfl_xor_sync(0xffffffffu, rs_b, 1);
        rs_b += __shfl_xor_sync(0xffffffffu, rs_b, 2);
        l_a = l_a * corr_a + rs_a;
        l_b = l_b * corr_b + rs_b;

        #pragma unroll
        for (int nb = 0; nb < 8; nb++) {
            o[nb][0] *= corr_a; o[nb][1] *= corr_a;
            o[nb][2] *= corr_b; o[nb][3] *= corr_b;
        }

        // ---- O += P V: single pass ------------------------------------------
        #pragma unroll
        for (int t = 0; t < 4; t++) {
            uint32_t pP[4];
            pP[0] = pack2h(s[2*t][0],   s[2*t][1]);
            pP[1] = pack2h(s[2*t][2],   s[2*t][3]);
            pP[2] = pack2h(s[2*t+1][0], s[2*t+1][1]);
            pP[3] = pack2h(s[2*t+1][2], s[2*t+1][3]);

            uint32_t vS[4][4];
            #pragma unroll
            for (int ng = 0; ng < 4; ng++)
                ldm_x4t(vS[ng], st + FV + (uint32_t)(t * 16 + va_row) * FROWB
                                + (uint32_t)(ng * 32) + va_co);
            #pragma unroll
            for (int ng = 0; ng < 4; ng++) {
                mma_f16(o[2*ng],   pP, vS[ng][0], vS[ng][1]);
                mma_f16(o[2*ng+1], pP, vS[ng][2], vS[ng][3]);
            }
        }
        __syncthreads();
    }

    // ---- epilogue: normalize, pack single fp16 ctx --------------------------
    const float inv_a = 1.0f / l_a, inv_b = 1.0f / l_b;
    const int row_a = q0 + w * 16 + (lane >> 2);
    const int col0  = (lane & 3) * 2;
    #pragma unroll
    for (int nb = 0; nb < 8; nb++) {
        int col = nb * 8 + col0;
        size_t ea = base + (size_t)row_a * DMODEL + col;
        size_t eb = base + (size_t)(row_a + 8) * DMODEL + col;
        *(uint32_t*)(g_C + ea) = pack2h(o[nb][0] * inv_a, o[nb][1] * inv_a);
        *(uint32_t*)(g_C + eb) = pack2h(o[nb][2] * inv_b, o[nb][3] * inv_b);
    }
}

// ---------------------------------------------------------------------------
extern "C" void kernel_launch(void* const* d_in, const int* in_sizes, int n_in,
                              void* d_out, int out_size)
{
    const float* x  = (const float*)d_in[0];
    const float* Wq = (const float*)d_in[1];
    const float* bq = (const float*)d_in[2];
    const float* Wk = (const float*)d_in[3];
    const float* bk = (const float*)d_in[4];
    const float* Wv = (const float*)d_in[5];
    const float* bv = (const float*)d_in[6];
    const float* Wo = (const float*)d_in[7];
    const float* bo = (const float*)d_in[8];
    float* out = (float*)d_out;

    cudaFuncSetAttribute(gemm_qkv_mma,   cudaFuncAttributeMaxDynamicSharedMemorySize, SMEM_QKV);
    cudaFuncSetAttribute(gemm_out_mma,   cudaFuncAttributeMaxDynamicSharedMemorySize, SMEM_OUT);
    cudaFuncSetAttribute(flash_attn_mma, cudaFuncAttributeMaxDynamicSharedMemorySize, SMEM_FLASH);

    split_all<<<(XN8 + 4 * WN8) / 256, 256>>>(x, Wq, Wk, Wv, Wo);

    dim3 qgrid(DMODEL / 128, MTOT / 128, 3);
    gemm_qkv_mma<<<qgrid, 256, SMEM_QKV>>>(bq, bk, bv);

    dim3 fgrid(SEQ / 128, NHEADS, BATCH);
    flash_attn_mma<<<fgrid, 256, SMEM_FLASH>>>();

    dim3 ogrid(DMODEL / 128, MTOT / 128, 1);
    gemm_out_mma<<<ogrid, 256, SMEM_OUT>>>(bo, out);
}

// round 10
// speedup vs baseline: 5.0869x; 1.1706x over previous
#include <cuda_runtime.h>
#include <cuda_fp16.h>
#include <math_constants.h>
#include <cstdint>

#define BATCH  2
#define SEQ    2048
#define DMODEL 1024
#define NHEADS 16
#define HDIM   64
#define MTOT   (BATCH*SEQ)   // 4096
#define WSZ    (DMODEL*DMODEL)

// ---------------- scratch (allocation-free rule: __device__ globals) --------
__device__ __half g_Xhi[(size_t)MTOT * DMODEL];
__device__ __half g_Whi[(size_t)4 * WSZ];
__device__ __half g_Wlo[(size_t)4 * WSZ];
__device__ __half g_Q  [(size_t)MTOT * DMODEL];
__device__ __half g_K  [(size_t)MTOT * DMODEL];
__device__ __half g_V  [(size_t)MTOT * DMODEL];
__device__ __half g_C  [(size_t)MTOT * DMODEL];

// ---------------- helpers (baseline ISA only) --------------------------------
__device__ __forceinline__ uint32_t smem_u32(const void* p) {
    uint32_t a;
    asm("{ .reg .u64 t; cvta.to.shared.u64 t, %1; cvt.u32.u64 %0, t; }"
        : "=r"(a) : "l"(p));
    return a;
}
__device__ __forceinline__ void cpasync16(uint32_t dst, const void* src) {
    asm volatile("cp.async.cg.shared.global [%0], [%1], 16;" :: "r"(dst), "l"(src));
}
#define CPASYNC_COMMIT() asm volatile("cp.async.commit_group;" ::: "memory")
#define CPASYNC_WAIT(n)  asm volatile("cp.async.wait_group %0;" :: "n"(n) : "memory")

__device__ __forceinline__ void ldm_x4(uint32_t* r, uint32_t addr) {
    asm volatile("ldmatrix.sync.aligned.m8n8.x4.shared.b16 {%0,%1,%2,%3}, [%4];"
        : "=r"(r[0]), "=r"(r[1]), "=r"(r[2]), "=r"(r[3]) : "r"(addr));
}
__device__ __forceinline__ void ldm_x4t(uint32_t* r, uint32_t addr) {
    asm volatile("ldmatrix.sync.aligned.m8n8.x4.trans.shared.b16 {%0,%1,%2,%3}, [%4];"
        : "=r"(r[0]), "=r"(r[1]), "=r"(r[2]), "=r"(r[3]) : "r"(addr));
}
__device__ __forceinline__ void mma_f16(float* c, const uint32_t* a,
                                        uint32_t b0, uint32_t b1) {
    asm volatile("mma.sync.aligned.m16n8k16.row.col.f32.f16.f16.f32 "
        "{%0,%1,%2,%3}, {%4,%5,%6,%7}, {%8,%9}, {%0,%1,%2,%3};"
        : "+f"(c[0]), "+f"(c[1]), "+f"(c[2]), "+f"(c[3])
        : "r"(a[0]), "r"(a[1]), "r"(a[2]), "r"(a[3]), "r"(b0), "r"(b1));
}
__device__ __forceinline__ uint32_t pack2h(float v0, float v1) {
    __half h0 = __float2half_rn(v0), h1 = __float2half_rn(v1);
    return ((uint32_t)__half_as_ushort(h1) << 16) | __half_as_ushort(h0);
}
__device__ __forceinline__ void split2h(float v0, float v1, uint32_t& hi, uint32_t& lo) {
    __half h0 = __float2half_rn(v0), h1 = __float2half_rn(v1);
    __half l0 = __float2half_rn(v0 - __half2float(h0));
    __half l1 = __float2half_rn(v1 - __half2float(h1));
    hi = ((uint32_t)__half_as_ushort(h1) << 16) | __half_as_ushort(h0);
    lo = ((uint32_t)__half_as_ushort(l1) << 16) | __half_as_ushort(l0);
}

// ---------------- fused fp32 -> fp16 convert/split ---------------------------
// x -> hi only. W -> hi/lo.
#define XN8  (MTOT * DMODEL / 8)          // 524288
#define WN8  (WSZ / 8)                    // 131072
__global__ __launch_bounds__(256)
void split_all(const float* __restrict__ x,  const float* __restrict__ Wq,
               const float* __restrict__ Wk, const float* __restrict__ Wv,
               const float* __restrict__ Wo)
{
    int id = blockIdx.x * 256 + threadIdx.x;
    if (id < XN8) {
        const float4* s = (const float4*)x + (size_t)id * 2;
        float4 a = s[0], b = s[1];
        uint4 hp;
        hp.x = pack2h(a.x, a.y);
        hp.y = pack2h(a.z, a.w);
        hp.z = pack2h(b.x, b.y);
        hp.w = pack2h(b.z, b.w);
        ((uint4*)g_Xhi)[id] = hp;
    } else {
        int r   = (id - XN8) >> 17;        // WN8 = 2^17
        int off = (id - XN8) & (WN8 - 1);
        const float* src = (r == 0) ? Wq : (r == 1) ? Wk : (r == 2) ? Wv : Wo;
        __half* hi = g_Whi + (size_t)r * WSZ;
        __half* lo = g_Wlo + (size_t)r * WSZ;
        const float4* s = (const float4*)src + (size_t)off * 2;
        float4 a = s[0], b = s[1];
        uint4 hp, lp;
        split2h(a.x, a.y, hp.x, lp.x);
        split2h(a.z, a.w, hp.y, lp.y);
        split2h(b.x, b.y, hp.z, lp.z);
        split2h(b.z, b.w, hp.w, lp.w);
        ((uint4*)hi)[off] = hp;
        ((uint4*)lo)[off] = lp;
    }
}

// ---------------- HMMA GEMM: Y = A(fp16) @ (Whi+Wlo)^T + bias ----------------
// 2 passes. outmode: 0 = fp32 Y ; 2 = single fp16
#define BK        32
#define ROWB      80
#define TILE_B    (128 * ROWB)
#define OFF_BH    (TILE_B)
#define OFF_BL    (2 * TILE_B)
#define STAGE_B   (3 * TILE_B)
#define SMEM_GEMM (2 * STAGE_B)            // 61440

__device__ __forceinline__ void load_chunk(
    uint32_t sdst, const __half* __restrict__ A,
    const __half* __restrict__ Whi, const __half* __restrict__ Wlo,
    int bm, int bn, int k0, int tid)
{
    #pragma unroll
    for (int it = 0; it < 2; it++) {
        int u = tid + it * 256;
        int r = u >> 2, c = u & 3;
        uint32_t so = (uint32_t)(r * ROWB + c * 16);
        size_t ga = (size_t)(bm + r) * DMODEL + k0 + c * 8;
        size_t gb = (size_t)(bn + r) * DMODEL + k0 + c * 8;
        cpasync16(sdst + so, A + ga);
        cpasync16(sdst + OFF_BH + so, Whi + gb);
        cpasync16(sdst + OFF_BL + so, Wlo + gb);
    }
}

__device__ __forceinline__ void gemm_hmma_body(
    const __half* __restrict__ A,
    const __half* __restrict__ Whi, const __half* __restrict__ Wlo,
    const float* __restrict__ bias, int outmode,
    float* __restrict__ Y, __half* __restrict__ Yh)
{
    extern __shared__ char smem[];
    const uint32_t sb = smem_u32(smem);
    const int tid  = threadIdx.x;
    const int lane = tid & 31;
    const int wid  = tid >> 5;
    const int wm   = wid & 1;
    const int wn   = wid >> 1;

    const int bm = blockIdx.y * 128;
    const int bn = blockIdx.x * 128;

    float acc[4][4][4];
    #pragma unroll
    for (int mi = 0; mi < 4; mi++)
        #pragma unroll
        for (int ni = 0; ni < 4; ni++)
            #pragma unroll
            for (int e = 0; e < 4; e++) acc[mi][ni][e] = 0.f;

    const uint32_t a_row  = (uint32_t)(wm * 64 + (lane & 15));
    const uint32_t a_koff = (uint32_t)(((lane >> 4) & 1) * 16);
    const uint32_t b_nrow = (uint32_t)(wn * 32 + (lane & 7) + ((lane >> 4) & 1) * 8);
    const uint32_t b_koff = (uint32_t)(((lane >> 3) & 1) * 16);

    load_chunk(sb, A, Whi, Wlo, bm, bn, 0, tid);
    CPASYNC_COMMIT();

    const int NCH = DMODEL / BK;
    for (int ch = 0; ch < NCH; ch++) {
        const uint32_t st = sb + (uint32_t)(ch & 1) * STAGE_B;
        if (ch + 1 < NCH) {
            load_chunk(sb + (uint32_t)((ch + 1) & 1) * STAGE_B,
                       A, Whi, Wlo, bm, bn, (ch + 1) * BK, tid);
            CPASYNC_COMMIT();
            CPASYNC_WAIT(1);
        } else {
            CPASYNC_WAIT(0);
        }
        __syncthreads();

        #pragma unroll
        for (int ks = 0; ks < 2; ks++) {
            const uint32_t kb = (uint32_t)(ks * 32);
            uint32_t aA[4][4], bH[2][4], bL[2][4];
            #pragma unroll
            for (int mi = 0; mi < 4; mi++)
                ldm_x4(aA[mi], st + (a_row + mi * 16) * ROWB + kb + a_koff);
            #pragma unroll
            for (int p = 0; p < 2; p++) {
                uint32_t bd = st + (b_nrow + p * 16) * ROWB + kb + b_koff;
                ldm_x4(bH[p], bd + OFF_BH);
                ldm_x4(bL[p], bd + OFF_BL);
            }
            #pragma unroll
            for (int mi = 0; mi < 4; mi++)
                #pragma unroll
                for (int ni = 0; ni < 4; ni++) {
                    const uint32_t* bh = &bH[ni >> 1][(ni & 1) * 2];
                    mma_f16(acc[mi][ni], aA[mi], bh[0], bh[1]);
                }
            #pragma unroll
            for (int mi = 0; mi < 4; mi++)
                #pragma unroll
                for (int ni = 0; ni < 4; ni++) {
                    const uint32_t* bl = &bL[ni >> 1][(ni & 1) * 2];
                    mma_f16(acc[mi][ni], aA[mi], bl[0], bl[1]);
                }
        }
        __syncthreads();
    }

    const int l4 = lane >> 2;
    const int l2 = (lane & 3) * 2;
    #pragma unroll
    for (int mi = 0; mi < 4; mi++) {
        #pragma unroll
        for (int ni = 0; ni < 4; ni++) {
            int gr = bm + wm * 64 + mi * 16 + l4;
            int gc = bn + wn * 32 + ni * 8 + l2;
            float b0 = bias[gc], b1 = bias[gc + 1];
            float v0 = acc[mi][ni][0] + b0, v1 = acc[mi][ni][1] + b1;
            float v2 = acc[mi][ni][2] + b0, v3 = acc[mi][ni][3] + b1;
            if (outmode == 0) {
                *(float2*)(Y + (size_t)gr * DMODEL + gc)       = make_float2(v0, v1);
                *(float2*)(Y + (size_t)(gr + 8) * DMODEL + gc) = make_float2(v2, v3);
            } else {
                *(uint32_t*)(Yh + (size_t)gr * DMODEL + gc)       = pack2h(v0, v1);
                *(uint32_t*)(Yh + (size_t)(gr + 8) * DMODEL + gc) = pack2h(v2, v3);
            }
        }
    }
}

__global__ __launch_bounds__(256, 2)
void gemm_qkv_mma(const float* __restrict__ bq, const float* __restrict__ bk,
                  const float* __restrict__ bv)
{
    int z = blockIdx.z;
    const float* bias = (z == 0) ? bq : (z == 1) ? bk : bv;
    __half* Yh = (z == 0) ? g_Q : (z == 1) ? g_K : g_V;
    gemm_hmma_body(g_Xhi, g_Whi + (size_t)z * WSZ, g_Wlo + (size_t)z * WSZ,
                   bias, 2, nullptr, Yh);
}

__global__ __launch_bounds__(256, 2)
void gemm_out_mma(const float* __restrict__ bo, float* __restrict__ Y)
{
    gemm_hmma_body(g_C, g_Whi + (size_t)3 * WSZ, g_Wlo + (size_t)3 * WSZ,
                   bo, 0, Y, nullptr);
}

// ---------------- flash attention: all-single fp16, 1-pass S and PV ----------
#define FROWB   144                        // 64 fp16 = 128B + 16B pad
#define FQTILE  (128 * FROWB)              // 18432
#define KTILE   (64 * FROWB)               // 9216
#define FSTAGE(s) (FQTILE + (s) * 2 * KTILE)
#define FK      0
#define FV      (KTILE)
#define SMEM_FLASH (FQTILE + 4 * KTILE)    // 55296 (54 KB)

__device__ __forceinline__ void flash_load_q(uint32_t sb, const __half* Qs,
                                             int q0, int tid)
{
    #pragma unroll
    for (int it = 0; it < 4; it++) {
        int u = tid + it * 256;           // 0..1023
        int r = u >> 3, c = u & 7;
        uint32_t so = (uint32_t)(r * FROWB + c * 16);
        cpasync16(sb + so, Qs + (size_t)(q0 + r) * DMODEL + c * 8);
    }
}
__device__ __forceinline__ void flash_load_kv(uint32_t stb,
    const __half* Ks, const __half* Vs, int k0, int tid)
{
    #pragma unroll
    for (int it = 0; it < 2; it++) {
        int u = tid + it * 256;           // 0..511
        int r = u >> 3, c = u & 7;
        uint32_t so = (uint32_t)(r * FROWB + c * 16);
        size_t ge = (size_t)(k0 + r) * DMODEL + c * 8;
        cpasync16(stb + FK + so, Ks + ge);
        cpasync16(stb + FV + so, Vs + ge);
    }
}

__global__ __launch_bounds__(256, 2)
void flash_attn_mma()
{
    extern __shared__ char smem[];
    const uint32_t sb = smem_u32(smem);
    const int tid  = threadIdx.x;
    const int w    = tid >> 5;
    const int lane = tid & 31;

    const int b  = blockIdx.z;
    const int h  = blockIdx.y;
    const int q0 = blockIdx.x * 128;

    const size_t base = (size_t)b * SEQ * DMODEL + (size_t)h * HDIM;
    const __half* Qs = g_Q + base;
    const __half* Ks = g_K + base;
    const __half* Vs = g_V + base;

    const uint32_t qa = (uint32_t)((w * 16 + (lane & 15)) * FROWB
                      + ((lane >> 4) & 1) * 16);
    const uint32_t ka_row = (uint32_t)((lane & 7) + ((lane >> 4) & 1) * 8);
    const uint32_t ka_ko  = (uint32_t)(((lane >> 3) & 1) * 16);
    const uint32_t va_row = (uint32_t)(lane & 15);
    const uint32_t va_co  = (uint32_t)(((lane >> 4) & 1) * 16);

    float o[8][4];
    #pragma unroll
    for (int nb = 0; nb < 8; nb++)
        #pragma unroll
        for (int e = 0; e < 4; e++) o[nb][e] = 0.f;
    float m_a = -CUDART_INF_F, m_b = -CUDART_INF_F, l_a = 0.f, l_b = 0.f;

    uint32_t aQ[4][4];

    flash_load_q(sb, Qs, q0, tid);
    flash_load_kv(sb + FSTAGE(0), Ks, Vs, 0, tid);
    CPASYNC_COMMIT();

    const int NKT = SEQ / 64;             // 32
    for (int kt = 0; kt < NKT; kt++) {
        const uint32_t st = sb + FSTAGE(kt & 1);
        if (kt + 1 < NKT) {
            flash_load_kv(sb + FSTAGE((kt + 1) & 1), Ks, Vs, (kt + 1) * 64, tid);
            CPASYNC_COMMIT();
            CPASYNC_WAIT(1);
        } else {
            CPASYNC_WAIT(0);
        }
        __syncthreads();

        if (kt == 0) {
            #pragma unroll
            for (int k4 = 0; k4 < 4; k4++)
                ldm_x4(aQ[k4], sb + qa + k4 * 32);
        }

        // ---- S = Q K^T : single pass -----------------------------------------
        float s[8][4];
        #pragma unroll
        for (int j = 0; j < 8; j++)
            #pragma unroll
            for (int e = 0; e < 4; e++) s[j][e] = 0.f;

        #pragma unroll
        for (int k4 = 0; k4 < 4; k4++) {
            uint32_t kS[4][4];
            #pragma unroll
            for (int nb = 0; nb < 4; nb++)
                ldm_x4(kS[nb], st + FK + (uint32_t)(nb * 16) * FROWB
                               + ka_row * FROWB + ka_ko + k4 * 32);
            #pragma unroll
            for (int nb = 0; nb < 4; nb++) {
                mma_f16(s[2*nb],   aQ[k4], kS[nb][0], kS[nb][1]);
                mma_f16(s[2*nb+1], aQ[k4], kS[nb][2], kS[nb][3]);
            }
        }

        // ---- online softmax (rows a = lane/4, b = lane/4+8) -----------------
        float mloc_a = -CUDART_INF_F, mloc_b = -CUDART_INF_F;
        #pragma unroll
        for (int j = 0; j < 8; j++) {
            s[j][0] *= 0.125f; s[j][1] *= 0.125f;
            s[j][2] *= 0.125f; s[j][3] *= 0.125f;
            mloc_a = fmaxf(mloc_a, fmaxf(s[j][0], s[j][1]));
            mloc_b = fmaxf(mloc_b, fmaxf(s[j][2], s[j][3]));
        }
        mloc_a = fmaxf(mloc_a, __shfl_xor_sync(0xffffffffu, mloc_a, 1));
        mloc_a = fmaxf(mloc_a, __shfl_xor_sync(0xffffffffu, mloc_a, 2));
        mloc_b = fmaxf(mloc_b, __shfl_xor_sync(0xffffffffu, mloc_b, 1));
        mloc_b = fmaxf(mloc_b, __shfl_xor_sync(0xffffffffu, mloc_b, 2));

        float mn_a = fmaxf(m_a, mloc_a), mn_b = fmaxf(m_b, mloc_b);
        float corr_a = __expf(m_a - mn_a), corr_b = __expf(m_b - mn_b);
        m_a = mn_a; m_b = mn_b;

        float rs_a = 0.f, rs_b = 0.f;
        #pragma unroll
        for (int j = 0; j < 8; j++) {
            s[j][0] = __expf(s[j][0] - mn_a);
            s[j][1] = __expf(s[j][1] - mn_a);
            s[j][2] = __expf(s[j][2] - mn_b);
            s[j][3] = __expf(s[j][3] - mn_b);
            rs_a += s[j][0] + s[j][1];
            rs_b += s[j][2] + s[j][3];
        }
        rs_a += __shfl_xor_sync(0xffffffffu, rs_a, 1);
        rs_a += __shfl_xor_sync(0xffffffffu, rs_a, 2);
        rs_b += __shfl_xor_sync(0xffffffffu, rs_b, 1);
        rs_b += __shfl_xor_sync(0xffffffffu, rs_b, 2);
        l_a = l_a * corr_a + rs_a;
        l_b = l_b * corr_b + rs_b;

        #pragma unroll
        for (int nb = 0; nb < 8; nb++) {
            o[nb][0] *= corr_a; o[nb][1] *= corr_a;
            o[nb][2] *= corr_b; o[nb][3] *= corr_b;
        }

        // ---- O += P V: single pass -------------------------------------------
        #pragma unroll
        for (int t = 0; t < 4; t++) {
            uint32_t pP[4];
            pP[0] = pack2h(s[2*t][0],   s[2*t][1]);
            pP[1] = pack2h(s[2*t][2],   s[2*t][3]);
            pP[2] = pack2h(s[2*t+1][0], s[2*t+1][1]);
            pP[3] = pack2h(s[2*t+1][2], s[2*t+1][3]);

            uint32_t vS[4][4];
            #pragma unroll
            for (int ng = 0; ng < 4; ng++)
                ldm_x4t(vS[ng], st + FV + (uint32_t)(t * 16 + va_row) * FROWB
                                + (uint32_t)(ng * 32) + va_co);
            #pragma unroll
            for (int ng = 0; ng < 4; ng++) {
                mma_f16(o[2*ng],   pP, vS[ng][0], vS[ng][1]);
                mma_f16(o[2*ng+1], pP, vS[ng][2], vS[ng][3]);
            }
        }
        __syncthreads();
    }

    // ---- epilogue: normalize, pack single fp16 ctx --------------------------
    const float inv_a = 1.0f / l_a, inv_b = 1.0f / l_b;
    const int row_a = q0 + w * 16 + (lane >> 2);
    const int col0  = (lane & 3) * 2;
    #pragma unroll
    for (int nb = 0; nb < 8; nb++) {
        int col = nb * 8 + col0;
        size_t ea = base + (size_t)row_a * DMODEL + col;
        size_t eb = base + (size_t)(row_a + 8) * DMODEL + col;
        *(uint32_t*)(g_C + ea) = pack2h(o[nb][0] * inv_a, o[nb][1] * inv_a);
        *(uint32_t*)(g_C + eb) = pack2h(o[nb][2] * inv_b, o[nb][3] * inv_b);
    }
}

// ---------------------------------------------------------------------------
extern "C" void kernel_launch(void* const* d_in, const int* in_sizes, int n_in,
                              void* d_out, int out_size)
{
    const float* x  = (const float*)d_in[0];
    const float* Wq = (const float*)d_in[1];
    const float* bq = (const float*)d_in[2];
    const float* Wk = (const float*)d_in[3];
    const float* bk = (const float*)d_in[4];
    const float* Wv = (const float*)d_in[5];
    const float* bv = (const float*)d_in[6];
    const float* Wo = (const float*)d_in[7];
    const float* bo = (const float*)d_in[8];
    float* out = (float*)d_out;

    cudaFuncSetAttribute(gemm_qkv_mma,   cudaFuncAttributeMaxDynamicSharedMemorySize, SMEM_GEMM);
    cudaFuncSetAttribute(gemm_out_mma,   cudaFuncAttributeMaxDynamicSharedMemorySize, SMEM_GEMM);
    cudaFuncSetAttribute(flash_attn_mma, cudaFuncAttributeMaxDynamicSharedMemorySize, SMEM_FLASH);

    split_all<<<(XN8 + 4 * WN8) / 256, 256>>>(x, Wq, Wk, Wv, Wo);

    dim3 qgrid(DMODEL / 128, MTOT / 128, 3);
    gemm_qkv_mma<<<qgrid, 256, SMEM_GEMM>>>(bq, bk, bv);

    dim3 fgrid(SEQ / 128, NHEADS, BATCH);
    flash_attn_mma<<<fgrid, 256, SMEM_FLASH>>>();

    dim3 ogrid(DMODEL / 128, MTOT / 128, 1);
    gemm_out_mma<<<ogrid, 256, SMEM_GEMM>>>(bo, out);
}

// round 11
// speedup vs baseline: 6.8234x; 1.3414x over previous
#include <cuda_runtime.h>
#include <cuda_fp16.h>
#include <math_constants.h>
#include <cstdint>

#define BATCH  2
#define SEQ    2048
#define DMODEL 1024
#define NHEADS 16
#define HDIM   64
#define MTOT   (BATCH*SEQ)   // 4096
#define WSZ    (DMODEL*DMODEL)

// ---------------- scratch (allocation-free rule: __device__ globals) --------
__device__ __half g_X[(size_t)MTOT * DMODEL];
__device__ __half g_W[(size_t)4 * WSZ];
__device__ __half g_Q[(size_t)MTOT * DMODEL];
__device__ __half g_K[(size_t)MTOT * DMODEL];
__device__ __half g_V[(size_t)MTOT * DMODEL];
__device__ __half g_C[(size_t)MTOT * DMODEL];

// ---------------- helpers (baseline ISA only) --------------------------------
__device__ __forceinline__ uint32_t smem_u32(const void* p) {
    uint32_t a;
    asm("{ .reg .u64 t; cvta.to.shared.u64 t, %1; cvt.u32.u64 %0, t; }"
        : "=r"(a) : "l"(p));
    return a;
}
__device__ __forceinline__ void cpasync16(uint32_t dst, const void* src) {
    asm volatile("cp.async.cg.shared.global [%0], [%1], 16;" :: "r"(dst), "l"(src));
}
#define CPASYNC_COMMIT() asm volatile("cp.async.commit_group;" ::: "memory")
#define CPASYNC_WAIT(n)  asm volatile("cp.async.wait_group %0;" :: "n"(n) : "memory")

__device__ __forceinline__ void ldm_x4(uint32_t* r, uint32_t addr) {
    asm volatile("ldmatrix.sync.aligned.m8n8.x4.shared.b16 {%0,%1,%2,%3}, [%4];"
        : "=r"(r[0]), "=r"(r[1]), "=r"(r[2]), "=r"(r[3]) : "r"(addr));
}
__device__ __forceinline__ void ldm_x4t(uint32_t* r, uint32_t addr) {
    asm volatile("ldmatrix.sync.aligned.m8n8.x4.trans.shared.b16 {%0,%1,%2,%3}, [%4];"
        : "=r"(r[0]), "=r"(r[1]), "=r"(r[2]), "=r"(r[3]) : "r"(addr));
}
__device__ __forceinline__ void mma_f16(float* c, const uint32_t* a,
                                        uint32_t b0, uint32_t b1) {
    asm volatile("mma.sync.aligned.m16n8k16.row.col.f32.f16.f16.f32 "
        "{%0,%1,%2,%3}, {%4,%5,%6,%7}, {%8,%9}, {%0,%1,%2,%3};"
        : "+f"(c[0]), "+f"(c[1]), "+f"(c[2]), "+f"(c[3])
        : "r"(a[0]), "r"(a[1]), "r"(a[2]), "r"(a[3]), "r"(b0), "r"(b1));
}
__device__ __forceinline__ uint32_t pack2h(float v0, float v1) {
    __half h0 = __float2half_rn(v0), h1 = __float2half_rn(v1);
    return ((uint32_t)__half_as_ushort(h1) << 16) | __half_as_ushort(h0);
}

// ---------------- fused fp32 -> fp16 convert (x + 4 weights) -----------------
#define XN8  (MTOT * DMODEL / 8)          // 524288
#define WN8  (WSZ / 8)                    // 131072
__global__ __launch_bounds__(256)
void split_all(const float* __restrict__ x,  const float* __restrict__ Wq,
               const float* __restrict__ Wk, const float* __restrict__ Wv,
               const float* __restrict__ Wo)
{
    int id = blockIdx.x * 256 + threadIdx.x;
    const float* src;
    __half* dst;
    int off;
    if (id < XN8) {
        src = x; dst = g_X; off = id;
    } else {
        int r = (id - XN8) >> 17;          // WN8 = 2^17
        off   = (id - XN8) & (WN8 - 1);
        src = (r == 0) ? Wq : (r == 1) ? Wk : (r == 2) ? Wv : Wo;
        dst = g_W + (size_t)r * WSZ;
    }
    const float4* s = (const float4*)src + (size_t)off * 2;
    float4 a = s[0], b = s[1];
    uint4 hp;
    hp.x = pack2h(a.x, a.y);
    hp.y = pack2h(a.z, a.w);
    hp.z = pack2h(b.x, b.y);
    hp.w = pack2h(b.z, b.w);
    ((uint4*)dst)[off] = hp;
}

// ---------------- HMMA GEMM: Y = A(fp16) @ W(fp16)^T + bias ------------------
// single pass. outmode: 0 = fp32 Y ; 2 = single fp16
#define BK        32
#define ROWB      80
#define TILE_B    (128 * ROWB)
#define OFF_B     (TILE_B)
#define STAGE_B   (2 * TILE_B)
#define SMEM_GEMM (2 * STAGE_B)            // 40960

__device__ __forceinline__ void load_chunk(
    uint32_t sdst, const __half* __restrict__ A, const __half* __restrict__ W,
    int bm, int bn, int k0, int tid)
{
    #pragma unroll
    for (int it = 0; it < 2; it++) {
        int u = tid + it * 256;
        int r = u >> 2, c = u & 3;
        uint32_t so = (uint32_t)(r * ROWB + c * 16);
        cpasync16(sdst + so,         A + (size_t)(bm + r) * DMODEL + k0 + c * 8);
        cpasync16(sdst + OFF_B + so, W + (size_t)(bn + r) * DMODEL + k0 + c * 8);
    }
}

__device__ __forceinline__ void gemm_hmma_body(
    const __half* __restrict__ A, const __half* __restrict__ W,
    const float* __restrict__ bias, int outmode,
    float* __restrict__ Y, __half* __restrict__ Yh)
{
    extern __shared__ char smem[];
    const uint32_t sb = smem_u32(smem);
    const int tid  = threadIdx.x;
    const int lane = tid & 31;
    const int wid  = tid >> 5;
    const int wm   = wid & 1;
    const int wn   = wid >> 1;

    const int bm = blockIdx.y * 128;
    const int bn = blockIdx.x * 128;

    float acc[4][4][4];
    #pragma unroll
    for (int mi = 0; mi < 4; mi++)
        #pragma unroll
        for (int ni = 0; ni < 4; ni++)
            #pragma unroll
            for (int e = 0; e < 4; e++) acc[mi][ni][e] = 0.f;

    const uint32_t a_row  = (uint32_t)(wm * 64 + (lane & 15));
    const uint32_t a_koff = (uint32_t)(((lane >> 4) & 1) * 16);
    const uint32_t b_nrow = (uint32_t)(wn * 32 + (lane & 7) + ((lane >> 4) & 1) * 8);
    const uint32_t b_koff = (uint32_t)(((lane >> 3) & 1) * 16);

    load_chunk(sb, A, W, bm, bn, 0, tid);
    CPASYNC_COMMIT();

    const int NCH = DMODEL / BK;
    for (int ch = 0; ch < NCH; ch++) {
        const uint32_t st = sb + (uint32_t)(ch & 1) * STAGE_B;
        if (ch + 1 < NCH) {
            load_chunk(sb + (uint32_t)((ch + 1) & 1) * STAGE_B,
                       A, W, bm, bn, (ch + 1) * BK, tid);
            CPASYNC_COMMIT();
            CPASYNC_WAIT(1);
        } else {
            CPASYNC_WAIT(0);
        }
        __syncthreads();

        #pragma unroll
        for (int ks = 0; ks < 2; ks++) {
            const uint32_t kb = (uint32_t)(ks * 32);
            uint32_t aA[4][4], bB[2][4];
            #pragma unroll
            for (int mi = 0; mi < 4; mi++)
                ldm_x4(aA[mi], st + (a_row + mi * 16) * ROWB + kb + a_koff);
            #pragma unroll
            for (int p = 0; p < 2; p++)
                ldm_x4(bB[p], st + OFF_B + (b_nrow + p * 16) * ROWB + kb + b_koff);
            #pragma unroll
            for (int mi = 0; mi < 4; mi++)
                #pragma unroll
                for (int ni = 0; ni < 4; ni++) {
                    const uint32_t* bb = &bB[ni >> 1][(ni & 1) * 2];
                    mma_f16(acc[mi][ni], aA[mi], bb[0], bb[1]);
                }
        }
        __syncthreads();
    }

    const int l4 = lane >> 2;
    const int l2 = (lane & 3) * 2;
    #pragma unroll
    for (int mi = 0; mi < 4; mi++) {
        #pragma unroll
        for (int ni = 0; ni < 4; ni++) {
            int gr = bm + wm * 64 + mi * 16 + l4;
            int gc = bn + wn * 32 + ni * 8 + l2;
            float b0 = bias[gc], b1 = bias[gc + 1];
            float v0 = acc[mi][ni][0] + b0, v1 = acc[mi][ni][1] + b1;
            float v2 = acc[mi][ni][2] + b0, v3 = acc[mi][ni][3] + b1;
            if (outmode == 0) {
                *(float2*)(Y + (size_t)gr * DMODEL + gc)       = make_float2(v0, v1);
                *(float2*)(Y + (size_t)(gr + 8) * DMODEL + gc) = make_float2(v2, v3);
            } else {
                *(uint32_t*)(Yh + (size_t)gr * DMODEL + gc)       = pack2h(v0, v1);
                *(uint32_t*)(Yh + (size_t)(gr + 8) * DMODEL + gc) = pack2h(v2, v3);
            }
        }
    }
}

__global__ __launch_bounds__(256, 2)
void gemm_qkv_mma(const float* __restrict__ bq, const float* __restrict__ bk,
                  const float* __restrict__ bv)
{
    int z = blockIdx.z;
    const float* bias = (z == 0) ? bq : (z == 1) ? bk : bv;
    __half* Yh = (z == 0) ? g_Q : (z == 1) ? g_K : g_V;
    gemm_hmma_body(g_X, g_W + (size_t)z * WSZ, bias, 2, nullptr, Yh);
}

__global__ __launch_bounds__(256, 2)
void gemm_out_mma(const float* __restrict__ bo, float* __restrict__ Y)
{
    gemm_hmma_body(g_C, g_W + (size_t)3 * WSZ, bo, 0, Y, nullptr);
}

// ---------------- flash attention: all-single fp16 (unchanged from R10) ------
#define FROWB   144                        // 64 fp16 = 128B + 16B pad
#define FQTILE  (128 * FROWB)              // 18432
#define KTILE   (64 * FROWB)               // 9216
#define FSTAGE(s) (FQTILE + (s) * 2 * KTILE)
#define FK      0
#define FV      (KTILE)
#define SMEM_FLASH (FQTILE + 4 * KTILE)    // 55296 (54 KB)

__device__ __forceinline__ void flash_load_q(uint32_t sb, const __half* Qs,
                                             int q0, int tid)
{
    #pragma unroll
    for (int it = 0; it < 4; it++) {
        int u = tid + it * 256;           // 0..1023
        int r = u >> 3, c = u & 7;
        uint32_t so = (uint32_t)(r * FROWB + c * 16);
        cpasync16(sb + so, Qs + (size_t)(q0 + r) * DMODEL + c * 8);
    }
}
__device__ __forceinline__ void flash_load_kv(uint32_t stb,
    const __half* Ks, const __half* Vs, int k0, int tid)
{
    #pragma unroll
    for (int it = 0; it < 2; it++) {
        int u = tid + it * 256;           // 0..511
        int r = u >> 3, c = u & 7;
        uint32_t so = (uint32_t)(r * FROWB + c * 16);
        size_t ge = (size_t)(k0 + r) * DMODEL + c * 8;
        cpasync16(stb + FK + so, Ks + ge);
        cpasync16(stb + FV + so, Vs + ge);
    }
}

__global__ __launch_bounds__(256, 2)
void flash_attn_mma()
{
    extern __shared__ char smem[];
    const uint32_t sb = smem_u32(smem);
    const int tid  = threadIdx.x;
    const int w    = tid >> 5;
    const int lane = tid & 31;

    const int b  = blockIdx.z;
    const int h  = blockIdx.y;
    const int q0 = blockIdx.x * 128;

    const size_t base = (size_t)b * SEQ * DMODEL + (size_t)h * HDIM;
    const __half* Qs = g_Q + base;
    const __half* Ks = g_K + base;
    const __half* Vs = g_V + base;

    const uint32_t qa = (uint32_t)((w * 16 + (lane & 15)) * FROWB
                      + ((lane >> 4) & 1) * 16);
    const uint32_t ka_row = (uint32_t)((lane & 7) + ((lane >> 4) & 1) * 8);
    const uint32_t ka_ko  = (uint32_t)(((lane >> 3) & 1) * 16);
    const uint32_t va_row = (uint32_t)(lane & 15);
    const uint32_t va_co  = (uint32_t)(((lane >> 4) & 1) * 16);

    float o[8][4];
    #pragma unroll
    for (int nb = 0; nb < 8; nb++)
        #pragma unroll
        for (int e = 0; e < 4; e++) o[nb][e] = 0.f;
    float m_a = -CUDART_INF_F, m_b = -CUDART_INF_F, l_a = 0.f, l_b = 0.f;

    uint32_t aQ[4][4];

    flash_load_q(sb, Qs, q0, tid);
    flash_load_kv(sb + FSTAGE(0), Ks, Vs, 0, tid);
    CPASYNC_COMMIT();

    const int NKT = SEQ / 64;             // 32
    for (int kt = 0; kt < NKT; kt++) {
        const uint32_t st = sb + FSTAGE(kt & 1);
        if (kt + 1 < NKT) {
            flash_load_kv(sb + FSTAGE((kt + 1) & 1), Ks, Vs, (kt + 1) * 64, tid);
            CPASYNC_COMMIT();
            CPASYNC_WAIT(1);
        } else {
            CPASYNC_WAIT(0);
        }
        __syncthreads();

        if (kt == 0) {
            #pragma unroll
            for (int k4 = 0; k4 < 4; k4++)
                ldm_x4(aQ[k4], sb + qa + k4 * 32);
        }

        // ---- S = Q K^T : single pass -----------------------------------------
        float s[8][4];
        #pragma unroll
        for (int j = 0; j < 8; j++)
            #pragma unroll
            for (int e = 0; e < 4; e++) s[j][e] = 0.f;

        #pragma unroll
        for (int k4 = 0; k4 < 4; k4++) {
            uint32_t kS[4][4];
            #pragma unroll
            for (int nb = 0; nb < 4; nb++)
                ldm_x4(kS[nb], st + FK + (uint32_t)(nb * 16) * FROWB
                               + ka_row * FROWB + ka_ko + k4 * 32);
            #pragma unroll
            for (int nb = 0; nb < 4; nb++) {
                mma_f16(s[2*nb],   aQ[k4], kS[nb][0], kS[nb][1]);
                mma_f16(s[2*nb+1], aQ[k4], kS[nb][2], kS[nb][3]);
            }
        }

        // ---- online softmax (rows a = lane/4, b = lane/4+8) -----------------
        float mloc_a = -CUDART_INF_F, mloc_b = -CUDART_INF_F;
        #pragma unroll
        for (int j = 0; j < 8; j++) {
            s[j][0] *= 0.125f; s[j][1] *= 0.125f;
            s[j][2] *= 0.125f; s[j][3] *= 0.125f;
            mloc_a = fmaxf(mloc_a, fmaxf(s[j][0], s[j][1]));
            mloc_b = fmaxf(mloc_b, fmaxf(s[j][2], s[j][3]));
        }
        mloc_a = fmaxf(mloc_a, __shfl_xor_sync(0xffffffffu, mloc_a, 1));
        mloc_a = fmaxf(mloc_a, __shfl_xor_sync(0xffffffffu, mloc_a, 2));
        mloc_b = fmaxf(mloc_b, __shfl_xor_sync(0xffffffffu, mloc_b, 1));
        mloc_b = fmaxf(mloc_b, __shfl_xor_sync(0xffffffffu, mloc_b, 2));

        float mn_a = fmaxf(m_a, mloc_a), mn_b = fmaxf(m_b, mloc_b);
        float corr_a = __expf(m_a - mn_a), corr_b = __expf(m_b - mn_b);
        m_a = mn_a; m_b = mn_b;

        float rs_a = 0.f, rs_b = 0.f;
        #pragma unroll
        for (int j = 0; j < 8; j++) {
            s[j][0] = __expf(s[j][0] - mn_a);
            s[j][1] = __expf(s[j][1] - mn_a);
            s[j][2] = __expf(s[j][2] - mn_b);
            s[j][3] = __expf(s[j][3] - mn_b);
            rs_a += s[j][0] + s[j][1];
            rs_b += s[j][2] + s[j][3];
        }
        rs_a += __shfl_xor_sync(0xffffffffu, rs_a, 1);
        rs_a += __shfl_xor_sync(0xffffffffu, rs_a, 2);
        rs_b += __shfl_xor_sync(0xffffffffu, rs_b, 1);
        rs_b += __shfl_xor_sync(0xffffffffu, rs_b, 2);
        l_a = l_a * corr_a + rs_a;
        l_b = l_b * corr_b + rs_b;

        #pragma unroll
        for (int nb = 0; nb < 8; nb++) {
            o[nb][0] *= corr_a; o[nb][1] *= corr_a;
            o[nb][2] *= corr_b; o[nb][3] *= corr_b;
        }

        // ---- O += P V: single pass -------------------------------------------
        #pragma unroll
        for (int t = 0; t < 4; t++) {
            uint32_t pP[4];
            pP[0] = pack2h(s[2*t][0],   s[2*t][1]);
            pP[1] = pack2h(s[2*t][2],   s[2*t][3]);
            pP[2] = pack2h(s[2*t+1][0], s[2*t+1][1]);
            pP[3] = pack2h(s[2*t+1][2], s[2*t+1][3]);

            uint32_t vS[4][4];
            #pragma unroll
            for (int ng = 0; ng < 4; ng++)
                ldm_x4t(vS[ng], st + FV + (uint32_t)(t * 16 + va_row) * FROWB
                                + (uint32_t)(ng * 32) + va_co);
            #pragma unroll
            for (int ng = 0; ng < 4; ng++) {
                mma_f16(o[2*ng],   pP, vS[ng][0], vS[ng][1]);
                mma_f16(o[2*ng+1], pP, vS[ng][2], vS[ng][3]);
            }
        }
        __syncthreads();
    }

    // ---- epilogue: normalize, pack single fp16 ctx --------------------------
    const float inv_a = 1.0f / l_a, inv_b = 1.0f / l_b;
    const int row_a = q0 + w * 16 + (lane >> 2);
    const int col0  = (lane & 3) * 2;
    #pragma unroll
    for (int nb = 0; nb < 8; nb++) {
        int col = nb * 8 + col0;
        size_t ea = base + (size_t)row_a * DMODEL + col;
        size_t eb = base + (size_t)(row_a + 8) * DMODEL + col;
        *(uint32_t*)(g_C + ea) = pack2h(o[nb][0] * inv_a, o[nb][1] * inv_a);
        *(uint32_t*)(g_C + eb) = pack2h(o[nb][2] * inv_b, o[nb][3] * inv_b);
    }
}

// ---------------------------------------------------------------------------
extern "C" void kernel_launch(void* const* d_in, const int* in_sizes, int n_in,
                              void* d_out, int out_size)
{
    const float* x  = (const float*)d_in[0];
    const float* Wq = (const float*)d_in[1];
    const float* bq = (const float*)d_in[2];
    const float* Wk = (const float*)d_in[3];
    const float* bk = (const float*)d_in[4];
    const float* Wv = (const float*)d_in[5];
    const float* bv = (const float*)d_in[6];
    const float* Wo = (const float*)d_in[7];
    const float* bo = (const float*)d_in[8];
    float* out = (float*)d_out;

    cudaFuncSetAttribute(gemm_qkv_mma,   cudaFuncAttributeMaxDynamicSharedMemorySize, SMEM_GEMM);
    cudaFuncSetAttribute(gemm_out_mma,   cudaFuncAttributeMaxDynamicSharedMemorySize, SMEM_GEMM);
    cudaFuncSetAttribute(flash_attn_mma, cudaFuncAttributeMaxDynamicSharedMemorySize, SMEM_FLASH);

    split_all<<<(XN8 + 4 * WN8) / 256, 256>>>(x, Wq, Wk, Wv, Wo);

    dim3 qgrid(DMODEL / 128, MTOT / 128, 3);
    gemm_qkv_mma<<<qgrid, 256, SMEM_GEMM>>>(bq, bk, bv);

    dim3 fgrid(SEQ / 128, NHEADS, BATCH);
    flash_attn_mma<<<fgrid, 256, SMEM_FLASH>>>();

    dim3 ogrid(DMODEL / 128, MTOT / 128, 1);
    gemm_out_mma<<<ogrid, 256, SMEM_GEMM>>>(bo, out);
}

// round 12
// speedup vs baseline: 7.2482x; 1.0622x over previous
#include <cuda_runtime.h>
#include <cuda_fp16.h>
#include <math_constants.h>
#include <cstdint>

#define BATCH  2
#define SEQ    2048
#define DMODEL 1024
#define NHEADS 16
#define HDIM   64
#define MTOT   (BATCH*SEQ)   // 4096
#define WSZ    (DMODEL*DMODEL)

// ---------------- scratch (allocation-free rule: __device__ globals) --------
__device__ __half g_X[(size_t)MTOT * DMODEL];
__device__ __half g_W[(size_t)4 * WSZ];
__device__ __half g_Q[(size_t)MTOT * DMODEL];
__device__ __half g_K[(size_t)MTOT * DMODEL];
__device__ __half g_V[(size_t)MTOT * DMODEL];
__device__ __half g_C[(size_t)MTOT * DMODEL];

// ---------------- helpers (baseline ISA only) --------------------------------
__device__ __forceinline__ uint32_t smem_u32(const void* p) {
    uint32_t a;
    asm("{ .reg .u64 t; cvta.to.shared.u64 t, %1; cvt.u32.u64 %0, t; }"
        : "=r"(a) : "l"(p));
    return a;
}
__device__ __forceinline__ void cpasync16(uint32_t dst, const void* src) {
    asm volatile("cp.async.cg.shared.global [%0], [%1], 16;" :: "r"(dst), "l"(src));
}
#define CPASYNC_COMMIT() asm volatile("cp.async.commit_group;" ::: "memory")
#define CPASYNC_WAIT(n)  asm volatile("cp.async.wait_group %0;" :: "n"(n) : "memory")

__device__ __forceinline__ void ldm_x4(uint32_t* r, uint32_t addr) {
    asm volatile("ldmatrix.sync.aligned.m8n8.x4.shared.b16 {%0,%1,%2,%3}, [%4];"
        : "=r"(r[0]), "=r"(r[1]), "=r"(r[2]), "=r"(r[3]) : "r"(addr));
}
__device__ __forceinline__ void ldm_x4t(uint32_t* r, uint32_t addr) {
    asm volatile("ldmatrix.sync.aligned.m8n8.x4.trans.shared.b16 {%0,%1,%2,%3}, [%4];"
        : "=r"(r[0]), "=r"(r[1]), "=r"(r[2]), "=r"(r[3]) : "r"(addr));
}
__device__ __forceinline__ void mma_f16(float* c, const uint32_t* a,
                                        uint32_t b0, uint32_t b1) {
    asm volatile("mma.sync.aligned.m16n8k16.row.col.f32.f16.f16.f32 "
        "{%0,%1,%2,%3}, {%4,%5,%6,%7}, {%8,%9}, {%0,%1,%2,%3};"
        : "+f"(c[0]), "+f"(c[1]), "+f"(c[2]), "+f"(c[3])
        : "r"(a[0]), "r"(a[1]), "r"(a[2]), "r"(a[3]), "r"(b0), "r"(b1));
}
__device__ __forceinline__ uint32_t pack2h(float v0, float v1) {
    __half h0 = __float2half_rn(v0), h1 = __float2half_rn(v1);
    return ((uint32_t)__half_as_ushort(h1) << 16) | __half_as_ushort(h0);
}

// ---------------- fused fp32 -> fp16 convert (x + 4 weights) -----------------
#define XN8  (MTOT * DMODEL / 8)          // 524288
#define WN8  (WSZ / 8)                    // 131072
__global__ __launch_bounds__(256)
void split_all(const float* __restrict__ x,  const float* __restrict__ Wq,
               const float* __restrict__ Wk, const float* __restrict__ Wv,
               const float* __restrict__ Wo)
{
    int id = blockIdx.x * 256 + threadIdx.x;
    const float* src;
    __half* dst;
    int off;
    if (id < XN8) {
        src = x; dst = g_X; off = id;
    } else {
        int r = (id - XN8) >> 17;          // WN8 = 2^17
        off   = (id - XN8) & (WN8 - 1);
        src = (r == 0) ? Wq : (r == 1) ? Wk : (r == 2) ? Wv : Wo;
        dst = g_W + (size_t)r * WSZ;
    }
    const float4* s = (const float4*)src + (size_t)off * 2;
    float4 a = s[0], b = s[1];
    uint4 hp;
    hp.x = pack2h(a.x, a.y);
    hp.y = pack2h(a.z, a.w);
    hp.z = pack2h(b.x, b.y);
    hp.w = pack2h(b.z, b.w);
    ((uint4*)dst)[id < XN8 ? id : off] = hp;
}

// ---------------- HMMA GEMM: Y = A(fp16) @ W(fp16)^T + bias ------------------
// single pass, BK=64 (4 k16 sub-steps per chunk, 16 chunks total)
// outmode: 0 = fp32 Y ; 2 = single fp16
#define BK        64
#define ROWB      144                      // 128B data + 16B pad (conflict-free)
#define TILE_B    (128 * ROWB)             // 18432
#define OFF_B     (TILE_B)
#define STAGE_B   (2 * TILE_B)             // 36864
#define SMEM_GEMM (2 * STAGE_B)            // 73728

__device__ __forceinline__ void load_chunk(
    uint32_t sdst, const __half* __restrict__ A, const __half* __restrict__ W,
    int bm, int bn, int k0, int tid)
{
    #pragma unroll
    for (int it = 0; it < 4; it++) {
        int u = tid + it * 256;            // 0..1023: 128 rows x 8 x 16B
        int r = u >> 3, c = u & 7;
        uint32_t so = (uint32_t)(r * ROWB + c * 16);
        cpasync16(sdst + so,         A + (size_t)(bm + r) * DMODEL + k0 + c * 8);
        cpasync16(sdst + OFF_B + so, W + (size_t)(bn + r) * DMODEL + k0 + c * 8);
    }
}

__device__ __forceinline__ void gemm_hmma_body(
    const __half* __restrict__ A, const __half* __restrict__ W,
    const float* __restrict__ bias, int outmode,
    float* __restrict__ Y, __half* __restrict__ Yh)
{
    extern __shared__ char smem[];
    const uint32_t sb = smem_u32(smem);
    const int tid  = threadIdx.x;
    const int lane = tid & 31;
    const int wid  = tid >> 5;
    const int wm   = wid & 1;
    const int wn   = wid >> 1;

    const int bm = blockIdx.y * 128;
    const int bn = blockIdx.x * 128;

    float acc[4][4][4];
    #pragma unroll
    for (int mi = 0; mi < 4; mi++)
        #pragma unroll
        for (int ni = 0; ni < 4; ni++)
            #pragma unroll
            for (int e = 0; e < 4; e++) acc[mi][ni][e] = 0.f;

    const uint32_t a_row  = (uint32_t)(wm * 64 + (lane & 15));
    const uint32_t a_koff = (uint32_t)(((lane >> 4) & 1) * 16);
    const uint32_t b_nrow = (uint32_t)(wn * 32 + (lane & 7) + ((lane >> 4) & 1) * 8);
    const uint32_t b_koff = (uint32_t)(((lane >> 3) & 1) * 16);

    load_chunk(sb, A, W, bm, bn, 0, tid);
    CPASYNC_COMMIT();

    const int NCH = DMODEL / BK;           // 16
    for (int ch = 0; ch < NCH; ch++) {
        const uint32_t st = sb + (uint32_t)(ch & 1) * STAGE_B;
        if (ch + 1 < NCH) {
            load_chunk(sb + (uint32_t)((ch + 1) & 1) * STAGE_B,
                       A, W, bm, bn, (ch + 1) * BK, tid);
            CPASYNC_COMMIT();
            CPASYNC_WAIT(1);
        } else {
            CPASYNC_WAIT(0);
        }
        __syncthreads();

        #pragma unroll
        for (int ks = 0; ks < 4; ks++) {   // 4 x k16 per chunk
            const uint32_t kb = (uint32_t)(ks * 32);
            uint32_t aA[4][4], bB[2][4];
            #pragma unroll
            for (int mi = 0; mi < 4; mi++)
                ldm_x4(aA[mi], st + (a_row + mi * 16) * ROWB + kb + a_koff);
            #pragma unroll
            for (int p = 0; p < 2; p++)
                ldm_x4(bB[p], st + OFF_B + (b_nrow + p * 16) * ROWB + kb + b_koff);
            #pragma unroll
            for (int mi = 0; mi < 4; mi++)
                #pragma unroll
                for (int ni = 0; ni < 4; ni++) {
                    const uint32_t* bb = &bB[ni >> 1][(ni & 1) * 2];
                    mma_f16(acc[mi][ni], aA[mi], bb[0], bb[1]);
                }
        }
        __syncthreads();
    }

    const int l4 = lane >> 2;
    const int l2 = (lane & 3) * 2;
    #pragma unroll
    for (int mi = 0; mi < 4; mi++) {
        #pragma unroll
        for (int ni = 0; ni < 4; ni++) {
            int gr = bm + wm * 64 + mi * 16 + l4;
            int gc = bn + wn * 32 + ni * 8 + l2;
            float b0 = bias[gc], b1 = bias[gc + 1];
            float v0 = acc[mi][ni][0] + b0, v1 = acc[mi][ni][1] + b1;
            float v2 = acc[mi][ni][2] + b0, v3 = acc[mi][ni][3] + b1;
            if (outmode == 0) {
                *(float2*)(Y + (size_t)gr * DMODEL + gc)       = make_float2(v0, v1);
                *(float2*)(Y + (size_t)(gr + 8) * DMODEL + gc) = make_float2(v2, v3);
            } else {
                *(uint32_t*)(Yh + (size_t)gr * DMODEL + gc)       = pack2h(v0, v1);
                *(uint32_t*)(Yh + (size_t)(gr + 8) * DMODEL + gc) = pack2h(v2, v3);
            }
        }
    }
}

__global__ __launch_bounds__(256, 2)
void gemm_qkv_mma(const float* __restrict__ bq, const float* __restrict__ bk,
                  const float* __restrict__ bv)
{
    int z = blockIdx.z;
    const float* bias = (z == 0) ? bq : (z == 1) ? bk : bv;
    __half* Yh = (z == 0) ? g_Q : (z == 1) ? g_K : g_V;
    gemm_hmma_body(g_X, g_W + (size_t)z * WSZ, bias, 2, nullptr, Yh);
}

__global__ __launch_bounds__(256, 2)
void gemm_out_mma(const float* __restrict__ bo, float* __restrict__ Y)
{
    gemm_hmma_body(g_C, g_W + (size_t)3 * WSZ, bo, 0, Y, nullptr);
}

// ---------------- flash attention: all-single fp16 (unchanged) ---------------
#define FROWB   144                        // 64 fp16 = 128B + 16B pad
#define FQTILE  (128 * FROWB)              // 18432
#define KTILE   (64 * FROWB)               // 9216
#define FSTAGE(s) (FQTILE + (s) * 2 * KTILE)
#define FK      0
#define FV      (KTILE)
#define SMEM_FLASH (FQTILE + 4 * KTILE)    // 55296 (54 KB)

__device__ __forceinline__ void flash_load_q(uint32_t sb, const __half* Qs,
                                             int q0, int tid)
{
    #pragma unroll
    for (int it = 0; it < 4; it++) {
        int u = tid + it * 256;           // 0..1023
        int r = u >> 3, c = u & 7;
        uint32_t so = (uint32_t)(r * FROWB + c * 16);
        cpasync16(sb + so, Qs + (size_t)(q0 + r) * DMODEL + c * 8);
    }
}
__device__ __forceinline__ void flash_load_kv(uint32_t stb,
    const __half* Ks, const __half* Vs, int k0, int tid)
{
    #pragma unroll
    for (int it = 0; it < 2; it++) {
        int u = tid + it * 256;           // 0..511
        int r = u >> 3, c = u & 7;
        uint32_t so = (uint32_t)(r * FROWB + c * 16);
        size_t ge = (size_t)(k0 + r) * DMODEL + c * 8;
        cpasync16(stb + FK + so, Ks + ge);
        cpasync16(stb + FV + so, Vs + ge);
    }
}

__global__ __launch_bounds__(256, 2)
void flash_attn_mma()
{
    extern __shared__ char smem[];
    const uint32_t sb = smem_u32(smem);
    const int tid  = threadIdx.x;
    const int w    = tid >> 5;
    const int lane = tid & 31;

    const int b  = blockIdx.z;
    const int h  = blockIdx.y;
    const int q0 = blockIdx.x * 128;

    const size_t base = (size_t)b * SEQ * DMODEL + (size_t)h * HDIM;
    const __half* Qs = g_Q + base;
    const __half* Ks = g_K + base;
    const __half* Vs = g_V + base;

    const uint32_t qa = (uint32_t)((w * 16 + (lane & 15)) * FROWB
                      + ((lane >> 4) & 1) * 16);
    const uint32_t ka_row = (uint32_t)((lane & 7) + ((lane >> 4) & 1) * 8);
    const uint32_t ka_ko  = (uint32_t)(((lane >> 3) & 1) * 16);
    const uint32_t va_row = (uint32_t)(lane & 15);
    const uint32_t va_co  = (uint32_t)(((lane >> 4) & 1) * 16);

    float o[8][4];
    #pragma unroll
    for (int nb = 0; nb < 8; nb++)
        #pragma unroll
        for (int e = 0; e < 4; e++) o[nb][e] = 0.f;
    float m_a = -CUDART_INF_F, m_b = -CUDART_INF_F, l_a = 0.f, l_b = 0.f;

    uint32_t aQ[4][4];

    flash_load_q(sb, Qs, q0, tid);
    flash_load_kv(sb + FSTAGE(0), Ks, Vs, 0, tid);
    CPASYNC_COMMIT();

    const int NKT = SEQ / 64;             // 32
    for (int kt = 0; kt < NKT; kt++) {
        const uint32_t st = sb + FSTAGE(kt & 1);
        if (kt + 1 < NKT) {
            flash_load_kv(sb + FSTAGE((kt + 1) & 1), Ks, Vs, (kt + 1) * 64, tid);
            CPASYNC_COMMIT();
            CPASYNC_WAIT(1);
        } else {
            CPASYNC_WAIT(0);
        }
        __syncthreads();

        if (kt == 0) {
            #pragma unroll
            for (int k4 = 0; k4 < 4; k4++)
                ldm_x4(aQ[k4], sb + qa + k4 * 32);
        }

        // ---- S = Q K^T : single pass -----------------------------------------
        float s[8][4];
        #pragma unroll
        for (int j = 0; j < 8; j++)
            #pragma unroll
            for (int e = 0; e < 4; e++) s[j][e] = 0.f;

        #pragma unroll
        for (int k4 = 0; k4 < 4; k4++) {
            uint32_t kS[4][4];
            #pragma unroll
            for (int nb = 0; nb < 4; nb++)
                ldm_x4(kS[nb], st + FK + (uint32_t)(nb * 16) * FROWB
                               + ka_row * FROWB + ka_ko + k4 * 32);
            #pragma unroll
            for (int nb = 0; nb < 4; nb++) {
                mma_f16(s[2*nb],   aQ[k4], kS[nb][0], kS[nb][1]);
                mma_f16(s[2*nb+1], aQ[k4], kS[nb][2], kS[nb][3]);
            }
        }

        // ---- online softmax (rows a = lane/4, b = lane/4+8) -----------------
        float mloc_a = -CUDART_INF_F, mloc_b = -CUDART_INF_F;
        #pragma unroll
        for (int j = 0; j < 8; j++) {
            s[j][0] *= 0.125f; s[j][1] *= 0.125f;
            s[j][2] *= 0.125f; s[j][3] *= 0.125f;
            mloc_a = fmaxf(mloc_a, fmaxf(s[j][0], s[j][1]));
            mloc_b = fmaxf(mloc_b, fmaxf(s[j][2], s[j][3]));
        }
        mloc_a = fmaxf(mloc_a, __shfl_xor_sync(0xffffffffu, mloc_a, 1));
        mloc_a = fmaxf(mloc_a, __shfl_xor_sync(0xffffffffu, mloc_a, 2));
        mloc_b = fmaxf(mloc_b, __shfl_xor_sync(0xffffffffu, mloc_b, 1));
        mloc_b = fmaxf(mloc_b, __shfl_xor_sync(0xffffffffu, mloc_b, 2));

        float mn_a = fmaxf(m_a, mloc_a), mn_b = fmaxf(m_b, mloc_b);
        float corr_a = __expf(m_a - mn_a), corr_b = __expf(m_b - mn_b);
        m_a = mn_a; m_b = mn_b;

        float rs_a = 0.f, rs_b = 0.f;
        #pragma unroll
        for (int j = 0; j < 8; j++) {
            s[j][0] = __expf(s[j][0] - mn_a);
            s[j][1] = __expf(s[j][1] - mn_a);
            s[j][2] = __expf(s[j][2] - mn_b);
            s[j][3] = __expf(s[j][3] - mn_b);
            rs_a += s[j][0] + s[j][1];
            rs_b += s[j][2] + s[j][3];
        }
        rs_a += __shfl_xor_sync(0xffffffffu, rs_a, 1);
        rs_a += __shfl_xor_sync(0xffffffffu, rs_a, 2);
        rs_b += __shfl_xor_sync(0xffffffffu, rs_b, 1);
        rs_b += __shfl_xor_sync(0xffffffffu, rs_b, 2);
        l_a = l_a * corr_a + rs_a;
        l_b = l_b * corr_b + rs_b;

        #pragma unroll
        for (int nb = 0; nb < 8; nb++) {
            o[nb][0] *= corr_a; o[nb][1] *= corr_a;
            o[nb][2] *= corr_b; o[nb][3] *= corr_b;
        }

        // ---- O += P V: single pass -------------------------------------------
        #pragma unroll
        for (int t = 0; t < 4; t++) {
            uint32_t pP[4];
            pP[0] = pack2h(s[2*t][0],   s[2*t][1]);
            pP[1] = pack2h(s[2*t][2],   s[2*t][3]);
            pP[2] = pack2h(s[2*t+1][0], s[2*t+1][1]);
            pP[3] = pack2h(s[2*t+1][2], s[2*t+1][3]);

            uint32_t vS[4][4];
            #pragma unroll
            for (int ng = 0; ng < 4; ng++)
                ldm_x4t(vS[ng], st + FV + (uint32_t)(t * 16 + va_row) * FROWB
                                + (uint32_t)(ng * 32) + va_co);
            #pragma unroll
            for (int ng = 0; ng < 4; ng++) {
                mma_f16(o[2*ng],   pP, vS[ng][0], vS[ng][1]);
                mma_f16(o[2*ng+1], pP, vS[ng][2], vS[ng][3]);
            }
        }
        __syncthreads();
    }

    // ---- epilogue: normalize, pack single fp16 ctx --------------------------
    const float inv_a = 1.0f / l_a, inv_b = 1.0f / l_b;
    const int row_a = q0 + w * 16 + (lane >> 2);
    const int col0  = (lane & 3) * 2;
    #pragma unroll
    for (int nb = 0; nb < 8; nb++) {
        int col = nb * 8 + col0;
        size_t ea = base + (size_t)row_a * DMODEL + col;
        size_t eb = base + (size_t)(row_a + 8) * DMODEL + col;
        *(uint32_t*)(g_C + ea) = pack2h(o[nb][0] * inv_a, o[nb][1] * inv_a);
        *(uint32_t*)(g_C + eb) = pack2h(o[nb][2] * inv_b, o[nb][3] * inv_b);
    }
}

// ---------------------------------------------------------------------------
extern "C" void kernel_launch(void* const* d_in, const int* in_sizes, int n_in,
                              void* d_out, int out_size)
{
    const float* x  = (const float*)d_in[0];
    const float* Wq = (const float*)d_in[1];
    const float* bq = (const float*)d_in[2];
    const float* Wk = (const float*)d_in[3];
    const float* bk = (const float*)d_in[4];
    const float* Wv = (const float*)d_in[5];
    const float* bv = (const float*)d_in[6];
    const float* Wo = (const float*)d_in[7];
    const float* bo = (const float*)d_in[8];
    float* out = (float*)d_out;

    cudaFuncSetAttribute(gemm_qkv_mma,   cudaFuncAttributeMaxDynamicSharedMemorySize, SMEM_GEMM);
    cudaFuncSetAttribute(gemm_out_mma,   cudaFuncAttributeMaxDynamicSharedMemorySize, SMEM_GEMM);
    cudaFuncSetAttribute(flash_attn_mma, cudaFuncAttributeMaxDynamicSharedMemorySize, SMEM_FLASH);

    split_all<<<(XN8 + 4 * WN8) / 256, 256>>>(x, Wq, Wk, Wv, Wo);

    dim3 qgrid(DMODEL / 128, MTOT / 128, 3);
    gemm_qkv_mma<<<qgrid, 256, SMEM_GEMM>>>(bq, bk, bv);

    dim3 fgrid(SEQ / 128, NHEADS, BATCH);
    flash_attn_mma<<<fgrid, 256, SMEM_FLASH>>>();

    dim3 ogrid(DMODEL / 128, MTOT / 128, 1);
    gemm_out_mma<<<ogrid, 256, SMEM_GEMM>>>(bo, out);
}

// round 13
// speedup vs baseline: 7.2978x; 1.0068x over previous
#include <cuda_runtime.h>
#include <cuda_fp16.h>
#include <math_constants.h>
#include <cstdint>

#define BATCH  2
#define SEQ    2048
#define DMODEL 1024
#define NHEADS 16
#define HDIM   64
#define MTOT   (BATCH*SEQ)   // 4096
#define WSZ    (DMODEL*DMODEL)

// ---------------- scratch (allocation-free rule: __device__ globals) --------
__device__ __half g_X[(size_t)MTOT * DMODEL];
__device__ __half g_W[(size_t)4 * WSZ];
__device__ __half g_Q[(size_t)MTOT * DMODEL];
__device__ __half g_K[(size_t)MTOT * DMODEL];
__device__ __half g_V[(size_t)MTOT * DMODEL];
__device__ __half g_C[(size_t)MTOT * DMODEL];

// ---------------- helpers (baseline ISA only) --------------------------------
__device__ __forceinline__ uint32_t smem_u32(const void* p) {
    uint32_t a;
    asm("{ .reg .u64 t; cvta.to.shared.u64 t, %1; cvt.u32.u64 %0, t; }"
        : "=r"(a) : "l"(p));
    return a;
}
__device__ __forceinline__ void cpasync16(uint32_t dst, const void* src) {
    asm volatile("cp.async.cg.shared.global [%0], [%1], 16;" :: "r"(dst), "l"(src));
}
#define CPASYNC_COMMIT() asm volatile("cp.async.commit_group;" ::: "memory")
#define CPASYNC_WAIT(n)  asm volatile("cp.async.wait_group %0;" :: "n"(n) : "memory")

__device__ __forceinline__ void ldm_x4(uint32_t* r, uint32_t addr) {
    asm volatile("ldmatrix.sync.aligned.m8n8.x4.shared.b16 {%0,%1,%2,%3}, [%4];"
        : "=r"(r[0]), "=r"(r[1]), "=r"(r[2]), "=r"(r[3]) : "r"(addr));
}
__device__ __forceinline__ void ldm_x4t(uint32_t* r, uint32_t addr) {
    asm volatile("ldmatrix.sync.aligned.m8n8.x4.trans.shared.b16 {%0,%1,%2,%3}, [%4];"
        : "=r"(r[0]), "=r"(r[1]), "=r"(r[2]), "=r"(r[3]) : "r"(addr));
}
__device__ __forceinline__ void mma_f16(float* c, const uint32_t* a,
                                        uint32_t b0, uint32_t b1) {
    asm volatile("mma.sync.aligned.m16n8k16.row.col.f32.f16.f16.f32 "
        "{%0,%1,%2,%3}, {%4,%5,%6,%7}, {%8,%9}, {%0,%1,%2,%3};"
        : "+f"(c[0]), "+f"(c[1]), "+f"(c[2]), "+f"(c[3])
        : "r"(a[0]), "r"(a[1]), "r"(a[2]), "r"(a[3]), "r"(b0), "r"(b1));
}
__device__ __forceinline__ uint32_t pack2h(float v0, float v1) {
    __half h0 = __float2half_rn(v0), h1 = __float2half_rn(v1);
    return ((uint32_t)__half_as_ushort(h1) << 16) | __half_as_ushort(h0);
}

// ---------------- fused fp32 -> fp16 convert (x + 4 weights) -----------------
#define XN8  (MTOT * DMODEL / 8)          // 524288
#define WN8  (WSZ / 8)                    // 131072
__global__ __launch_bounds__(256)
void split_all(const float* __restrict__ x,  const float* __restrict__ Wq,
               const float* __restrict__ Wk, const float* __restrict__ Wv,
               const float* __restrict__ Wo)
{
    int id = blockIdx.x * 256 + threadIdx.x;
    const float* src;
    __half* dst;
    int off;
    if (id < XN8) {
        src = x; dst = g_X; off = id;
    } else {
        int r = (id - XN8) >> 17;          // WN8 = 2^17
        off   = (id - XN8) & (WN8 - 1);
        src = (r == 0) ? Wq : (r == 1) ? Wk : (r == 2) ? Wv : Wo;
        dst = g_W + (size_t)r * WSZ;
    }
    const float4* s = (const float4*)src + (size_t)off * 2;
    float4 a = s[0], b = s[1];
    uint4 hp;
    hp.x = pack2h(a.x, a.y);
    hp.y = pack2h(a.z, a.w);
    hp.z = pack2h(b.x, b.y);
    hp.w = pack2h(b.z, b.w);
    ((uint4*)dst)[off] = hp;
}

// ---------------- HMMA GEMM: Y = A(fp16) @ W(fp16)^T + bias ------------------
// single pass, BK=64, 3-stage cp.async pipeline, ONE barrier per chunk.
// outmode: 0 = fp32 Y ; 2 = single fp16
#define BK        64
#define ROWB      144                      // 128B data + 16B pad (conflict-free)
#define TILE_B    (128 * ROWB)             // 18432
#define OFF_B     (TILE_B)
#define STAGE_B   (2 * TILE_B)             // 36864
#define SMEM_GEMM (3 * STAGE_B)            // 110592

__device__ __forceinline__ void load_chunk(
    uint32_t sdst, const __half* __restrict__ A, const __half* __restrict__ W,
    int bm, int bn, int k0, int tid)
{
    #pragma unroll
    for (int it = 0; it < 4; it++) {
        int u = tid + it * 256;            // 0..1023: 128 rows x 8 x 16B
        int r = u >> 3, c = u & 7;
        uint32_t so = (uint32_t)(r * ROWB + c * 16);
        cpasync16(sdst + so,         A + (size_t)(bm + r) * DMODEL + k0 + c * 8);
        cpasync16(sdst + OFF_B + so, W + (size_t)(bn + r) * DMODEL + k0 + c * 8);
    }
}

__device__ __forceinline__ void gemm_hmma_body(
    const __half* __restrict__ A, const __half* __restrict__ W,
    const float* __restrict__ bias, int outmode,
    float* __restrict__ Y, __half* __restrict__ Yh)
{
    extern __shared__ char smem[];
    const uint32_t sb = smem_u32(smem);
    const int tid  = threadIdx.x;
    const int lane = tid & 31;
    const int wid  = tid >> 5;
    const int wm   = wid & 1;
    const int wn   = wid >> 1;

    const int bm = blockIdx.y * 128;
    const int bn = blockIdx.x * 128;

    float acc[4][4][4];
    #pragma unroll
    for (int mi = 0; mi < 4; mi++)
        #pragma unroll
        for (int ni = 0; ni < 4; ni++)
            #pragma unroll
            for (int e = 0; e < 4; e++) acc[mi][ni][e] = 0.f;

    const uint32_t a_row  = (uint32_t)(wm * 64 + (lane & 15));
    const uint32_t a_koff = (uint32_t)(((lane >> 4) & 1) * 16);
    const uint32_t b_nrow = (uint32_t)(wn * 32 + (lane & 7) + ((lane >> 4) & 1) * 8);
    const uint32_t b_koff = (uint32_t)(((lane >> 3) & 1) * 16);

    load_chunk(sb,           A, W, bm, bn, 0,  tid);
    CPASYNC_COMMIT();
    load_chunk(sb + STAGE_B, A, W, bm, bn, BK, tid);
    CPASYNC_COMMIT();

    const int NCH = DMODEL / BK;           // 16
    uint32_t stage = 0;                     // byte offset of current stage
    for (int ch = 0; ch < NCH; ch++) {
        if (ch == NCH - 1) { CPASYNC_WAIT(0); } else { CPASYNC_WAIT(1); }
        __syncthreads();

        if (ch + 2 < NCH) {
            uint32_t s2 = stage + 2 * STAGE_B;
            if (s2 >= 3 * STAGE_B) s2 -= 3 * STAGE_B;
            load_chunk(sb + s2, A, W, bm, bn, (ch + 2) * BK, tid);
            CPASYNC_COMMIT();
        }

        const uint32_t st = sb + stage;
        #pragma unroll
        for (int ks = 0; ks < 4; ks++) {   // 4 x k16 per chunk
            const uint32_t kb = (uint32_t)(ks * 32);
            uint32_t aA[4][4], bB[2][4];
            #pragma unroll
            for (int mi = 0; mi < 4; mi++)
                ldm_x4(aA[mi], st + (a_row + mi * 16) * ROWB + kb + a_koff);
            #pragma unroll
            for (int p = 0; p < 2; p++)
                ldm_x4(bB[p], st + OFF_B + (b_nrow + p * 16) * ROWB + kb + b_koff);
            #pragma unroll
            for (int mi = 0; mi < 4; mi++)
                #pragma unroll
                for (int ni = 0; ni < 4; ni++) {
                    const uint32_t* bb = &bB[ni >> 1][(ni & 1) * 2];
                    mma_f16(acc[mi][ni], aA[mi], bb[0], bb[1]);
                }
        }
        stage += STAGE_B;
        if (stage >= 3 * STAGE_B) stage = 0;
    }

    const int l4 = lane >> 2;
    const int l2 = (lane & 3) * 2;
    #pragma unroll
    for (int mi = 0; mi < 4; mi++) {
        #pragma unroll
        for (int ni = 0; ni < 4; ni++) {
            int gr = bm + wm * 64 + mi * 16 + l4;
            int gc = bn + wn * 32 + ni * 8 + l2;
            float b0 = bias[gc], b1 = bias[gc + 1];
            float v0 = acc[mi][ni][0] + b0, v1 = acc[mi][ni][1] + b1;
            float v2 = acc[mi][ni][2] + b0, v3 = acc[mi][ni][3] + b1;
            if (outmode == 0) {
                *(float2*)(Y + (size_t)gr * DMODEL + gc)       = make_float2(v0, v1);
                *(float2*)(Y + (size_t)(gr + 8) * DMODEL + gc) = make_float2(v2, v3);
            } else {
                *(uint32_t*)(Yh + (size_t)gr * DMODEL + gc)       = pack2h(v0, v1);
                *(uint32_t*)(Yh + (size_t)(gr + 8) * DMODEL + gc) = pack2h(v2, v3);
            }
        }
    }
}

__global__ __launch_bounds__(256, 2)
void gemm_qkv_mma(const float* __restrict__ bq, const float* __restrict__ bk,
                  const float* __restrict__ bv)
{
    int z = blockIdx.z;
    const float* bias = (z == 0) ? bq : (z == 1) ? bk : bv;
    __half* Yh = (z == 0) ? g_Q : (z == 1) ? g_K : g_V;
    gemm_hmma_body(g_X, g_W + (size_t)z * WSZ, bias, 2, nullptr, Yh);
}

__global__ __launch_bounds__(256, 2)
void gemm_out_mma(const float* __restrict__ bo, float* __restrict__ Y)
{
    gemm_hmma_body(g_C, g_W + (size_t)3 * WSZ, bo, 0, Y, nullptr);
}

// ---------------- flash attention: 3-stage KV pipeline, one barrier/iter -----
#define FROWB   144                        // 64 fp16 = 128B + 16B pad
#define FQTILE  (128 * FROWB)              // 18432
#define KTILE   (64 * FROWB)               // 9216
#define KVSTAGE (2 * KTILE)                // 18432
#define FK      0
#define FV      (KTILE)
#define SMEM_FLASH (FQTILE + 3 * KVSTAGE)  // 73728 (72 KB)

__device__ __forceinline__ void flash_load_q(uint32_t sb, const __half* Qs,
                                             int q0, int tid)
{
    #pragma unroll
    for (int it = 0; it < 4; it++) {
        int u = tid + it * 256;           // 0..1023
        int r = u >> 3, c = u & 7;
        uint32_t so = (uint32_t)(r * FROWB + c * 16);
        cpasync16(sb + so, Qs + (size_t)(q0 + r) * DMODEL + c * 8);
    }
}
__device__ __forceinline__ void flash_load_kv(uint32_t stb,
    const __half* Ks, const __half* Vs, int k0, int tid)
{
    #pragma unroll
    for (int it = 0; it < 2; it++) {
        int u = tid + it * 256;           // 0..511
        int r = u >> 3, c = u & 7;
        uint32_t so = (uint32_t)(r * FROWB + c * 16);
        size_t ge = (size_t)(k0 + r) * DMODEL + c * 8;
        cpasync16(stb + FK + so, Ks + ge);
        cpasync16(stb + FV + so, Vs + ge);
    }
}

__global__ __launch_bounds__(256, 2)
void flash_attn_mma()
{
    extern __shared__ char smem[];
    const uint32_t sb = smem_u32(smem);
    const uint32_t kvb = sb + FQTILE;
    const int tid  = threadIdx.x;
    const int w    = tid >> 5;
    const int lane = tid & 31;

    const int b  = blockIdx.z;
    const int h  = blockIdx.y;
    const int q0 = blockIdx.x * 128;

    const size_t base = (size_t)b * SEQ * DMODEL + (size_t)h * HDIM;
    const __half* Qs = g_Q + base;
    const __half* Ks = g_K + base;
    const __half* Vs = g_V + base;

    const uint32_t qa = (uint32_t)((w * 16 + (lane & 15)) * FROWB
                      + ((lane >> 4) & 1) * 16);
    const uint32_t ka_row = (uint32_t)((lane & 7) + ((lane >> 4) & 1) * 8);
    const uint32_t ka_ko  = (uint32_t)(((lane >> 3) & 1) * 16);
    const uint32_t va_row = (uint32_t)(lane & 15);
    const uint32_t va_co  = (uint32_t)(((lane >> 4) & 1) * 16);

    float o[8][4];
    #pragma unroll
    for (int nb = 0; nb < 8; nb++)
        #pragma unroll
        for (int e = 0; e < 4; e++) o[nb][e] = 0.f;
    float m_a = -CUDART_INF_F, m_b = -CUDART_INF_F, l_a = 0.f, l_b = 0.f;

    uint32_t aQ[4][4];

    // Q rides with KV stage-0's group (both waited before first use)
    flash_load_q(sb, Qs, q0, tid);
    flash_load_kv(kvb, Ks, Vs, 0, tid);
    CPASYNC_COMMIT();
    flash_load_kv(kvb + KVSTAGE, Ks, Vs, 64, tid);
    CPASYNC_COMMIT();

    const int NKT = SEQ / 64;             // 32
    uint32_t stage = 0;
    for (int kt = 0; kt < NKT; kt++) {
        if (kt == NKT - 1) { CPASYNC_WAIT(0); } else { CPASYNC_WAIT(1); }
        __syncthreads();

        if (kt + 2 < NKT) {
            uint32_t s2 = stage + 2 * KVSTAGE;
            if (s2 >= 3 * KVSTAGE) s2 -= 3 * KVSTAGE;
            flash_load_kv(kvb + s2, Ks, Vs, (kt + 2) * 64, tid);
            CPASYNC_COMMIT();
        }

        const uint32_t st = kvb + stage;

        if (kt == 0) {
            #pragma unroll
            for (int k4 = 0; k4 < 4; k4++)
                ldm_x4(aQ[k4], sb + qa + k4 * 32);
        }

        // ---- S = Q K^T : single pass -----------------------------------------
        float s[8][4];
        #pragma unroll
        for (int j = 0; j < 8; j++)
            #pragma unroll
            for (int e = 0; e < 4; e++) s[j][e] = 0.f;

        #pragma unroll
        for (int k4 = 0; k4 < 4; k4++) {
            uint32_t kS[4][4];
            #pragma unroll
            for (int nb = 0; nb < 4; nb++)
                ldm_x4(kS[nb], st + FK + (uint32_t)(nb * 16) * FROWB
                               + ka_row * FROWB + ka_ko + k4 * 32);
            #pragma unroll
            for (int nb = 0; nb < 4; nb++) {
                mma_f16(s[2*nb],   aQ[k4], kS[nb][0], kS[nb][1]);
                mma_f16(s[2*nb+1], aQ[k4], kS[nb][2], kS[nb][3]);
            }
        }

        // ---- online softmax (rows a = lane/4, b = lane/4+8) -----------------
        float mloc_a = -CUDART_INF_F, mloc_b = -CUDART_INF_F;
        #pragma unroll
        for (int j = 0; j < 8; j++) {
            s[j][0] *= 0.125f; s[j][1] *= 0.125f;
            s[j][2] *= 0.125f; s[j][3] *= 0.125f;
            mloc_a = fmaxf(mloc_a, fmaxf(s[j][0], s[j][1]));
            mloc_b = fmaxf(mloc_b, fmaxf(s[j][2], s[j][3]));
        }
        mloc_a = fmaxf(mloc_a, __shfl_xor_sync(0xffffffffu, mloc_a, 1));
        mloc_a = fmaxf(mloc_a, __shfl_xor_sync(0xffffffffu, mloc_a, 2));
        mloc_b = fmaxf(mloc_b, __shfl_xor_sync(0xffffffffu, mloc_b, 1));
        mloc_b = fmaxf(mloc_b, __shfl_xor_sync(0xffffffffu, mloc_b, 2));

        float mn_a = fmaxf(m_a, mloc_a), mn_b = fmaxf(m_b, mloc_b);
        float corr_a = __expf(m_a - mn_a), corr_b = __expf(m_b - mn_b);
        m_a = mn_a; m_b = mn_b;

        float rs_a = 0.f, rs_b = 0.f;
        #pragma unroll
        for (int j = 0; j < 8; j++) {
            s[j][0] = __expf(s[j][0] - mn_a);
            s[j][1] = __expf(s[j][1] - mn_a);
            s[j][2] = __expf(s[j][2] - mn_b);
            s[j][3] = __expf(s[j][3] - mn_b);
            rs_a += s[j][0] + s[j][1];
            rs_b += s[j][2] + s[j][3];
        }
        rs_a += __shfl_xor_sync(0xffffffffu, rs_a, 1);
        rs_a += __shfl_xor_sync(0xffffffffu, rs_a, 2);
        rs_b += __shfl_xor_sync(0xffffffffu, rs_b, 1);
        rs_b += __shfl_xor_sync(0xffffffffu, rs_b, 2);
        l_a = l_a * corr_a + rs_a;
        l_b = l_b * corr_b + rs_b;

        #pragma unroll
        for (int nb = 0; nb < 8; nb++) {
            o[nb][0] *= corr_a; o[nb][1] *= corr_a;
            o[nb][2] *= corr_b; o[nb][3] *= corr_b;
        }

        // ---- O += P V: single pass -------------------------------------------
        #pragma unroll
        for (int t = 0; t < 4; t++) {
            uint32_t pP[4];
            pP[0] = pack2h(s[2*t][0],   s[2*t][1]);
            pP[1] = pack2h(s[2*t][2],   s[2*t][3]);
            pP[2] = pack2h(s[2*t+1][0], s[2*t+1][1]);
            pP[3] = pack2h(s[2*t+1][2], s[2*t+1][3]);

            uint32_t vS[4][4];
            #pragma unroll
            for (int ng = 0; ng < 4; ng++)
                ldm_x4t(vS[ng], st + FV + (uint32_t)(t * 16 + va_row) * FROWB
                                + (uint32_t)(ng * 32) + va_co);
            #pragma unroll
            for (int ng = 0; ng < 4; ng++) {
                mma_f16(o[2*ng],   pP, vS[ng][0], vS[ng][1]);
                mma_f16(o[2*ng+1], pP, vS[ng][2], vS[ng][3]);
            }
        }
        stage += KVSTAGE;
        if (stage >= 3 * KVSTAGE) stage = 0;
    }

    // ---- epilogue: normalize, pack single fp16 ctx --------------------------
    const float inv_a = 1.0f / l_a, inv_b = 1.0f / l_b;
    const int row_a = q0 + w * 16 + (lane >> 2);
    const int col0  = (lane & 3) * 2;
    #pragma unroll
    for (int nb = 0; nb < 8; nb++) {
        int col = nb * 8 + col0;
        size_t ea = base + (size_t)row_a * DMODEL + col;
        size_t eb = base + (size_t)(row_a + 8) * DMODEL + col;
        *(uint32_t*)(g_C + ea) = pack2h(o[nb][0] * inv_a, o[nb][1] * inv_a);
        *(uint32_t*)(g_C + eb) = pack2h(o[nb][2] * inv_b, o[nb][3] * inv_b);
    }
}

// ---------------------------------------------------------------------------
extern "C" void kernel_launch(void* const* d_in, const int* in_sizes, int n_in,
                              void* d_out, int out_size)
{
    const float* x  = (const float*)d_in[0];
    const float* Wq = (const float*)d_in[1];
    const float* bq = (const float*)d_in[2];
    const float* Wk = (const float*)d_in[3];
    const float* bk = (const float*)d_in[4];
    const float* Wv = (const float*)d_in[5];
    const float* bv = (const float*)d_in[6];
    const float* Wo = (const float*)d_in[7];
    const float* bo = (const float*)d_in[8];
    float* out = (float*)d_out;

    cudaFuncSetAttribute(gemm_qkv_mma,   cudaFuncAttributeMaxDynamicSharedMemorySize, SMEM_GEMM);
    cudaFuncSetAttribute(gemm_out_mma,   cudaFuncAttributeMaxDynamicSharedMemorySize, SMEM_GEMM);
    cudaFuncSetAttribute(flash_attn_mma, cudaFuncAttributeMaxDynamicSharedMemorySize, SMEM_FLASH);

    split_all<<<(XN8 + 4 * WN8) / 256, 256>>>(x, Wq, Wk, Wv, Wo);

    dim3 qgrid(DMODEL / 128, MTOT / 128, 3);
    gemm_qkv_mma<<<qgrid, 256, SMEM_GEMM>>>(bq, bk, bv);

    dim3 fgrid(SEQ / 128, NHEADS, BATCH);
    flash_attn_mma<<<fgrid, 256, SMEM_FLASH>>>();

    dim3 ogrid(DMODEL / 128, MTOT / 128, 1);
    gemm_out_mma<<<ogrid, 256, SMEM_GEMM>>>(bo, out);
}

// round 14
// speedup vs baseline: 7.3118x; 1.0019x over previous
#include <cuda_runtime.h>
#include <cuda_fp16.h>
#include <math_constants.h>
#include <cstdint>

#define BATCH  2
#define SEQ    2048
#define DMODEL 1024
#define NHEADS 16
#define HDIM   64
#define MTOT   (BATCH*SEQ)   // 4096
#define WSZ    (DMODEL*DMODEL)

// ---------------- scratch (allocation-free rule: __device__ globals) --------
__device__ __half g_X[(size_t)MTOT * DMODEL];
__device__ __half g_W[(size_t)4 * WSZ];
__device__ __half g_Q[(size_t)MTOT * DMODEL];
__device__ __half g_K[(size_t)MTOT * DMODEL];
__device__ __half g_V[(size_t)MTOT * DMODEL];
__device__ __half g_C[(size_t)MTOT * DMODEL];

// ---------------- helpers (baseline ISA only) --------------------------------
__device__ __forceinline__ uint32_t smem_u32(const void* p) {
    uint32_t a;
    asm("{ .reg .u64 t; cvta.to.shared.u64 t, %1; cvt.u32.u64 %0, t; }"
        : "=r"(a) : "l"(p));
    return a;
}
__device__ __forceinline__ void cpasync16(uint32_t dst, const void* src) {
    asm volatile("cp.async.cg.shared.global [%0], [%1], 16;" :: "r"(dst), "l"(src));
}
#define CPASYNC_COMMIT() asm volatile("cp.async.commit_group;" ::: "memory")
#define CPASYNC_WAIT(n)  asm volatile("cp.async.wait_group %0;" :: "n"(n) : "memory")

__device__ __forceinline__ void ldm_x4(uint32_t* r, uint32_t addr) {
    asm volatile("ldmatrix.sync.aligned.m8n8.x4.shared.b16 {%0,%1,%2,%3}, [%4];"
        : "=r"(r[0]), "=r"(r[1]), "=r"(r[2]), "=r"(r[3]) : "r"(addr));
}
__device__ __forceinline__ void ldm_x4t(uint32_t* r, uint32_t addr) {
    asm volatile("ldmatrix.sync.aligned.m8n8.x4.trans.shared.b16 {%0,%1,%2,%3}, [%4];"
        : "=r"(r[0]), "=r"(r[1]), "=r"(r[2]), "=r"(r[3]) : "r"(addr));
}
__device__ __forceinline__ void mma_f16(float* c, const uint32_t* a,
                                        uint32_t b0, uint32_t b1) {
    asm volatile("mma.sync.aligned.m16n8k16.row.col.f32.f16.f16.f32 "
        "{%0,%1,%2,%3}, {%4,%5,%6,%7}, {%8,%9}, {%0,%1,%2,%3};"
        : "+f"(c[0]), "+f"(c[1]), "+f"(c[2]), "+f"(c[3])
        : "r"(a[0]), "r"(a[1]), "r"(a[2]), "r"(a[3]), "r"(b0), "r"(b1));
}
__device__ __forceinline__ uint32_t pack2h(float v0, float v1) {
    __half h0 = __float2half_rn(v0), h1 = __float2half_rn(v1);
    return ((uint32_t)__half_as_ushort(h1) << 16) | __half_as_ushort(h0);
}

// ---------------- fused fp32 -> fp16 convert (x + 4 weights) -----------------
#define XN8  (MTOT * DMODEL / 8)          // 524288
#define WN8  (WSZ / 8)                    // 131072
__global__ __launch_bounds__(256)
void split_all(const float* __restrict__ x,  const float* __restrict__ Wq,
               const float* __restrict__ Wk, const float* __restrict__ Wv,
               const float* __restrict__ Wo)
{
    int id = blockIdx.x * 256 + threadIdx.x;
    const float* src;
    __half* dst;
    int off;
    if (id < XN8) {
        src = x; dst = g_X; off = id;
    } else {
        int r = (id - XN8) >> 17;          // WN8 = 2^17
        off   = (id - XN8) & (WN8 - 1);
        src = (r == 0) ? Wq : (r == 1) ? Wk : (r == 2) ? Wv : Wo;
        dst = g_W + (size_t)r * WSZ;
    }
    const float4* s = (const float4*)src + (size_t)off * 2;
    float4 a = s[0], b = s[1];
    uint4 hp;
    hp.x = pack2h(a.x, a.y);
    hp.y = pack2h(a.z, a.w);
    hp.z = pack2h(b.x, b.y);
    hp.w = pack2h(b.z, b.w);
    ((uint4*)dst)[off] = hp;
}

// ---------------- HMMA GEMM: Y = A(fp16) @ W(fp16)^T + bias ------------------
// 128 threads (4 warps, 2m x 2n), warp tile 64x64, CTA tile 128x128, BK=64.
// 2-stage cp.async pipeline. outmode: 0 = fp32 Y ; 2 = single fp16
#define BK        64
#define ROWB      144                      // 128B data + 16B pad (conflict-free)
#define TILE_B    (128 * ROWB)             // 18432
#define OFF_B     (TILE_B)
#define STAGE_B   (2 * TILE_B)             // 36864
#define SMEM_GEMM (2 * STAGE_B)            // 73728

__device__ __forceinline__ void load_chunk(
    uint32_t sdst, const __half* __restrict__ A, const __half* __restrict__ W,
    int bm, int bn, int k0, int tid)
{
    #pragma unroll
    for (int it = 0; it < 8; it++) {
        int u = tid + it * 128;            // 0..1023: 128 rows x 8 x 16B
        int r = u >> 3, c = u & 7;
        uint32_t so = (uint32_t)(r * ROWB + c * 16);
        cpasync16(sdst + so,         A + (size_t)(bm + r) * DMODEL + k0 + c * 8);
        cpasync16(sdst + OFF_B + so, W + (size_t)(bn + r) * DMODEL + k0 + c * 8);
    }
}

__device__ __forceinline__ void gemm_hmma_body(
    const __half* __restrict__ A, const __half* __restrict__ W,
    const float* __restrict__ bias, int outmode,
    float* __restrict__ Y, __half* __restrict__ Yh)
{
    extern __shared__ char smem[];
    const uint32_t sb = smem_u32(smem);
    const int tid  = threadIdx.x;
    const int lane = tid & 31;
    const int wid  = tid >> 5;             // 0..3
    const int wm   = wid & 1;              // 64-row half
    const int wn   = wid >> 1;             // 64-col half

    const int bm = blockIdx.y * 128;
    const int bn = blockIdx.x * 128;

    float acc[4][8][4];
    #pragma unroll
    for (int mi = 0; mi < 4; mi++)
        #pragma unroll
        for (int ni = 0; ni < 8; ni++)
            #pragma unroll
            for (int e = 0; e < 4; e++) acc[mi][ni][e] = 0.f;

    const uint32_t a_row  = (uint32_t)(wm * 64 + (lane & 15));
    const uint32_t a_koff = (uint32_t)(((lane >> 4) & 1) * 16);
    const uint32_t b_nrow = (uint32_t)(wn * 64 + (lane & 7) + ((lane >> 4) & 1) * 8);
    const uint32_t b_koff = (uint32_t)(((lane >> 3) & 1) * 16);

    load_chunk(sb, A, W, bm, bn, 0, tid);
    CPASYNC_COMMIT();

    const int NCH = DMODEL / BK;           // 16
    for (int ch = 0; ch < NCH; ch++) {
        const uint32_t st = sb + (uint32_t)(ch & 1) * STAGE_B;
        if (ch + 1 < NCH) {
            load_chunk(sb + (uint32_t)((ch + 1) & 1) * STAGE_B,
                       A, W, bm, bn, (ch + 1) * BK, tid);
            CPASYNC_COMMIT();
            CPASYNC_WAIT(1);
        } else {
            CPASYNC_WAIT(0);
        }
        __syncthreads();

        #pragma unroll
        for (int ks = 0; ks < 4; ks++) {   // 4 x k16 per chunk
            const uint32_t kb = (uint32_t)(ks * 32);
            uint32_t aA[4][4], bB[4][4];
            #pragma unroll
            for (int mi = 0; mi < 4; mi++)
                ldm_x4(aA[mi], st + (a_row + mi * 16) * ROWB + kb + a_koff);
            #pragma unroll
            for (int p = 0; p < 4; p++)
                ldm_x4(bB[p], st + OFF_B + (b_nrow + p * 16) * ROWB + kb + b_koff);
            #pragma unroll
            for (int mi = 0; mi < 4; mi++)
                #pragma unroll
                for (int ni = 0; ni < 8; ni++) {
                    const uint32_t* bb = &bB[ni >> 1][(ni & 1) * 2];
                    mma_f16(acc[mi][ni], aA[mi], bb[0], bb[1]);
                }
        }
        __syncthreads();
    }

    const int l4 = lane >> 2;
    const int l2 = (lane & 3) * 2;
    #pragma unroll
    for (int mi = 0; mi < 4; mi++) {
        #pragma unroll
        for (int ni = 0; ni < 8; ni++) {
            int gr = bm + wm * 64 + mi * 16 + l4;
            int gc = bn + wn * 64 + ni * 8 + l2;
            float b0 = bias[gc], b1 = bias[gc + 1];
            float v0 = acc[mi][ni][0] + b0, v1 = acc[mi][ni][1] + b1;
            float v2 = acc[mi][ni][2] + b0, v3 = acc[mi][ni][3] + b1;
            if (outmode == 0) {
                *(float2*)(Y + (size_t)gr * DMODEL + gc)       = make_float2(v0, v1);
                *(float2*)(Y + (size_t)(gr + 8) * DMODEL + gc) = make_float2(v2, v3);
            } else {
                *(uint32_t*)(Yh + (size_t)gr * DMODEL + gc)       = pack2h(v0, v1);
                *(uint32_t*)(Yh + (size_t)(gr + 8) * DMODEL + gc) = pack2h(v2, v3);
            }
        }
    }
}

__global__ __launch_bounds__(128, 2)
void gemm_qkv_mma(const float* __restrict__ bq, const float* __restrict__ bk,
                  const float* __restrict__ bv)
{
    int z = blockIdx.z;
    const float* bias = (z == 0) ? bq : (z == 1) ? bk : bv;
    __half* Yh = (z == 0) ? g_Q : (z == 1) ? g_K : g_V;
    gemm_hmma_body(g_X, g_W + (size_t)z * WSZ, bias, 2, nullptr, Yh);
}

__global__ __launch_bounds__(128, 2)
void gemm_out_mma(const float* __restrict__ bo, float* __restrict__ Y)
{
    gemm_hmma_body(g_C, g_W + (size_t)3 * WSZ, bo, 0, Y, nullptr);
}

// ---------------- flash attention: unchanged from R13 ------------------------
#define FROWB   144                        // 64 fp16 = 128B + 16B pad
#define FQTILE  (128 * FROWB)              // 18432
#define KTILE   (64 * FROWB)               // 9216
#define KVSTAGE (2 * KTILE)                // 18432
#define FK      0
#define FV      (KTILE)
#define SMEM_FLASH (FQTILE + 3 * KVSTAGE)  // 73728 (72 KB)

__device__ __forceinline__ void flash_load_q(uint32_t sb, const __half* Qs,
                                             int q0, int tid)
{
    #pragma unroll
    for (int it = 0; it < 4; it++) {
        int u = tid + it * 256;           // 0..1023
        int r = u >> 3, c = u & 7;
        uint32_t so = (uint32_t)(r * FROWB + c * 16);
        cpasync16(sb + so, Qs + (size_t)(q0 + r) * DMODEL + c * 8);
    }
}
__device__ __forceinline__ void flash_load_kv(uint32_t stb,
    const __half* Ks, const __half* Vs, int k0, int tid)
{
    #pragma unroll
    for (int it = 0; it < 2; it++) {
        int u = tid + it * 256;           // 0..511
        int r = u >> 3, c = u & 7;
        uint32_t so = (uint32_t)(r * FROWB + c * 16);
        size_t ge = (size_t)(k0 + r) * DMODEL + c * 8;
        cpasync16(stb + FK + so, Ks + ge);
        cpasync16(stb + FV + so, Vs + ge);
    }
}

__global__ __launch_bounds__(256, 2)
void flash_attn_mma()
{
    extern __shared__ char smem[];
    const uint32_t sb = smem_u32(smem);
    const uint32_t kvb = sb + FQTILE;
    const int tid  = threadIdx.x;
    const int w    = tid >> 5;
    const int lane = tid & 31;

    const int b  = blockIdx.z;
    const int h  = blockIdx.y;
    const int q0 = blockIdx.x * 128;

    const size_t base = (size_t)b * SEQ * DMODEL + (size_t)h * HDIM;
    const __half* Qs = g_Q + base;
    const __half* Ks = g_K + base;
    const __half* Vs = g_V + base;

    const uint32_t qa = (uint32_t)((w * 16 + (lane & 15)) * FROWB
                      + ((lane >> 4) & 1) * 16);
    const uint32_t ka_row = (uint32_t)((lane & 7) + ((lane >> 4) & 1) * 8);
    const uint32_t ka_ko  = (uint32_t)(((lane >> 3) & 1) * 16);
    const uint32_t va_row = (uint32_t)(lane & 15);
    const uint32_t va_co  = (uint32_t)(((lane >> 4) & 1) * 16);

    float o[8][4];
    #pragma unroll
    for (int nb = 0; nb < 8; nb++)
        #pragma unroll
        for (int e = 0; e < 4; e++) o[nb][e] = 0.f;
    float m_a = -CUDART_INF_F, m_b = -CUDART_INF_F, l_a = 0.f, l_b = 0.f;

    uint32_t aQ[4][4];

    flash_load_q(sb, Qs, q0, tid);
    flash_load_kv(kvb, Ks, Vs, 0, tid);
    CPASYNC_COMMIT();
    flash_load_kv(kvb + KVSTAGE, Ks, Vs, 64, tid);
    CPASYNC_COMMIT();

    const int NKT = SEQ / 64;             // 32
    uint32_t stage = 0;
    for (int kt = 0; kt < NKT; kt++) {
        if (kt == NKT - 1) { CPASYNC_WAIT(0); } else { CPASYNC_WAIT(1); }
        __syncthreads();

        if (kt + 2 < NKT) {
            uint32_t s2 = stage + 2 * KVSTAGE;
            if (s2 >= 3 * KVSTAGE) s2 -= 3 * KVSTAGE;
            flash_load_kv(kvb + s2, Ks, Vs, (kt + 2) * 64, tid);
            CPASYNC_COMMIT();
        }

        const uint32_t st = kvb + stage;

        if (kt == 0) {
            #pragma unroll
            for (int k4 = 0; k4 < 4; k4++)
                ldm_x4(aQ[k4], sb + qa + k4 * 32);
        }

        float s[8][4];
        #pragma unroll
        for (int j = 0; j < 8; j++)
            #pragma unroll
            for (int e = 0; e < 4; e++) s[j][e] = 0.f;

        #pragma unroll
        for (int k4 = 0; k4 < 4; k4++) {
            uint32_t kS[4][4];
            #pragma unroll
            for (int nb = 0; nb < 4; nb++)
                ldm_x4(kS[nb], st + FK + (uint32_t)(nb * 16) * FROWB
                               + ka_row * FROWB + ka_ko + k4 * 32);
            #pragma unroll
            for (int nb = 0; nb < 4; nb++) {
                mma_f16(s[2*nb],   aQ[k4], kS[nb][0], kS[nb][1]);
                mma_f16(s[2*nb+1], aQ[k4], kS[nb][2], kS[nb][3]);
            }
        }

        float mloc_a = -CUDART_INF_F, mloc_b = -CUDART_INF_F;
        #pragma unroll
        for (int j = 0; j < 8; j++) {
            s[j][0] *= 0.125f; s[j][1] *= 0.125f;
            s[j][2] *= 0.125f; s[j][3] *= 0.125f;
            mloc_a = fmaxf(mloc_a, fmaxf(s[j][0], s[j][1]));
            mloc_b = fmaxf(mloc_b, fmaxf(s[j][2], s[j][3]));
        }
        mloc_a = fmaxf(mloc_a, __shfl_xor_sync(0xffffffffu, mloc_a, 1));
        mloc_a = fmaxf(mloc_a, __shfl_xor_sync(0xffffffffu, mloc_a, 2));
        mloc_b = fmaxf(mloc_b, __shfl_xor_sync(0xffffffffu, mloc_b, 1));
        mloc_b = fmaxf(mloc_b, __shfl_xor_sync(0xffffffffu, mloc_b, 2));

        float mn_a = fmaxf(m_a, mloc_a), mn_b = fmaxf(m_b, mloc_b);
        float corr_a = __expf(m_a - mn_a), corr_b = __expf(m_b - mn_b);
        m_a = mn_a; m_b = mn_b;

        float rs_a = 0.f, rs_b = 0.f;
        #pragma unroll
        for (int j = 0; j < 8; j++) {
            s[j][0] = __expf(s[j][0] - mn_a);
            s[j][1] = __expf(s[j][1] - mn_a);
            s[j][2] = __expf(s[j][2] - mn_b);
            s[j][3] = __expf(s[j][3] - mn_b);
            rs_a += s[j][0] + s[j][1];
            rs_b += s[j][2] + s[j][3];
        }
        rs_a += __shfl_xor_sync(0xffffffffu, rs_a, 1);
        rs_a += __shfl_xor_sync(0xffffffffu, rs_a, 2);
        rs_b += __shfl_xor_sync(0xffffffffu, rs_b, 1);
        rs_b += __shfl_xor_sync(0xffffffffu, rs_b, 2);
        l_a = l_a * corr_a + rs_a;
        l_b = l_b * corr_b + rs_b;

        #pragma unroll
        for (int nb = 0; nb < 8; nb++) {
            o[nb][0] *= corr_a; o[nb][1] *= corr_a;
            o[nb][2] *= corr_b; o[nb][3] *= corr_b;
        }

        #pragma unroll
        for (int t = 0; t < 4; t++) {
            uint32_t pP[4];
            pP[0] = pack2h(s[2*t][0],   s[2*t][1]);
            pP[1] = pack2h(s[2*t][2],   s[2*t][3]);
            pP[2] = pack2h(s[2*t+1][0], s[2*t+1][1]);
            pP[3] = pack2h(s[2*t+1][2], s[2*t+1][3]);

            uint32_t vS[4][4];
            #pragma unroll
            for (int ng = 0; ng < 4; ng++)
                ldm_x4t(vS[ng], st + FV + (uint32_t)(t * 16 + va_row) * FROWB
                                + (uint32_t)(ng * 32) + va_co);
            #pragma unroll
            for (int ng = 0; ng < 4; ng++) {
                mma_f16(o[2*ng],   pP, vS[ng][0], vS[ng][1]);
                mma_f16(o[2*ng+1], pP, vS[ng][2], vS[ng][3]);
            }
        }
        stage += KVSTAGE;
        if (stage >= 3 * KVSTAGE) stage = 0;
    }

    const float inv_a = 1.0f / l_a, inv_b = 1.0f / l_b;
    const int row_a = q0 + w * 16 + (lane >> 2);
    const int col0  = (lane & 3) * 2;
    #pragma unroll
    for (int nb = 0; nb < 8; nb++) {
        int col = nb * 8 + col0;
        size_t ea = base + (size_t)row_a * DMODEL + col;
        size_t eb = base + (size_t)(row_a + 8) * DMODEL + col;
        *(uint32_t*)(g_C + ea) = pack2h(o[nb][0] * inv_a, o[nb][1] * inv_a);
        *(uint32_t*)(g_C + eb) = pack2h(o[nb][2] * inv_b, o[nb][3] * inv_b);
    }
}

// ---------------------------------------------------------------------------
extern "C" void kernel_launch(void* const* d_in, const int* in_sizes, int n_in,
                              void* d_out, int out_size)
{
    const float* x  = (const float*)d_in[0];
    const float* Wq = (const float*)d_in[1];
    const float* bq = (const float*)d_in[2];
    const float* Wk = (const float*)d_in[3];
    const float* bk = (const float*)d_in[4];
    const float* Wv = (const float*)d_in[5];
    const float* bv = (const float*)d_in[6];
    const float* Wo = (const float*)d_in[7];
    const float* bo = (const float*)d_in[8];
    float* out = (float*)d_out;

    cudaFuncSetAttribute(gemm_qkv_mma,   cudaFuncAttributeMaxDynamicSharedMemorySize, SMEM_GEMM);
    cudaFuncSetAttribute(gemm_out_mma,   cudaFuncAttributeMaxDynamicSharedMemorySize, SMEM_GEMM);
    cudaFuncSetAttribute(flash_attn_mma, cudaFuncAttributeMaxDynamicSharedMemorySize, SMEM_FLASH);

    split_all<<<(XN8 + 4 * WN8) / 256, 256>>>(x, Wq, Wk, Wv, Wo);

    dim3 qgrid(DMODEL / 128, MTOT / 128, 3);
    gemm_qkv_mma<<<qgrid, 128, SMEM_GEMM>>>(bq, bk, bv);

    dim3 fgrid(SEQ / 128, NHEADS, BATCH);
    flash_attn_mma<<<fgrid, 256, SMEM_FLASH>>>();

    dim3 ogrid(DMODEL / 128, MTOT / 128, 1);
    gemm_out_mma<<<ogrid, 128, SMEM_GEMM>>>(bo, out);
}